// round 1
// baseline (speedup 1.0000x reference)
#include <cuda_runtime.h>
#include <cstdint>
#include <cstdio>

#define SEQ   2048
#define HID   2560
#define QD    4096      // 32 heads * 128
#define KVD   1024      // 8 heads * 128
#define QKVD  6144      // QD + 2*KVD
#define HD    128
#define NQH   32
#define NKVH  8

// ---------------------------------------------------------------------------
// Scratch (device globals; no allocation allowed)
// ---------------------------------------------------------------------------
__device__ float g_qkv[(size_t)SEQ * QKVD];   // [s, 6144]: Q | K | V
__device__ float g_o[(size_t)SEQ * QD];       // attention output [s, h*128+d]

// ---------------------------------------------------------------------------
// SGEMM (NT): C[m, coff+n] = sum_k A[m,k] * B[n,k]
// A: [M,K] row-major, B: [N,K] row-major, C row stride ldc.
// BM=BN=128, BK=8, 256 threads, 8x8 per thread.
// ---------------------------------------------------------------------------
#define BM 128
#define BN 128
#define BKK 8

__global__ __launch_bounds__(256)
void sgemm_nt(const float* __restrict__ A, const float* __restrict__ B,
              float* __restrict__ C, int M, int N, int K, int ldc, int coff) {
    __shared__ float As[BKK][BM];
    __shared__ float Bs[BKK][BN];

    const int bx = blockIdx.x, by = blockIdx.y;
    const int tid = threadIdx.x;
    const int tx = tid & 15, ty = tid >> 4;

    const float* Ab = A + (size_t)by * BM * K;
    const float* Bb = B + (size_t)bx * BN * K;

    const int lrow = tid >> 1;          // 0..127
    const int lc4  = (tid & 1) * 4;     // 0 or 4

    float acc[8][8];
    #pragma unroll
    for (int i = 0; i < 8; i++)
        #pragma unroll
        for (int j = 0; j < 8; j++) acc[i][j] = 0.0f;

    for (int k0 = 0; k0 < K; k0 += BKK) {
        float4 a4 = *(const float4*)(Ab + (size_t)lrow * K + k0 + lc4);
        float4 b4 = *(const float4*)(Bb + (size_t)lrow * K + k0 + lc4);
        As[lc4 + 0][lrow] = a4.x; As[lc4 + 1][lrow] = a4.y;
        As[lc4 + 2][lrow] = a4.z; As[lc4 + 3][lrow] = a4.w;
        Bs[lc4 + 0][lrow] = b4.x; Bs[lc4 + 1][lrow] = b4.y;
        Bs[lc4 + 2][lrow] = b4.z; Bs[lc4 + 3][lrow] = b4.w;
        __syncthreads();

        #pragma unroll
        for (int kk = 0; kk < BKK; kk++) {
            float4 a0 = *(const float4*)&As[kk][ty * 8];
            float4 a1 = *(const float4*)&As[kk][ty * 8 + 4];
            float4 b0 = *(const float4*)&Bs[kk][tx * 8];
            float4 b1 = *(const float4*)&Bs[kk][tx * 8 + 4];
            float ar[8] = {a0.x, a0.y, a0.z, a0.w, a1.x, a1.y, a1.z, a1.w};
            float br[8] = {b0.x, b0.y, b0.z, b0.w, b1.x, b1.y, b1.z, b1.w};
            #pragma unroll
            for (int i = 0; i < 8; i++)
                #pragma unroll
                for (int j = 0; j < 8; j++)
                    acc[i][j] += ar[i] * br[j];
        }
        __syncthreads();
    }

    #pragma unroll
    for (int i = 0; i < 8; i++) {
        float* crow = C + (size_t)(by * BM + ty * 8 + i) * ldc + coff + bx * BN + tx * 8;
        float4 c0 = {acc[i][0], acc[i][1], acc[i][2], acc[i][3]};
        float4 c1 = {acc[i][4], acc[i][5], acc[i][6], acc[i][7]};
        *(float4*)(crow)     = c0;
        *(float4*)(crow + 4) = c1;
    }
}

// ---------------------------------------------------------------------------
// RMSNorm (per head, eps=1e-6) + RoPE, in place on g_qkv Q and K sections.
// One warp per (token, head); 40 heads (32 Q + 8 K).
// ---------------------------------------------------------------------------
__global__ __launch_bounds__(256)
void rms_rope_kernel(const float* __restrict__ cosb, const float* __restrict__ sinb,
                     const float* __restrict__ qw, const float* __restrict__ kw) {
    int gw = (blockIdx.x * blockDim.x + threadIdx.x) >> 5;
    int lane = threadIdx.x & 31;
    if (gw >= SEQ * 40) return;
    int s = gw / 40;
    int h = gw % 40;

    float* base;
    const float* w;
    if (h < NQH) { base = g_qkv + (size_t)s * QKVD + h * HD;              w = qw; }
    else         { base = g_qkv + (size_t)s * QKVD + QD + (h - NQH) * HD; w = kw; }

    int d = lane * 4;
    float4 x = *(float4*)(base + d);
    float ss = x.x * x.x + x.y * x.y + x.z * x.z + x.w * x.w;
    #pragma unroll
    for (int o = 16; o > 0; o >>= 1) ss += __shfl_xor_sync(0xffffffffu, ss, o);
    float r = rsqrtf(ss * (1.0f / 128.0f) + 1e-6f);

    float4 wv = *(const float4*)(w + d);
    float4 xn;
    xn.x = x.x * r * wv.x; xn.y = x.y * r * wv.y;
    xn.z = x.z * r * wv.z; xn.w = x.w * r * wv.w;

    // rotate-half partner lives 64 dims away -> lane ^ 16
    float4 ot;
    ot.x = __shfl_xor_sync(0xffffffffu, xn.x, 16);
    ot.y = __shfl_xor_sync(0xffffffffu, xn.y, 16);
    ot.z = __shfl_xor_sync(0xffffffffu, xn.z, 16);
    ot.w = __shfl_xor_sync(0xffffffffu, xn.w, 16);
    float sgn = (d < 64) ? -1.0f : 1.0f;

    float4 c = *(const float4*)(cosb + (size_t)s * HD + d);
    float4 si = *(const float4*)(sinb + (size_t)s * HD + d);
    float4 out;
    out.x = xn.x * c.x + sgn * ot.x * si.x;
    out.y = xn.y * c.y + sgn * ot.y * si.y;
    out.z = xn.z * c.z + sgn * ot.z * si.z;
    out.w = xn.w * c.w + sgn * ot.w * si.w;
    *(float4*)(base + d) = out;
}

// ---------------------------------------------------------------------------
// Flash attention, fp32, causal, GQA (q head h uses kv head h/4).
// Block: (head, q-tile of 64). 256 threads. Online softmax.
// smem: Qs[64][128], Kst[128][65] (transposed, padded), Vs[64][128],
//       Ss[64][65], m/l/alpha[64] -> 116224 B dynamic.
// ---------------------------------------------------------------------------
#define BQ 64
#define BKV 64

__global__ __launch_bounds__(256)
void flash_attn_kernel() {
    extern __shared__ float sm[];
    float* Qs   = sm;                    // 64*128
    float* Kst  = Qs + 64 * 128;         // 128*65
    float* Vs   = Kst + 128 * 65;        // 64*128
    float* Ss   = Vs + 64 * 128;         // 64*65
    float* mrow = Ss + 64 * 65;          // 64
    float* lrow = mrow + 64;             // 64
    float* arow = lrow + 64;             // 64

    const int h  = blockIdx.x;
    const int q0 = blockIdx.y * BQ;
    const int kh = h >> 2;
    const int tid = threadIdx.x;
    const int tx = tid & 15, ty = tid >> 4;
    const float scale = 0.08838834764831845f;  // 1/sqrt(128)

    // load Q tile
    for (int i = tid; i < 64 * 32; i += 256) {
        int row = i >> 5, c4 = (i & 31) << 2;
        *(float4*)(Qs + row * 128 + c4) =
            *(const float4*)(g_qkv + (size_t)(q0 + row) * QKVD + h * HD + c4);
    }
    if (tid < 64) { mrow[tid] = -1e30f; lrow[tid] = 0.0f; }

    float o_acc[4][8];
    #pragma unroll
    for (int i = 0; i < 4; i++)
        #pragma unroll
        for (int j = 0; j < 8; j++) o_acc[i][j] = 0.0f;

    __syncthreads();

    for (int k0 = 0; k0 <= q0; k0 += BKV) {
        // load K (transposed) and V tiles
        {
            int wrow = tid >> 5;
            int d4 = (tid & 31) << 2;
            for (int rr = wrow; rr < 64; rr += 8) {
                const float* kp = g_qkv + (size_t)(k0 + rr) * QKVD + QD + kh * HD;
                float4 k4 = *(const float4*)(kp + d4);
                Kst[(d4 + 0) * 65 + rr] = k4.x;
                Kst[(d4 + 1) * 65 + rr] = k4.y;
                Kst[(d4 + 2) * 65 + rr] = k4.z;
                Kst[(d4 + 3) * 65 + rr] = k4.w;
                const float* vp = g_qkv + (size_t)(k0 + rr) * QKVD + QD + KVD + kh * HD;
                *(float4*)(Vs + rr * 128 + d4) = *(const float4*)(vp + d4);
            }
        }
        __syncthreads();

        // S = Q K^T  (each thread: rows ty+16i, cols tx+16j)
        float s_acc[4][4];
        #pragma unroll
        for (int i = 0; i < 4; i++)
            #pragma unroll
            for (int j = 0; j < 4; j++) s_acc[i][j] = 0.0f;

        for (int d = 0; d < 128; d++) {
            float qv[4], kv[4];
            #pragma unroll
            for (int i = 0; i < 4; i++) qv[i] = Qs[(ty + 16 * i) * 128 + d];
            #pragma unroll
            for (int j = 0; j < 4; j++) kv[j] = Kst[d * 65 + tx + 16 * j];
            #pragma unroll
            for (int i = 0; i < 4; i++)
                #pragma unroll
                for (int j = 0; j < 4; j++) s_acc[i][j] += qv[i] * kv[j];
        }

        // scale + causal mask -> Ss
        #pragma unroll
        for (int i = 0; i < 4; i++) {
            int r = ty + 16 * i, qg = q0 + r;
            #pragma unroll
            for (int j = 0; j < 4; j++) {
                int c = tx + 16 * j, kg = k0 + c;
                Ss[r * 65 + c] = (kg <= qg) ? s_acc[i][j] * scale : -1e30f;
            }
        }
        __syncthreads();

        // online softmax per row (threads 0..63)
        if (tid < 64) {
            int r = tid;
            float m_old = mrow[r];
            float m = m_old;
            for (int c = 0; c < 64; c++) m = fmaxf(m, Ss[r * 65 + c]);
            float l = 0.0f;
            for (int c = 0; c < 64; c++) {
                float p = __expf(Ss[r * 65 + c] - m);
                Ss[r * 65 + c] = p;
                l += p;
            }
            float alpha = __expf(m_old - m);
            arow[r] = alpha;
            mrow[r] = m;
            lrow[r] = lrow[r] * alpha + l;
        }
        __syncthreads();

        // O = O*alpha + P V   (rows ty+16i, cols tx+16j)
        #pragma unroll
        for (int i = 0; i < 4; i++) {
            float al = arow[ty + 16 * i];
            #pragma unroll
            for (int j = 0; j < 8; j++) o_acc[i][j] *= al;
        }
        for (int k = 0; k < 64; k++) {
            float pv[4], vv[8];
            #pragma unroll
            for (int i = 0; i < 4; i++) pv[i] = Ss[(ty + 16 * i) * 65 + k];
            #pragma unroll
            for (int j = 0; j < 8; j++) vv[j] = Vs[k * 128 + tx + 16 * j];
            #pragma unroll
            for (int i = 0; i < 4; i++)
                #pragma unroll
                for (int j = 0; j < 8; j++) o_acc[i][j] += pv[i] * vv[j];
        }
        __syncthreads();
    }

    // write O / l
    #pragma unroll
    for (int i = 0; i < 4; i++) {
        int r = ty + 16 * i;
        float inv = 1.0f / lrow[r];
        #pragma unroll
        for (int j = 0; j < 8; j++) {
            g_o[(size_t)(q0 + r) * QD + h * HD + tx + 16 * j] = o_acc[i][j] * inv;
        }
    }
}

// ---------------------------------------------------------------------------
// launch
// ---------------------------------------------------------------------------
extern "C" void kernel_launch(void* const* d_in, const int* in_sizes, int n_in,
                              void* d_out, int out_size) {
    const float* hidden = (const float*)d_in[0];
    const float* cosb   = (const float*)d_in[1];
    const float* sinb   = (const float*)d_in[2];
    const float* Wq     = (const float*)d_in[3];
    const float* Wk     = (const float*)d_in[4];
    const float* Wv     = (const float*)d_in[5];
    const float* Wo     = (const float*)d_in[6];
    const float* qw     = (const float*)d_in[7];
    const float* kw     = (const float*)d_in[8];
    float* out = (float*)d_out;

    float* qkv_ptr = nullptr;
    float* o_ptr = nullptr;
    cudaGetSymbolAddress((void**)&qkv_ptr, g_qkv);
    cudaGetSymbolAddress((void**)&o_ptr, g_o);

    static const size_t attn_smem = (64 * 128 + 128 * 65 + 64 * 128 + 64 * 65 + 3 * 64) * sizeof(float);
    cudaFuncSetAttribute(flash_attn_kernel, cudaFuncAttributeMaxDynamicSharedMemorySize, (int)attn_smem);

    // QKV projections into fused buffer
    sgemm_nt<<<dim3(QD / BN, SEQ / BM), 256>>>(hidden, Wq, qkv_ptr, SEQ, QD, HID, QKVD, 0);
    sgemm_nt<<<dim3(KVD / BN, SEQ / BM), 256>>>(hidden, Wk, qkv_ptr, SEQ, KVD, HID, QKVD, QD);
    sgemm_nt<<<dim3(KVD / BN, SEQ / BM), 256>>>(hidden, Wv, qkv_ptr, SEQ, KVD, HID, QKVD, QD + KVD);

    // RMSNorm + RoPE on Q and K
    {
        int nwarps = SEQ * 40;
        int nblocks = (nwarps * 32 + 255) / 256;
        rms_rope_kernel<<<nblocks, 256>>>(cosb, sinb, qw, kw);
    }

    // causal GQA flash attention
    flash_attn_kernel<<<dim3(NQH, SEQ / BQ), 256, attn_smem>>>();

    // output projection
    sgemm_nt<<<dim3(HID / BN, SEQ / BM), 256>>>(o_ptr, Wo, out, SEQ, HID, QD, HID, 0);
}

// round 3
// speedup vs baseline: 2.0312x; 2.0312x over previous
#include <cuda_runtime.h>
#include <cuda_bf16.h>
#include <cstdint>
#include <cstdio>

#define SEQ   2048
#define HID   2560
#define QD    4096      // 32 heads * 128
#define KVD   1024      // 8 heads * 128
#define QKVD  6144      // QD + 2*KVD
#define HD    128
#define NQH   32
#define NKVH  8

// ---------------------------------------------------------------------------
// Scratch (device globals; no allocation allowed)
// ---------------------------------------------------------------------------
__device__ float g_qkv[(size_t)SEQ * QKVD];   // [s, 6144]: Q | K | V (fp32)
__device__ float g_o[(size_t)SEQ * QD];       // attention output [s, h*128+d]

// split-precision bf16 copies
__device__ __nv_bfloat16 g_hid_hi[(size_t)SEQ * HID];
__device__ __nv_bfloat16 g_hid_lo[(size_t)SEQ * HID];
__device__ __nv_bfloat16 g_wqkv_hi[(size_t)QKVD * HID];  // Wq|Wk|Wv stacked rows
__device__ __nv_bfloat16 g_wqkv_lo[(size_t)QKVD * HID];
__device__ __nv_bfloat16 g_wo_hi[(size_t)HID * QD];
__device__ __nv_bfloat16 g_wo_lo[(size_t)HID * QD];
__device__ __nv_bfloat16 g_ao_hi[(size_t)SEQ * QD];
__device__ __nv_bfloat16 g_ao_lo[(size_t)SEQ * QD];

// ---------------------------------------------------------------------------
// PTX helpers (arch-agnostic: cp.async / ldmatrix / mma.sync only)
// ---------------------------------------------------------------------------
__device__ __forceinline__ uint32_t smem_u32(const void* p) {
    uint32_t a;
    asm("{ .reg .u64 t; cvta.to.shared.u64 t, %1; cvt.u32.u64 %0, t; }" : "=r"(a) : "l"(p));
    return a;
}
__device__ __forceinline__ void cpa16(uint32_t s, const void* g) {
    asm volatile("cp.async.cg.shared.global [%0], [%1], 16;" :: "r"(s), "l"(g));
}
__device__ __forceinline__ void cpa_commit() {
    asm volatile("cp.async.commit_group;" ::: "memory");
}
__device__ __forceinline__ void cpa_wait1() {
    asm volatile("cp.async.wait_group 1;" ::: "memory");
}
__device__ __forceinline__ void cpa_wait0() {
    asm volatile("cp.async.wait_group 0;" ::: "memory");
}
__device__ __forceinline__ void ldm_x4(uint32_t* r, uint32_t addr) {
    asm volatile("ldmatrix.sync.aligned.m8n8.x4.shared.b16 {%0,%1,%2,%3}, [%4];"
                 : "=r"(r[0]), "=r"(r[1]), "=r"(r[2]), "=r"(r[3]) : "r"(addr));
}
__device__ __forceinline__ void mma_bf16(float* c, const uint32_t* a, const uint32_t* b) {
    asm volatile(
        "mma.sync.aligned.m16n8k16.row.col.f32.bf16.bf16.f32 "
        "{%0,%1,%2,%3}, {%4,%5,%6,%7}, {%8,%9}, {%0,%1,%2,%3};"
        : "+f"(c[0]), "+f"(c[1]), "+f"(c[2]), "+f"(c[3])
        : "r"(a[0]), "r"(a[1]), "r"(a[2]), "r"(a[3]), "r"(b[0]), "r"(b[1]));
}

// ---------------------------------------------------------------------------
// fp32 -> bf16 hi/lo conversion (4 elems/thread)
// ---------------------------------------------------------------------------
__global__ __launch_bounds__(256)
void cvt_hilo(const float* __restrict__ src, __nv_bfloat16* __restrict__ hi,
              __nv_bfloat16* __restrict__ lo, int n) {
    int i = (blockIdx.x * blockDim.x + threadIdx.x) * 4;
    if (i >= n) return;
    float4 x = *(const float4*)(src + i);
    __nv_bfloat16 h0 = __float2bfloat16(x.x);
    __nv_bfloat16 h1 = __float2bfloat16(x.y);
    __nv_bfloat16 h2 = __float2bfloat16(x.z);
    __nv_bfloat16 h3 = __float2bfloat16(x.w);
    __nv_bfloat162 hA; hA.x = h0; hA.y = h1;
    __nv_bfloat162 hB; hB.x = h2; hB.y = h3;
    *(__nv_bfloat162*)(hi + i)     = hA;
    *(__nv_bfloat162*)(hi + i + 2) = hB;
    __nv_bfloat162 lA, lB;
    lA.x = __float2bfloat16(x.x - __bfloat162float(h0));
    lA.y = __float2bfloat16(x.y - __bfloat162float(h1));
    lB.x = __float2bfloat16(x.z - __bfloat162float(h2));
    lB.y = __float2bfloat16(x.w - __bfloat162float(h3));
    *(__nv_bfloat162*)(lo + i)     = lA;
    *(__nv_bfloat162*)(lo + i + 2) = lB;
}

// ---------------------------------------------------------------------------
// mma.sync bf16 split-precision GEMM (NT): C[m,n] = sum_k A[m,k]*B[n,k]
// CTA 128x128, BK=32, 8 warps (4 along M x 2 along N), warp tile 32x64.
// D = Ahi*Bhi + Ahi*Blo + Alo*Bhi accumulated in fp32.
// Double-buffered cp.async. smem stride 40 halves (80B) -> conflict-free
// ldmatrix and 16B-aligned cp.async destinations.
// ---------------------------------------------------------------------------
#define BK 32
#define LDS_STR 40                    // halves per row
#define TILE_H (128 * LDS_STR)        // halves per matrix tile (5120)
#define STAGE_H (4 * TILE_H)          // Ahi|Alo|Bhi|Blo per stage (20480 halves)
#define GEMM_SMEM (2 * STAGE_H * 2)   // bytes: 81920

__global__ __launch_bounds__(256, 2)
void gemm_mma(const __nv_bfloat16* __restrict__ Ahi, const __nv_bfloat16* __restrict__ Alo,
              const __nv_bfloat16* __restrict__ Bhi, const __nv_bfloat16* __restrict__ Blo,
              float* __restrict__ C, int K, int ldc) {
    extern __shared__ __nv_bfloat16 smem[];
    const uint32_t sbase = smem_u32(smem);

    const int tid  = threadIdx.x;
    const int warp = tid >> 5;
    const int lane = tid & 31;
    const int wm   = warp & 3;        // 0..3 -> rows wm*32
    const int wn   = warp >> 2;       // 0..1 -> cols wn*64
    const int bx = blockIdx.x, by = blockIdx.y;

    const __nv_bfloat16* gA[2] = { Ahi + (size_t)(by * 128) * K, Alo + (size_t)(by * 128) * K };
    const __nv_bfloat16* gB[2] = { Bhi + (size_t)(bx * 128) * K, Blo + (size_t)(bx * 128) * K };

    float acc[2][8][4];
    #pragma unroll
    for (int i = 0; i < 2; i++)
        #pragma unroll
        for (int j = 0; j < 8; j++)
            #pragma unroll
            for (int t = 0; t < 4; t++) acc[i][j][t] = 0.0f;

    const int nchunk = K / BK;

    // per-thread load slots: 512 16B-chunks per matrix tile, 2 per thread
    const int r0 = tid >> 2;              // rows tid/4 and tid/4+64
    const int ch0 = (tid & 3) * 8;        // half offset within row (8 halves = 16B)

    auto load_stage = [&](int c, int s) {
        const size_t koff = (size_t)c * BK;
        uint32_t dst = sbase + (uint32_t)(s * STAGE_H) * 2;
        #pragma unroll
        for (int p = 0; p < 2; p++) {     // A hi/lo
            const __nv_bfloat16* src = gA[p] + koff;
            uint32_t d = dst + (uint32_t)(p * TILE_H) * 2;
            cpa16(d + (r0 * LDS_STR + ch0) * 2,        src + (size_t)r0 * K + ch0);
            cpa16(d + ((r0 + 64) * LDS_STR + ch0) * 2, src + (size_t)(r0 + 64) * K + ch0);
        }
        #pragma unroll
        for (int p = 0; p < 2; p++) {     // B hi/lo
            const __nv_bfloat16* src = gB[p] + koff;
            uint32_t d = dst + (uint32_t)((2 + p) * TILE_H) * 2;
            cpa16(d + (r0 * LDS_STR + ch0) * 2,        src + (size_t)r0 * K + ch0);
            cpa16(d + ((r0 + 64) * LDS_STR + ch0) * 2, src + (size_t)(r0 + 64) * K + ch0);
        }
    };

    // ldmatrix lane addressing (constant across chunks)
    const int a_row = (lane & 7) + ((lane >> 3) & 1) * 8;  // 0..15 within m16 tile
    const int a_kof = (lane >> 4) * 8;                      // 0 or 8
    const int b_mat = lane >> 3;                            // 0..3
    const int b_row = lane & 7;
    const int b_kof = (b_mat & 1) * 8;
    const int b_jof = (b_mat >> 1);                         // 0 or 1 (tile within pair)

    load_stage(0, 0);
    cpa_commit();

    for (int c = 0; c < nchunk; c++) {
        if (c + 1 < nchunk) {
            load_stage(c + 1, (c + 1) & 1);
            cpa_commit();
            cpa_wait1();
        } else {
            cpa_wait0();
        }
        __syncthreads();

        const uint32_t st = sbase + (uint32_t)((c & 1) * STAGE_H) * 2;
        const uint32_t sAh = st;
        const uint32_t sAl = st + (uint32_t)TILE_H * 2;
        const uint32_t sBh = st + (uint32_t)(2 * TILE_H) * 2;
        const uint32_t sBl = st + (uint32_t)(3 * TILE_H) * 2;

        #pragma unroll
        for (int ks = 0; ks < 2; ks++) {
            uint32_t ah[2][4], al[2][4];
            #pragma unroll
            for (int i = 0; i < 2; i++) {
                int m_local = wm * 32 + i * 16 + a_row;
                int k = ks * 16 + a_kof;
                uint32_t off = (uint32_t)(m_local * LDS_STR + k) * 2;
                ldm_x4(ah[i], sAh + off);
                ldm_x4(al[i], sAl + off);
            }
            #pragma unroll
            for (int jp = 0; jp < 4; jp++) {
                int n_local = wn * 64 + (jp * 2 + b_jof) * 8 + b_row;
                int k = ks * 16 + b_kof;
                uint32_t off = (uint32_t)(n_local * LDS_STR + k) * 2;
                uint32_t rh[4], rl[4];
                ldm_x4(rh, sBh + off);
                ldm_x4(rl, sBl + off);
                // rh = {b[2jp][0], b[2jp][1], b[2jp+1][0], b[2jp+1][1]}
                #pragma unroll
                for (int jj = 0; jj < 2; jj++) {
                    int j = jp * 2 + jj;
                    #pragma unroll
                    for (int i = 0; i < 2; i++) {
                        mma_bf16(acc[i][j], ah[i], rh + jj * 2);
                        mma_bf16(acc[i][j], ah[i], rl + jj * 2);
                        mma_bf16(acc[i][j], al[i], rh + jj * 2);
                    }
                }
            }
        }
        __syncthreads();
    }

    // epilogue: direct fp32 stores
    const int gid = lane >> 2;
    const int tgc = (lane & 3) * 2;
    #pragma unroll
    for (int i = 0; i < 2; i++) {
        int row = by * 128 + wm * 32 + i * 16 + gid;
        #pragma unroll
        for (int j = 0; j < 8; j++) {
            int col = bx * 128 + wn * 64 + j * 8 + tgc;
            float2 v0 = {acc[i][j][0], acc[i][j][1]};
            float2 v1 = {acc[i][j][2], acc[i][j][3]};
            *(float2*)(C + (size_t)row * ldc + col)       = v0;
            *(float2*)(C + (size_t)(row + 8) * ldc + col) = v1;
        }
    }
}

// ---------------------------------------------------------------------------
// RMSNorm (per head, eps=1e-6) + RoPE, in place on g_qkv Q and K sections.
// ---------------------------------------------------------------------------
__global__ __launch_bounds__(256)
void rms_rope_kernel(const float* __restrict__ cosb, const float* __restrict__ sinb,
                     const float* __restrict__ qw, const float* __restrict__ kw) {
    int gw = (blockIdx.x * blockDim.x + threadIdx.x) >> 5;
    int lane = threadIdx.x & 31;
    if (gw >= SEQ * 40) return;
    int s = gw / 40;
    int h = gw % 40;

    float* base;
    const float* w;
    if (h < NQH) { base = g_qkv + (size_t)s * QKVD + h * HD;              w = qw; }
    else         { base = g_qkv + (size_t)s * QKVD + QD + (h - NQH) * HD; w = kw; }

    int d = lane * 4;
    float4 x = *(float4*)(base + d);
    float ss = x.x * x.x + x.y * x.y + x.z * x.z + x.w * x.w;
    #pragma unroll
    for (int o = 16; o > 0; o >>= 1) ss += __shfl_xor_sync(0xffffffffu, ss, o);
    float r = rsqrtf(ss * (1.0f / 128.0f) + 1e-6f);

    float4 wv = *(const float4*)(w + d);
    float4 xn;
    xn.x = x.x * r * wv.x; xn.y = x.y * r * wv.y;
    xn.z = x.z * r * wv.z; xn.w = x.w * r * wv.w;

    float4 ot;
    ot.x = __shfl_xor_sync(0xffffffffu, xn.x, 16);
    ot.y = __shfl_xor_sync(0xffffffffu, xn.y, 16);
    ot.z = __shfl_xor_sync(0xffffffffu, xn.z, 16);
    ot.w = __shfl_xor_sync(0xffffffffu, xn.w, 16);
    float sgn = (d < 64) ? -1.0f : 1.0f;

    float4 c = *(const float4*)(cosb + (size_t)s * HD + d);
    float4 si = *(const float4*)(sinb + (size_t)s * HD + d);
    float4 out;
    out.x = xn.x * c.x + sgn * ot.x * si.x;
    out.y = xn.y * c.y + sgn * ot.y * si.y;
    out.z = xn.z * c.z + sgn * ot.z * si.z;
    out.w = xn.w * c.w + sgn * ot.w * si.w;
    *(float4*)(base + d) = out;
}

// ---------------------------------------------------------------------------
// Flash attention, fp32, causal, GQA (q head h uses kv head h/4).
// ---------------------------------------------------------------------------
#define BQ 64
#define BKV 64

__global__ __launch_bounds__(256)
void flash_attn_kernel() {
    extern __shared__ float sm[];
    float* Qs   = sm;                    // 64*128
    float* Kst  = Qs + 64 * 128;         // 128*65
    float* Vs   = Kst + 128 * 65;        // 64*128
    float* Ss   = Vs + 64 * 128;         // 64*65
    float* mrow = Ss + 64 * 65;          // 64
    float* lrow = mrow + 64;             // 64
    float* arow = lrow + 64;             // 64

    const int h  = blockIdx.x;
    const int q0 = blockIdx.y * BQ;
    const int kh = h >> 2;
    const int tid = threadIdx.x;
    const int tx = tid & 15, ty = tid >> 4;
    const float scale = 0.08838834764831845f;

    for (int i = tid; i < 64 * 32; i += 256) {
        int row = i >> 5, c4 = (i & 31) << 2;
        *(float4*)(Qs + row * 128 + c4) =
            *(const float4*)(g_qkv + (size_t)(q0 + row) * QKVD + h * HD + c4);
    }
    if (tid < 64) { mrow[tid] = -1e30f; lrow[tid] = 0.0f; }

    float o_acc[4][8];
    #pragma unroll
    for (int i = 0; i < 4; i++)
        #pragma unroll
        for (int j = 0; j < 8; j++) o_acc[i][j] = 0.0f;

    __syncthreads();

    for (int k0 = 0; k0 <= q0; k0 += BKV) {
        {
            int wrow = tid >> 5;
            int d4 = (tid & 31) << 2;
            for (int rr = wrow; rr < 64; rr += 8) {
                const float* kp = g_qkv + (size_t)(k0 + rr) * QKVD + QD + kh * HD;
                float4 k4 = *(const float4*)(kp + d4);
                Kst[(d4 + 0) * 65 + rr] = k4.x;
                Kst[(d4 + 1) * 65 + rr] = k4.y;
                Kst[(d4 + 2) * 65 + rr] = k4.z;
                Kst[(d4 + 3) * 65 + rr] = k4.w;
                const float* vp = g_qkv + (size_t)(k0 + rr) * QKVD + QD + KVD + kh * HD;
                *(float4*)(Vs + rr * 128 + d4) = *(const float4*)(vp + d4);
            }
        }
        __syncthreads();

        float s_acc[4][4];
        #pragma unroll
        for (int i = 0; i < 4; i++)
            #pragma unroll
            for (int j = 0; j < 4; j++) s_acc[i][j] = 0.0f;

        for (int d = 0; d < 128; d++) {
            float qv[4], kv[4];
            #pragma unroll
            for (int i = 0; i < 4; i++) qv[i] = Qs[(ty + 16 * i) * 128 + d];
            #pragma unroll
            for (int j = 0; j < 4; j++) kv[j] = Kst[d * 65 + tx + 16 * j];
            #pragma unroll
            for (int i = 0; i < 4; i++)
                #pragma unroll
                for (int j = 0; j < 4; j++) s_acc[i][j] += qv[i] * kv[j];
        }

        #pragma unroll
        for (int i = 0; i < 4; i++) {
            int r = ty + 16 * i, qg = q0 + r;
            #pragma unroll
            for (int j = 0; j < 4; j++) {
                int c = tx + 16 * j, kg = k0 + c;
                Ss[r * 65 + c] = (kg <= qg) ? s_acc[i][j] * scale : -1e30f;
            }
        }
        __syncthreads();

        if (tid < 64) {
            int r = tid;
            float m_old = mrow[r];
            float m = m_old;
            for (int c = 0; c < 64; c++) m = fmaxf(m, Ss[r * 65 + c]);
            float l = 0.0f;
            for (int c = 0; c < 64; c++) {
                float p = __expf(Ss[r * 65 + c] - m);
                Ss[r * 65 + c] = p;
                l += p;
            }
            float alpha = __expf(m_old - m);
            arow[r] = alpha;
            mrow[r] = m;
            lrow[r] = lrow[r] * alpha + l;
        }
        __syncthreads();

        #pragma unroll
        for (int i = 0; i < 4; i++) {
            float al = arow[ty + 16 * i];
            #pragma unroll
            for (int j = 0; j < 8; j++) o_acc[i][j] *= al;
        }
        for (int k = 0; k < 64; k++) {
            float pv[4], vv[8];
            #pragma unroll
            for (int i = 0; i < 4; i++) pv[i] = Ss[(ty + 16 * i) * 65 + k];
            #pragma unroll
            for (int j = 0; j < 8; j++) vv[j] = Vs[k * 128 + tx + 16 * j];
            #pragma unroll
            for (int i = 0; i < 4; i++)
                #pragma unroll
                for (int j = 0; j < 8; j++) o_acc[i][j] += pv[i] * vv[j];
        }
        __syncthreads();
    }

    #pragma unroll
    for (int i = 0; i < 4; i++) {
        int r = ty + 16 * i;
        float inv = 1.0f / lrow[r];
        #pragma unroll
        for (int j = 0; j < 8; j++) {
            g_o[(size_t)(q0 + r) * QD + h * HD + tx + 16 * j] = o_acc[i][j] * inv;
        }
    }
}

// ---------------------------------------------------------------------------
// launch
// ---------------------------------------------------------------------------
extern "C" void kernel_launch(void* const* d_in, const int* in_sizes, int n_in,
                              void* d_out, int out_size) {
    const float* hidden = (const float*)d_in[0];
    const float* cosb   = (const float*)d_in[1];
    const float* sinb   = (const float*)d_in[2];
    const float* Wq     = (const float*)d_in[3];
    const float* Wk     = (const float*)d_in[4];
    const float* Wv     = (const float*)d_in[5];
    const float* Wo     = (const float*)d_in[6];
    const float* qw     = (const float*)d_in[7];
    const float* kw     = (const float*)d_in[8];
    float* out = (float*)d_out;

    float *qkv_ptr = nullptr, *o_ptr = nullptr;
    __nv_bfloat16 *hid_hi, *hid_lo, *wqkv_hi, *wqkv_lo, *wo_hi, *wo_lo, *ao_hi, *ao_lo;
    cudaGetSymbolAddress((void**)&qkv_ptr, g_qkv);
    cudaGetSymbolAddress((void**)&o_ptr, g_o);
    cudaGetSymbolAddress((void**)&hid_hi, g_hid_hi);
    cudaGetSymbolAddress((void**)&hid_lo, g_hid_lo);
    cudaGetSymbolAddress((void**)&wqkv_hi, g_wqkv_hi);
    cudaGetSymbolAddress((void**)&wqkv_lo, g_wqkv_lo);
    cudaGetSymbolAddress((void**)&wo_hi, g_wo_hi);
    cudaGetSymbolAddress((void**)&wo_lo, g_wo_lo);
    cudaGetSymbolAddress((void**)&ao_hi, g_ao_hi);
    cudaGetSymbolAddress((void**)&ao_lo, g_ao_lo);

    static const size_t attn_smem = (64 * 128 + 128 * 65 + 64 * 128 + 64 * 65 + 3 * 64) * sizeof(float);
    cudaFuncSetAttribute(flash_attn_kernel, cudaFuncAttributeMaxDynamicSharedMemorySize, (int)attn_smem);
    cudaFuncSetAttribute(gemm_mma, cudaFuncAttributeMaxDynamicSharedMemorySize, GEMM_SMEM);

    // fp32 -> bf16 hi/lo conversions
    {
        int n;
        n = SEQ * HID;  cvt_hilo<<<(n / 4 + 255) / 256, 256>>>(hidden, hid_hi, hid_lo, n);
        n = QD * HID;   cvt_hilo<<<(n / 4 + 255) / 256, 256>>>(Wq, wqkv_hi, wqkv_lo, n);
        n = KVD * HID;  cvt_hilo<<<(n / 4 + 255) / 256, 256>>>(Wk, wqkv_hi + (size_t)QD * HID,
                                                               wqkv_lo + (size_t)QD * HID, n);
        n = KVD * HID;  cvt_hilo<<<(n / 4 + 255) / 256, 256>>>(Wv, wqkv_hi + (size_t)(QD + KVD) * HID,
                                                               wqkv_lo + (size_t)(QD + KVD) * HID, n);
        n = HID * QD;   cvt_hilo<<<(n / 4 + 255) / 256, 256>>>(Wo, wo_hi, wo_lo, n);
    }

    // fused QKV projection: C[2048, 6144] = hidden @ [Wq|Wk|Wv]^T
    gemm_mma<<<dim3(QKVD / 128, SEQ / 128), 256, GEMM_SMEM>>>(
        hid_hi, hid_lo, wqkv_hi, wqkv_lo, qkv_ptr, HID, QKVD);

    // RMSNorm + RoPE on Q and K
    {
        int nwarps = SEQ * 40;
        int nblocks = (nwarps * 32 + 255) / 256;
        rms_rope_kernel<<<nblocks, 256>>>(cosb, sinb, qw, kw);
    }

    // causal GQA flash attention
    flash_attn_kernel<<<dim3(NQH, SEQ / BQ), 256, attn_smem>>>();

    // attention output -> bf16 hi/lo
    {
        int n = SEQ * QD;
        cvt_hilo<<<(n / 4 + 255) / 256, 256>>>(o_ptr, ao_hi, ao_lo, n);
    }

    // output projection: out[2048, 2560] = O @ Wo^T
    gemm_mma<<<dim3(HID / 128, SEQ / 128), 256, GEMM_SMEM>>>(
        ao_hi, ao_lo, wo_hi, wo_lo, out, QD, HID);
}

// round 4
// speedup vs baseline: 3.3021x; 1.6257x over previous
#include <cuda_runtime.h>
#include <cuda_bf16.h>
#include <cstdint>
#include <cstdio>

#define SEQ   2048
#define HID   2560
#define QD    4096      // 32 heads * 128
#define KVD   1024      // 8 heads * 128
#define QKVD  6144      // QD + 2*KVD
#define HD    128
#define NQH   32
#define NKVH  8

// ---------------------------------------------------------------------------
// Scratch (device globals; no allocation allowed)
// ---------------------------------------------------------------------------
__device__ float g_qkv[(size_t)SEQ * QKVD];   // [s, 6144]: Q | K | V (fp32)

// split-precision bf16 buffers
__device__ __nv_bfloat16 g_hid_hi[(size_t)SEQ * HID];
__device__ __nv_bfloat16 g_hid_lo[(size_t)SEQ * HID];
__device__ __nv_bfloat16 g_wqkv_hi[(size_t)QKVD * HID];
__device__ __nv_bfloat16 g_wqkv_lo[(size_t)QKVD * HID];
__device__ __nv_bfloat16 g_wo_hi[(size_t)HID * QD];
__device__ __nv_bfloat16 g_wo_lo[(size_t)HID * QD];
__device__ __nv_bfloat16 g_ao_hi[(size_t)SEQ * QD];
__device__ __nv_bfloat16 g_ao_lo[(size_t)SEQ * QD];

// attention operands, [head][seq][128] layout
__device__ __nv_bfloat16 g_qh[(size_t)NQH * SEQ * HD];
__device__ __nv_bfloat16 g_ql[(size_t)NQH * SEQ * HD];
__device__ __nv_bfloat16 g_kh[(size_t)NKVH * SEQ * HD];
__device__ __nv_bfloat16 g_kl[(size_t)NKVH * SEQ * HD];
__device__ __nv_bfloat16 g_vh[(size_t)NKVH * SEQ * HD];
__device__ __nv_bfloat16 g_vl[(size_t)NKVH * SEQ * HD];

// ---------------------------------------------------------------------------
// PTX helpers (arch-agnostic: cp.async / ldmatrix / mma.sync only)
// ---------------------------------------------------------------------------
__device__ __forceinline__ uint32_t smem_u32(const void* p) {
    uint32_t a;
    asm("{ .reg .u64 t; cvta.to.shared.u64 t, %1; cvt.u32.u64 %0, t; }" : "=r"(a) : "l"(p));
    return a;
}
__device__ __forceinline__ void cpa16(uint32_t s, const void* g) {
    asm volatile("cp.async.cg.shared.global [%0], [%1], 16;" :: "r"(s), "l"(g));
}
__device__ __forceinline__ void cpa_commit() {
    asm volatile("cp.async.commit_group;" ::: "memory");
}
__device__ __forceinline__ void cpa_wait1() {
    asm volatile("cp.async.wait_group 1;" ::: "memory");
}
__device__ __forceinline__ void cpa_wait0() {
    asm volatile("cp.async.wait_group 0;" ::: "memory");
}
__device__ __forceinline__ void ldm_x4(uint32_t* r, uint32_t addr) {
    asm volatile("ldmatrix.sync.aligned.m8n8.x4.shared.b16 {%0,%1,%2,%3}, [%4];"
                 : "=r"(r[0]), "=r"(r[1]), "=r"(r[2]), "=r"(r[3]) : "r"(addr));
}
__device__ __forceinline__ void ldm_x4_t(uint32_t* r, uint32_t addr) {
    asm volatile("ldmatrix.sync.aligned.m8n8.x4.trans.shared.b16 {%0,%1,%2,%3}, [%4];"
                 : "=r"(r[0]), "=r"(r[1]), "=r"(r[2]), "=r"(r[3]) : "r"(addr));
}
__device__ __forceinline__ void mma_bf16(float* c, const uint32_t* a, const uint32_t* b) {
    asm volatile(
        "mma.sync.aligned.m16n8k16.row.col.f32.bf16.bf16.f32 "
        "{%0,%1,%2,%3}, {%4,%5,%6,%7}, {%8,%9}, {%0,%1,%2,%3};"
        : "+f"(c[0]), "+f"(c[1]), "+f"(c[2]), "+f"(c[3])
        : "r"(a[0]), "r"(a[1]), "r"(a[2]), "r"(a[3]), "r"(b[0]), "r"(b[1]));
}
__device__ __forceinline__ uint32_t pack_bf2(float x, float y) {
    __nv_bfloat162 t;
    t.x = __float2bfloat16(x);
    t.y = __float2bfloat16(y);
    return *(uint32_t*)&t;
}

// ---------------------------------------------------------------------------
// fp32 -> bf16 hi/lo conversion
// ---------------------------------------------------------------------------
__global__ __launch_bounds__(256)
void cvt_hilo(const float* __restrict__ src, __nv_bfloat16* __restrict__ hi,
              __nv_bfloat16* __restrict__ lo, int n) {
    int i = (blockIdx.x * blockDim.x + threadIdx.x) * 4;
    if (i >= n) return;
    float4 x = *(const float4*)(src + i);
    __nv_bfloat16 h0 = __float2bfloat16(x.x);
    __nv_bfloat16 h1 = __float2bfloat16(x.y);
    __nv_bfloat16 h2 = __float2bfloat16(x.z);
    __nv_bfloat16 h3 = __float2bfloat16(x.w);
    __nv_bfloat162 hA; hA.x = h0; hA.y = h1;
    __nv_bfloat162 hB; hB.x = h2; hB.y = h3;
    *(__nv_bfloat162*)(hi + i)     = hA;
    *(__nv_bfloat162*)(hi + i + 2) = hB;
    __nv_bfloat162 lA, lB;
    lA.x = __float2bfloat16(x.x - __bfloat162float(h0));
    lA.y = __float2bfloat16(x.y - __bfloat162float(h1));
    lB.x = __float2bfloat16(x.z - __bfloat162float(h2));
    lB.y = __float2bfloat16(x.w - __bfloat162float(h3));
    *(__nv_bfloat162*)(lo + i)     = lA;
    *(__nv_bfloat162*)(lo + i + 2) = lB;
}

// ---------------------------------------------------------------------------
// mma.sync bf16 split-precision GEMM (NT)  (unchanged from round 3)
// ---------------------------------------------------------------------------
#define BK 32
#define LDS_STR 40
#define TILE_H (128 * LDS_STR)
#define STAGE_H (4 * TILE_H)
#define GEMM_SMEM (2 * STAGE_H * 2)

__global__ __launch_bounds__(256, 2)
void gemm_mma(const __nv_bfloat16* __restrict__ Ahi, const __nv_bfloat16* __restrict__ Alo,
              const __nv_bfloat16* __restrict__ Bhi, const __nv_bfloat16* __restrict__ Blo,
              float* __restrict__ C, int K, int ldc) {
    extern __shared__ __nv_bfloat16 smem[];
    const uint32_t sbase = smem_u32(smem);

    const int tid  = threadIdx.x;
    const int warp = tid >> 5;
    const int lane = tid & 31;
    const int wm   = warp & 3;
    const int wn   = warp >> 2;
    const int bx = blockIdx.x, by = blockIdx.y;

    const __nv_bfloat16* gA[2] = { Ahi + (size_t)(by * 128) * K, Alo + (size_t)(by * 128) * K };
    const __nv_bfloat16* gB[2] = { Bhi + (size_t)(bx * 128) * K, Blo + (size_t)(bx * 128) * K };

    float acc[2][8][4];
    #pragma unroll
    for (int i = 0; i < 2; i++)
        #pragma unroll
        for (int j = 0; j < 8; j++)
            #pragma unroll
            for (int t = 0; t < 4; t++) acc[i][j][t] = 0.0f;

    const int nchunk = K / BK;
    const int r0 = tid >> 2;
    const int ch0 = (tid & 3) * 8;

    auto load_stage = [&](int c, int s) {
        const size_t koff = (size_t)c * BK;
        uint32_t dst = sbase + (uint32_t)(s * STAGE_H) * 2;
        #pragma unroll
        for (int p = 0; p < 2; p++) {
            const __nv_bfloat16* src = gA[p] + koff;
            uint32_t d = dst + (uint32_t)(p * TILE_H) * 2;
            cpa16(d + (r0 * LDS_STR + ch0) * 2,        src + (size_t)r0 * K + ch0);
            cpa16(d + ((r0 + 64) * LDS_STR + ch0) * 2, src + (size_t)(r0 + 64) * K + ch0);
        }
        #pragma unroll
        for (int p = 0; p < 2; p++) {
            const __nv_bfloat16* src = gB[p] + koff;
            uint32_t d = dst + (uint32_t)((2 + p) * TILE_H) * 2;
            cpa16(d + (r0 * LDS_STR + ch0) * 2,        src + (size_t)r0 * K + ch0);
            cpa16(d + ((r0 + 64) * LDS_STR + ch0) * 2, src + (size_t)(r0 + 64) * K + ch0);
        }
    };

    const int a_row = (lane & 7) + ((lane >> 3) & 1) * 8;
    const int a_kof = (lane >> 4) * 8;
    const int b_mat = lane >> 3;
    const int b_row = lane & 7;
    const int b_kof = (b_mat & 1) * 8;
    const int b_jof = (b_mat >> 1);

    load_stage(0, 0);
    cpa_commit();

    for (int c = 0; c < nchunk; c++) {
        if (c + 1 < nchunk) {
            load_stage(c + 1, (c + 1) & 1);
            cpa_commit();
            cpa_wait1();
        } else {
            cpa_wait0();
        }
        __syncthreads();

        const uint32_t st = sbase + (uint32_t)((c & 1) * STAGE_H) * 2;
        const uint32_t sAh = st;
        const uint32_t sAl = st + (uint32_t)TILE_H * 2;
        const uint32_t sBh = st + (uint32_t)(2 * TILE_H) * 2;
        const uint32_t sBl = st + (uint32_t)(3 * TILE_H) * 2;

        #pragma unroll
        for (int ks = 0; ks < 2; ks++) {
            uint32_t ah[2][4], al[2][4];
            #pragma unroll
            for (int i = 0; i < 2; i++) {
                int m_local = wm * 32 + i * 16 + a_row;
                int k = ks * 16 + a_kof;
                uint32_t off = (uint32_t)(m_local * LDS_STR + k) * 2;
                ldm_x4(ah[i], sAh + off);
                ldm_x4(al[i], sAl + off);
            }
            #pragma unroll
            for (int jp = 0; jp < 4; jp++) {
                int n_local = wn * 64 + (jp * 2 + b_jof) * 8 + b_row;
                int k = ks * 16 + b_kof;
                uint32_t off = (uint32_t)(n_local * LDS_STR + k) * 2;
                uint32_t rh[4], rl[4];
                ldm_x4(rh, sBh + off);
                ldm_x4(rl, sBl + off);
                #pragma unroll
                for (int jj = 0; jj < 2; jj++) {
                    int j = jp * 2 + jj;
                    #pragma unroll
                    for (int i = 0; i < 2; i++) {
                        mma_bf16(acc[i][j], ah[i], rh + jj * 2);
                        mma_bf16(acc[i][j], ah[i], rl + jj * 2);
                        mma_bf16(acc[i][j], al[i], rh + jj * 2);
                    }
                }
            }
        }
        __syncthreads();
    }

    const int gid = lane >> 2;
    const int tgc = (lane & 3) * 2;
    #pragma unroll
    for (int i = 0; i < 2; i++) {
        int row = by * 128 + wm * 32 + i * 16 + gid;
        #pragma unroll
        for (int j = 0; j < 8; j++) {
            int col = bx * 128 + wn * 64 + j * 8 + tgc;
            float2 v0 = {acc[i][j][0], acc[i][j][1]};
            float2 v1 = {acc[i][j][2], acc[i][j][3]};
            *(float2*)(C + (size_t)row * ldc + col)       = v0;
            *(float2*)(C + (size_t)(row + 8) * ldc + col) = v1;
        }
    }
}

// ---------------------------------------------------------------------------
// RMSNorm + RoPE, reading fp32 g_qkv, writing bf16 hi/lo into [h][s][d]
// buffers. 48 "heads": 0-31 Q (norm+rope+scale), 32-39 K (norm+rope),
// 40-47 V (plain convert). One warp each.
// ---------------------------------------------------------------------------
__global__ __launch_bounds__(256)
void rms_rope_kernel(const float* __restrict__ cosb, const float* __restrict__ sinb,
                     const float* __restrict__ qw, const float* __restrict__ kw) {
    int gw = (blockIdx.x * blockDim.x + threadIdx.x) >> 5;
    int lane = threadIdx.x & 31;
    if (gw >= SEQ * 48) return;
    int s = gw / 48;
    int h = gw % 48;
    int d = lane * 4;

    __nv_bfloat16 *dh, *dl;
    float4 out;

    if (h < 40) {
        const float* base;
        const float* w;
        if (h < NQH) {
            base = g_qkv + (size_t)s * QKVD + h * HD;
            w = qw;
            dh = g_qh + ((size_t)h * SEQ + s) * HD;
            dl = g_ql + ((size_t)h * SEQ + s) * HD;
        } else {
            int kh = h - NQH;
            base = g_qkv + (size_t)s * QKVD + QD + kh * HD;
            w = kw;
            dh = g_kh + ((size_t)kh * SEQ + s) * HD;
            dl = g_kl + ((size_t)kh * SEQ + s) * HD;
        }
        float4 x = *(const float4*)(base + d);
        float ss = x.x * x.x + x.y * x.y + x.z * x.z + x.w * x.w;
        #pragma unroll
        for (int o = 16; o > 0; o >>= 1) ss += __shfl_xor_sync(0xffffffffu, ss, o);
        float r = rsqrtf(ss * (1.0f / 128.0f) + 1e-6f);

        float4 wv = *(const float4*)(w + d);
        float4 xn;
        xn.x = x.x * r * wv.x; xn.y = x.y * r * wv.y;
        xn.z = x.z * r * wv.z; xn.w = x.w * r * wv.w;

        float4 ot;
        ot.x = __shfl_xor_sync(0xffffffffu, xn.x, 16);
        ot.y = __shfl_xor_sync(0xffffffffu, xn.y, 16);
        ot.z = __shfl_xor_sync(0xffffffffu, xn.z, 16);
        ot.w = __shfl_xor_sync(0xffffffffu, xn.w, 16);
        float sgn = (d < 64) ? -1.0f : 1.0f;

        float4 c = *(const float4*)(cosb + (size_t)s * HD + d);
        float4 si = *(const float4*)(sinb + (size_t)s * HD + d);
        out.x = xn.x * c.x + sgn * ot.x * si.x;
        out.y = xn.y * c.y + sgn * ot.y * si.y;
        out.z = xn.z * c.z + sgn * ot.z * si.z;
        out.w = xn.w * c.w + sgn * ot.w * si.w;
        if (h < NQH) {   // fold softmax scale into Q
            const float sc = 0.08838834764831845f;
            out.x *= sc; out.y *= sc; out.z *= sc; out.w *= sc;
        }
    } else {
        int vh = h - 40;
        const float* base = g_qkv + (size_t)s * QKVD + QD + KVD + vh * HD;
        out = *(const float4*)(base + d);
        dh = g_vh + ((size_t)vh * SEQ + s) * HD;
        dl = g_vl + ((size_t)vh * SEQ + s) * HD;
    }

    __nv_bfloat162 h0, h1, l0, l1;
    h0.x = __float2bfloat16(out.x); h0.y = __float2bfloat16(out.y);
    h1.x = __float2bfloat16(out.z); h1.y = __float2bfloat16(out.w);
    l0.x = __float2bfloat16(out.x - __bfloat162float(h0.x));
    l0.y = __float2bfloat16(out.y - __bfloat162float(h0.y));
    l1.x = __float2bfloat16(out.z - __bfloat162float(h1.x));
    l1.y = __float2bfloat16(out.w - __bfloat162float(h1.y));
    *(__nv_bfloat162*)(dh + d)     = h0;
    *(__nv_bfloat162*)(dh + d + 2) = h1;
    *(__nv_bfloat162*)(dl + d)     = l0;
    *(__nv_bfloat162*)(dl + d + 2) = l1;
}

// ---------------------------------------------------------------------------
// Tensor-core flash attention (split-precision bf16), causal, GQA.
// CTA = (head, 64-row q tile), 4 warps. BKV=64.
// smem: Qh|Ql|Kh|Kl|Vh|Vl, each 64 rows x 136-half stride = 102 KB.
// ---------------------------------------------------------------------------
#define ASTR 136               // halves per smem row
#define AMAT (64 * ASTR)       // halves per matrix
#define ATTN_SMEM (6 * AMAT * 2)

__global__ __launch_bounds__(128, 2)
void flash_mma_kernel() {
    extern __shared__ __nv_bfloat16 asm_smem[];
    const uint32_t sb = smem_u32(asm_smem);
    const uint32_t sQh = sb;
    const uint32_t sQl = sQh + AMAT * 2;
    const uint32_t sKh = sQl + AMAT * 2;
    const uint32_t sKl = sKh + AMAT * 2;
    const uint32_t sVh = sKl + AMAT * 2;
    const uint32_t sVl = sVh + AMAT * 2;

    const int h  = blockIdx.x;
    const int q0 = blockIdx.y * 64;
    const int kh = h >> 2;
    const int tid = threadIdx.x;
    const int warp = tid >> 5;
    const int lane = tid & 31;
    const int gid = lane >> 2;
    const int tig = lane & 3;

    // load Q tile (hi/lo)
    {
        const __nv_bfloat16* gh = g_qh + ((size_t)h * SEQ + q0) * HD;
        const __nv_bfloat16* gl = g_ql + ((size_t)h * SEQ + q0) * HD;
        #pragma unroll
        for (int i = 0; i < 8; i++) {
            int ch = tid + i * 128;
            int row = ch >> 4, c = ch & 15;
            uint32_t off = (uint32_t)(row * ASTR) * 2 + c * 16;
            cpa16(sQh + off, gh + (size_t)row * HD + c * 8);
            cpa16(sQl + off, gl + (size_t)row * HD + c * 8);
        }
        cpa_commit();
    }

    float oacc[16][4];
    #pragma unroll
    for (int j = 0; j < 16; j++)
        #pragma unroll
        for (int t = 0; t < 4; t++) oacc[j][t] = 0.0f;
    float mrow[2] = {-1e30f, -1e30f};
    float lrow[2] = {0.0f, 0.0f};

    // ldmatrix lane addressing (byte offsets within smem matrices)
    const uint32_t qoff_row = (uint32_t)((warp * 16 + (lane & 15)) * ASTR) * 2;
    const uint32_t qoff_col = (uint32_t)((lane >> 4) * 8) * 2;
    const uint32_t koff_rowbase = (uint32_t)((lane & 7) * ASTR) * 2;
    const uint32_t koff_col = (uint32_t)(((lane >> 3) & 3) * 8) * 2;
    const uint32_t voff_rowbase = (uint32_t)(((lane & 7) + 8 * ((lane >> 3) & 1)) * ASTR) * 2;
    const uint32_t voff_col = (uint32_t)((lane >> 4) * 8) * 2;

    for (int k0 = 0; k0 <= q0; k0 += 64) {
        // load K,V tiles (hi/lo)
        {
            const __nv_bfloat16* bkh = g_kh + ((size_t)kh * SEQ + k0) * HD;
            const __nv_bfloat16* bkl = g_kl + ((size_t)kh * SEQ + k0) * HD;
            const __nv_bfloat16* bvh = g_vh + ((size_t)kh * SEQ + k0) * HD;
            const __nv_bfloat16* bvl = g_vl + ((size_t)kh * SEQ + k0) * HD;
            #pragma unroll
            for (int i = 0; i < 8; i++) {
                int ch = tid + i * 128;
                int row = ch >> 4, c = ch & 15;
                uint32_t off = (uint32_t)(row * ASTR) * 2 + c * 16;
                size_t goff = (size_t)row * HD + c * 8;
                cpa16(sKh + off, bkh + goff);
                cpa16(sKl + off, bkl + goff);
                cpa16(sVh + off, bvh + goff);
                cpa16(sVl + off, bvl + goff);
            }
            cpa_commit();
            cpa_wait0();
        }
        __syncthreads();

        // ---- S = Q K^T (3-term split) ----
        float sacc[8][4];
        #pragma unroll
        for (int j = 0; j < 8; j++)
            #pragma unroll
            for (int t = 0; t < 4; t++) sacc[j][t] = 0.0f;

        #pragma unroll
        for (int ks2 = 0; ks2 < 4; ks2++) {
            uint32_t ah[2][4], al[2][4];
            #pragma unroll
            for (int e = 0; e < 2; e++) {
                uint32_t off = qoff_row + ((uint32_t)((ks2 * 2 + e) * 16) * 2 + qoff_col);
                ldm_x4(ah[e], sQh + off);
                ldm_x4(al[e], sQl + off);
            }
            #pragma unroll
            for (int jn = 0; jn < 8; jn++) {
                uint32_t off = (uint32_t)(jn * 8 * ASTR) * 2 + koff_rowbase +
                               (uint32_t)(ks2 * 32) * 2 + koff_col;
                uint32_t kh4[4], kl4[4];
                ldm_x4(kh4, sKh + off);
                ldm_x4(kl4, sKl + off);
                #pragma unroll
                for (int e = 0; e < 2; e++) {
                    mma_bf16(sacc[jn], ah[e], kh4 + e * 2);
                    mma_bf16(sacc[jn], ah[e], kl4 + e * 2);
                    mma_bf16(sacc[jn], al[e], kh4 + e * 2);
                }
            }
        }

        // ---- causal mask on diagonal tile ----
        if (k0 == q0) {
            int qg0 = q0 + warp * 16 + gid;
            #pragma unroll
            for (int jn = 0; jn < 8; jn++) {
                int kg = k0 + jn * 8 + tig * 2;
                if (kg > qg0)     sacc[jn][0] = -1e30f;
                if (kg + 1 > qg0) sacc[jn][1] = -1e30f;
                if (kg > qg0 + 8)     sacc[jn][2] = -1e30f;
                if (kg + 1 > qg0 + 8) sacc[jn][3] = -1e30f;
            }
        }

        // ---- online softmax (registers) ----
        float mn0 = mrow[0], mn1 = mrow[1];
        #pragma unroll
        for (int jn = 0; jn < 8; jn++) {
            mn0 = fmaxf(mn0, fmaxf(sacc[jn][0], sacc[jn][1]));
            mn1 = fmaxf(mn1, fmaxf(sacc[jn][2], sacc[jn][3]));
        }
        mn0 = fmaxf(mn0, __shfl_xor_sync(0xffffffffu, mn0, 1));
        mn0 = fmaxf(mn0, __shfl_xor_sync(0xffffffffu, mn0, 2));
        mn1 = fmaxf(mn1, __shfl_xor_sync(0xffffffffu, mn1, 1));
        mn1 = fmaxf(mn1, __shfl_xor_sync(0xffffffffu, mn1, 2));
        float al0 = __expf(mrow[0] - mn0);
        float al1 = __expf(mrow[1] - mn1);
        mrow[0] = mn0; mrow[1] = mn1;
        lrow[0] *= al0; lrow[1] *= al1;

        uint32_t ph[8][2], pl[8][2];
        #pragma unroll
        for (int jn = 0; jn < 8; jn++) {
            float p0 = __expf(sacc[jn][0] - mn0);
            float p1 = __expf(sacc[jn][1] - mn0);
            float p2 = __expf(sacc[jn][2] - mn1);
            float p3 = __expf(sacc[jn][3] - mn1);
            lrow[0] += p0 + p1;
            lrow[1] += p2 + p3;
            __nv_bfloat16 b0 = __float2bfloat16(p0), b1 = __float2bfloat16(p1);
            __nv_bfloat16 b2 = __float2bfloat16(p2), b3 = __float2bfloat16(p3);
            __nv_bfloat162 t0; t0.x = b0; t0.y = b1;
            __nv_bfloat162 t1; t1.x = b2; t1.y = b3;
            ph[jn][0] = *(uint32_t*)&t0;
            ph[jn][1] = *(uint32_t*)&t1;
            pl[jn][0] = pack_bf2(p0 - __bfloat162float(b0), p1 - __bfloat162float(b1));
            pl[jn][1] = pack_bf2(p2 - __bfloat162float(b2), p3 - __bfloat162float(b3));
        }
        #pragma unroll
        for (int jd = 0; jd < 16; jd++) {
            oacc[jd][0] *= al0; oacc[jd][1] *= al0;
            oacc[jd][2] *= al1; oacc[jd][3] *= al1;
        }

        // ---- O += P V (3-term split) ----
        #pragma unroll
        for (int kks = 0; kks < 4; kks++) {
            uint32_t aPh[4] = {ph[2 * kks][0], ph[2 * kks][1], ph[2 * kks + 1][0], ph[2 * kks + 1][1]};
            uint32_t aPl[4] = {pl[2 * kks][0], pl[2 * kks][1], pl[2 * kks + 1][0], pl[2 * kks + 1][1]};
            #pragma unroll
            for (int jd2 = 0; jd2 < 8; jd2++) {
                uint32_t off = (uint32_t)(kks * 16 * ASTR) * 2 + voff_rowbase +
                               (uint32_t)(jd2 * 16) * 2 + voff_col;
                uint32_t vh4[4], vl4[4];
                ldm_x4_t(vh4, sVh + off);
                ldm_x4_t(vl4, sVl + off);
                mma_bf16(oacc[jd2 * 2],     aPh, vh4);
                mma_bf16(oacc[jd2 * 2],     aPh, vl4);
                mma_bf16(oacc[jd2 * 2],     aPl, vh4);
                mma_bf16(oacc[jd2 * 2 + 1], aPh, vh4 + 2);
                mma_bf16(oacc[jd2 * 2 + 1], aPh, vl4 + 2);
                mma_bf16(oacc[jd2 * 2 + 1], aPl, vh4 + 2);
            }
        }
        __syncthreads();
    }

    // final: reduce l across quad, normalize, write bf16 hi/lo
    lrow[0] += __shfl_xor_sync(0xffffffffu, lrow[0], 1);
    lrow[0] += __shfl_xor_sync(0xffffffffu, lrow[0], 2);
    lrow[1] += __shfl_xor_sync(0xffffffffu, lrow[1], 1);
    lrow[1] += __shfl_xor_sync(0xffffffffu, lrow[1], 2);
    float inv0 = 1.0f / lrow[0];
    float inv1 = 1.0f / lrow[1];

    int row0 = q0 + warp * 16 + gid;
    #pragma unroll
    for (int jd = 0; jd < 16; jd++) {
        int col = h * HD + jd * 8 + tig * 2;
        float v0 = oacc[jd][0] * inv0, v1 = oacc[jd][1] * inv0;
        float v2 = oacc[jd][2] * inv1, v3 = oacc[jd][3] * inv1;
        __nv_bfloat162 h0; h0.x = __float2bfloat16(v0); h0.y = __float2bfloat16(v1);
        __nv_bfloat162 h1; h1.x = __float2bfloat16(v2); h1.y = __float2bfloat16(v3);
        *(__nv_bfloat162*)(g_ao_hi + (size_t)row0 * QD + col) = h0;
        *(__nv_bfloat162*)(g_ao_hi + (size_t)(row0 + 8) * QD + col) = h1;
        __nv_bfloat162 l0, l1;
        l0.x = __float2bfloat16(v0 - __bfloat162float(h0.x));
        l0.y = __float2bfloat16(v1 - __bfloat162float(h0.y));
        l1.x = __float2bfloat16(v2 - __bfloat162float(h1.x));
        l1.y = __float2bfloat16(v3 - __bfloat162float(h1.y));
        *(__nv_bfloat162*)(g_ao_lo + (size_t)row0 * QD + col) = l0;
        *(__nv_bfloat162*)(g_ao_lo + (size_t)(row0 + 8) * QD + col) = l1;
    }
}

// ---------------------------------------------------------------------------
// launch
// ---------------------------------------------------------------------------
extern "C" void kernel_launch(void* const* d_in, const int* in_sizes, int n_in,
                              void* d_out, int out_size) {
    const float* hidden = (const float*)d_in[0];
    const float* cosb   = (const float*)d_in[1];
    const float* sinb   = (const float*)d_in[2];
    const float* Wq     = (const float*)d_in[3];
    const float* Wk     = (const float*)d_in[4];
    const float* Wv     = (const float*)d_in[5];
    const float* Wo     = (const float*)d_in[6];
    const float* qw     = (const float*)d_in[7];
    const float* kw     = (const float*)d_in[8];
    float* out = (float*)d_out;

    float* qkv_ptr = nullptr;
    __nv_bfloat16 *hid_hi, *hid_lo, *wqkv_hi, *wqkv_lo, *wo_hi, *wo_lo, *ao_hi, *ao_lo;
    cudaGetSymbolAddress((void**)&qkv_ptr, g_qkv);
    cudaGetSymbolAddress((void**)&hid_hi, g_hid_hi);
    cudaGetSymbolAddress((void**)&hid_lo, g_hid_lo);
    cudaGetSymbolAddress((void**)&wqkv_hi, g_wqkv_hi);
    cudaGetSymbolAddress((void**)&wqkv_lo, g_wqkv_lo);
    cudaGetSymbolAddress((void**)&wo_hi, g_wo_hi);
    cudaGetSymbolAddress((void**)&wo_lo, g_wo_lo);
    cudaGetSymbolAddress((void**)&ao_hi, g_ao_hi);
    cudaGetSymbolAddress((void**)&ao_lo, g_ao_lo);

    cudaFuncSetAttribute(gemm_mma, cudaFuncAttributeMaxDynamicSharedMemorySize, GEMM_SMEM);
    cudaFuncSetAttribute(flash_mma_kernel, cudaFuncAttributeMaxDynamicSharedMemorySize, ATTN_SMEM);

    // fp32 -> bf16 hi/lo conversions
    {
        int n;
        n = SEQ * HID;  cvt_hilo<<<(n / 4 + 255) / 256, 256>>>(hidden, hid_hi, hid_lo, n);
        n = QD * HID;   cvt_hilo<<<(n / 4 + 255) / 256, 256>>>(Wq, wqkv_hi, wqkv_lo, n);
        n = KVD * HID;  cvt_hilo<<<(n / 4 + 255) / 256, 256>>>(Wk, wqkv_hi + (size_t)QD * HID,
                                                               wqkv_lo + (size_t)QD * HID, n);
        n = KVD * HID;  cvt_hilo<<<(n / 4 + 255) / 256, 256>>>(Wv, wqkv_hi + (size_t)(QD + KVD) * HID,
                                                               wqkv_lo + (size_t)(QD + KVD) * HID, n);
        n = HID * QD;   cvt_hilo<<<(n / 4 + 255) / 256, 256>>>(Wo, wo_hi, wo_lo, n);
    }

    // fused QKV projection: g_qkv[2048, 6144] = hidden @ [Wq|Wk|Wv]^T
    gemm_mma<<<dim3(QKVD / 128, SEQ / 128), 256, GEMM_SMEM>>>(
        hid_hi, hid_lo, wqkv_hi, wqkv_lo, qkv_ptr, HID, QKVD);

    // RMSNorm + RoPE + split-convert into [h][s][d] bf16 buffers
    {
        int nwarps = SEQ * 48;
        int nblocks = (nwarps * 32 + 255) / 256;
        rms_rope_kernel<<<nblocks, 256>>>(cosb, sinb, qw, kw);
    }

    // tensor-core causal GQA flash attention -> g_ao_hi/lo
    flash_mma_kernel<<<dim3(NQH, SEQ / 64), 128, ATTN_SMEM>>>();

    // output projection: out[2048, 2560] = O @ Wo^T
    gemm_mma<<<dim3(HID / 128, SEQ / 128), 256, GEMM_SMEM>>>(
        ao_hi, ao_lo, wo_hi, wo_lo, out, QD, HID);
}

// round 5
// speedup vs baseline: 3.3529x; 1.0154x over previous
#include <cuda_runtime.h>
#include <cuda_bf16.h>
#include <cstdint>
#include <cstdio>

#define SEQ   2048
#define HID   2560
#define QD    4096      // 32 heads * 128
#define KVD   1024      // 8 heads * 128
#define QKVD  6144      // QD + 2*KVD
#define HD    128
#define NQH   32
#define NKVH  8

// ---------------------------------------------------------------------------
// Scratch (device globals; no allocation allowed)
// ---------------------------------------------------------------------------
__device__ float g_qkv[(size_t)SEQ * QKVD];   // [s, 6144]: Q | K | V (fp32)

// split-precision bf16 buffers
__device__ __nv_bfloat16 g_hid_hi[(size_t)SEQ * HID];
__device__ __nv_bfloat16 g_hid_lo[(size_t)SEQ * HID];
__device__ __nv_bfloat16 g_wqkv_hi[(size_t)QKVD * HID];
__device__ __nv_bfloat16 g_wqkv_lo[(size_t)QKVD * HID];
__device__ __nv_bfloat16 g_wo_hi[(size_t)HID * QD];
__device__ __nv_bfloat16 g_wo_lo[(size_t)HID * QD];
__device__ __nv_bfloat16 g_ao_hi[(size_t)SEQ * QD];
__device__ __nv_bfloat16 g_ao_lo[(size_t)SEQ * QD];

// attention operands, [head][seq][128] layout
__device__ __nv_bfloat16 g_qh[(size_t)NQH * SEQ * HD];
__device__ __nv_bfloat16 g_ql[(size_t)NQH * SEQ * HD];
__device__ __nv_bfloat16 g_kh[(size_t)NKVH * SEQ * HD];
__device__ __nv_bfloat16 g_kl[(size_t)NKVH * SEQ * HD];
__device__ __nv_bfloat16 g_vh[(size_t)NKVH * SEQ * HD];
__device__ __nv_bfloat16 g_vl[(size_t)NKVH * SEQ * HD];

// ---------------------------------------------------------------------------
// PTX helpers (arch-agnostic: cp.async / ldmatrix / mma.sync only)
// ---------------------------------------------------------------------------
__device__ __forceinline__ uint32_t smem_u32(const void* p) {
    uint32_t a;
    asm("{ .reg .u64 t; cvta.to.shared.u64 t, %1; cvt.u32.u64 %0, t; }" : "=r"(a) : "l"(p));
    return a;
}
__device__ __forceinline__ void cpa16(uint32_t s, const void* g) {
    asm volatile("cp.async.cg.shared.global [%0], [%1], 16;" :: "r"(s), "l"(g));
}
__device__ __forceinline__ void cpa_commit() {
    asm volatile("cp.async.commit_group;" ::: "memory");
}
__device__ __forceinline__ void cpa_wait1() {
    asm volatile("cp.async.wait_group 1;" ::: "memory");
}
__device__ __forceinline__ void cpa_wait0() {
    asm volatile("cp.async.wait_group 0;" ::: "memory");
}
__device__ __forceinline__ void ldm_x4(uint32_t* r, uint32_t addr) {
    asm volatile("ldmatrix.sync.aligned.m8n8.x4.shared.b16 {%0,%1,%2,%3}, [%4];"
                 : "=r"(r[0]), "=r"(r[1]), "=r"(r[2]), "=r"(r[3]) : "r"(addr));
}
__device__ __forceinline__ void ldm_x4_t(uint32_t* r, uint32_t addr) {
    asm volatile("ldmatrix.sync.aligned.m8n8.x4.trans.shared.b16 {%0,%1,%2,%3}, [%4];"
                 : "=r"(r[0]), "=r"(r[1]), "=r"(r[2]), "=r"(r[3]) : "r"(addr));
}
__device__ __forceinline__ void mma_bf16(float* c, const uint32_t* a, const uint32_t* b) {
    asm volatile(
        "mma.sync.aligned.m16n8k16.row.col.f32.bf16.bf16.f32 "
        "{%0,%1,%2,%3}, {%4,%5,%6,%7}, {%8,%9}, {%0,%1,%2,%3};"
        : "+f"(c[0]), "+f"(c[1]), "+f"(c[2]), "+f"(c[3])
        : "r"(a[0]), "r"(a[1]), "r"(a[2]), "r"(a[3]), "r"(b[0]), "r"(b[1]));
}
__device__ __forceinline__ uint32_t pack_bf2(float x, float y) {
    __nv_bfloat162 t;
    t.x = __float2bfloat16(x);
    t.y = __float2bfloat16(y);
    return *(uint32_t*)&t;
}

// ---------------------------------------------------------------------------
// fp32 -> bf16 hi/lo conversion
// ---------------------------------------------------------------------------
__global__ __launch_bounds__(256)
void cvt_hilo(const float* __restrict__ src, __nv_bfloat16* __restrict__ hi,
              __nv_bfloat16* __restrict__ lo, int n) {
    int i = (blockIdx.x * blockDim.x + threadIdx.x) * 4;
    if (i >= n) return;
    float4 x = *(const float4*)(src + i);
    __nv_bfloat16 h0 = __float2bfloat16(x.x);
    __nv_bfloat16 h1 = __float2bfloat16(x.y);
    __nv_bfloat16 h2 = __float2bfloat16(x.z);
    __nv_bfloat16 h3 = __float2bfloat16(x.w);
    __nv_bfloat162 hA; hA.x = h0; hA.y = h1;
    __nv_bfloat162 hB; hB.x = h2; hB.y = h3;
    *(__nv_bfloat162*)(hi + i)     = hA;
    *(__nv_bfloat162*)(hi + i + 2) = hB;
    __nv_bfloat162 lA, lB;
    lA.x = __float2bfloat16(x.x - __bfloat162float(h0));
    lA.y = __float2bfloat16(x.y - __bfloat162float(h1));
    lB.x = __float2bfloat16(x.z - __bfloat162float(h2));
    lB.y = __float2bfloat16(x.w - __bfloat162float(h3));
    *(__nv_bfloat162*)(lo + i)     = lA;
    *(__nv_bfloat162*)(lo + i + 2) = lB;
}

// ---------------------------------------------------------------------------
// mma.sync bf16 split-precision GEMM (NT): C[m,n] = sum_k A[m,k]*B[n,k]
// CTA 128x128, BK=32, 8 warps (4x2), warp tile 32x64.
// D = Ahi*Bhi + Ahi*Blo + Alo*Bhi, fp32 accum. MMA issue is term-major so
// same-accumulator RAW distance is 4 (was 1).
// ---------------------------------------------------------------------------
#define BK 32
#define LDS_STR 40
#define TILE_H (128 * LDS_STR)
#define STAGE_H (4 * TILE_H)
#define GEMM_SMEM (2 * STAGE_H * 2)

__global__ __launch_bounds__(256, 2)
void gemm_mma(const __nv_bfloat16* __restrict__ Ahi, const __nv_bfloat16* __restrict__ Alo,
              const __nv_bfloat16* __restrict__ Bhi, const __nv_bfloat16* __restrict__ Blo,
              float* __restrict__ C, int K, int ldc) {
    extern __shared__ __nv_bfloat16 smem[];
    const uint32_t sbase = smem_u32(smem);

    const int tid  = threadIdx.x;
    const int warp = tid >> 5;
    const int lane = tid & 31;
    const int wm   = warp & 3;
    const int wn   = warp >> 2;
    const int bx = blockIdx.x, by = blockIdx.y;

    const __nv_bfloat16* gA[2] = { Ahi + (size_t)(by * 128) * K, Alo + (size_t)(by * 128) * K };
    const __nv_bfloat16* gB[2] = { Bhi + (size_t)(bx * 128) * K, Blo + (size_t)(bx * 128) * K };

    float acc[2][8][4];
    #pragma unroll
    for (int i = 0; i < 2; i++)
        #pragma unroll
        for (int j = 0; j < 8; j++)
            #pragma unroll
            for (int t = 0; t < 4; t++) acc[i][j][t] = 0.0f;

    const int nchunk = K / BK;
    const int r0 = tid >> 2;
    const int ch0 = (tid & 3) * 8;

    auto load_stage = [&](int c, int s) {
        const size_t koff = (size_t)c * BK;
        uint32_t dst = sbase + (uint32_t)(s * STAGE_H) * 2;
        #pragma unroll
        for (int p = 0; p < 2; p++) {
            const __nv_bfloat16* src = gA[p] + koff;
            uint32_t d = dst + (uint32_t)(p * TILE_H) * 2;
            cpa16(d + (r0 * LDS_STR + ch0) * 2,        src + (size_t)r0 * K + ch0);
            cpa16(d + ((r0 + 64) * LDS_STR + ch0) * 2, src + (size_t)(r0 + 64) * K + ch0);
        }
        #pragma unroll
        for (int p = 0; p < 2; p++) {
            const __nv_bfloat16* src = gB[p] + koff;
            uint32_t d = dst + (uint32_t)((2 + p) * TILE_H) * 2;
            cpa16(d + (r0 * LDS_STR + ch0) * 2,        src + (size_t)r0 * K + ch0);
            cpa16(d + ((r0 + 64) * LDS_STR + ch0) * 2, src + (size_t)(r0 + 64) * K + ch0);
        }
    };

    const int a_row = (lane & 7) + ((lane >> 3) & 1) * 8;
    const int a_kof = (lane >> 4) * 8;
    const int b_mat = lane >> 3;
    const int b_row = lane & 7;
    const int b_kof = (b_mat & 1) * 8;
    const int b_jof = (b_mat >> 1);

    load_stage(0, 0);
    cpa_commit();

    for (int c = 0; c < nchunk; c++) {
        if (c + 1 < nchunk) {
            load_stage(c + 1, (c + 1) & 1);
            cpa_commit();
            cpa_wait1();
        } else {
            cpa_wait0();
        }
        __syncthreads();

        const uint32_t st = sbase + (uint32_t)((c & 1) * STAGE_H) * 2;
        const uint32_t sAh = st;
        const uint32_t sAl = st + (uint32_t)TILE_H * 2;
        const uint32_t sBh = st + (uint32_t)(2 * TILE_H) * 2;
        const uint32_t sBl = st + (uint32_t)(3 * TILE_H) * 2;

        #pragma unroll
        for (int ks = 0; ks < 2; ks++) {
            uint32_t ah[2][4], al[2][4];
            #pragma unroll
            for (int i = 0; i < 2; i++) {
                int m_local = wm * 32 + i * 16 + a_row;
                int k = ks * 16 + a_kof;
                uint32_t off = (uint32_t)(m_local * LDS_STR + k) * 2;
                ldm_x4(ah[i], sAh + off);
                ldm_x4(al[i], sAl + off);
            }
            #pragma unroll
            for (int jp = 0; jp < 4; jp++) {
                int n_local = wn * 64 + (jp * 2 + b_jof) * 8 + b_row;
                int k = ks * 16 + b_kof;
                uint32_t off = (uint32_t)(n_local * LDS_STR + k) * 2;
                uint32_t rh[4], rl[4];
                ldm_x4(rh, sBh + off);
                ldm_x4(rl, sBl + off);
                const int j0 = jp * 2, j1 = jp * 2 + 1;
                // term-major issue: same-acc RAW distance = 4
                mma_bf16(acc[0][j0], ah[0], rh);      mma_bf16(acc[0][j1], ah[0], rh + 2);
                mma_bf16(acc[1][j0], ah[1], rh);      mma_bf16(acc[1][j1], ah[1], rh + 2);
                mma_bf16(acc[0][j0], ah[0], rl);      mma_bf16(acc[0][j1], ah[0], rl + 2);
                mma_bf16(acc[1][j0], ah[1], rl);      mma_bf16(acc[1][j1], ah[1], rl + 2);
                mma_bf16(acc[0][j0], al[0], rh);      mma_bf16(acc[0][j1], al[0], rh + 2);
                mma_bf16(acc[1][j0], al[1], rh);      mma_bf16(acc[1][j1], al[1], rh + 2);
            }
        }
        __syncthreads();
    }

    const int gid = lane >> 2;
    const int tgc = (lane & 3) * 2;
    #pragma unroll
    for (int i = 0; i < 2; i++) {
        int row = by * 128 + wm * 32 + i * 16 + gid;
        #pragma unroll
        for (int j = 0; j < 8; j++) {
            int col = bx * 128 + wn * 64 + j * 8 + tgc;
            float2 v0 = {acc[i][j][0], acc[i][j][1]};
            float2 v1 = {acc[i][j][2], acc[i][j][3]};
            *(float2*)(C + (size_t)row * ldc + col)       = v0;
            *(float2*)(C + (size_t)(row + 8) * ldc + col) = v1;
        }
    }
}

// ---------------------------------------------------------------------------
// RMSNorm + RoPE, reading fp32 g_qkv, writing bf16 hi/lo into [h][s][d]
// buffers. 48 "heads": 0-31 Q (norm+rope+scale), 32-39 K (norm+rope),
// 40-47 V (plain convert). One warp each.
// ---------------------------------------------------------------------------
__global__ __launch_bounds__(256)
void rms_rope_kernel(const float* __restrict__ cosb, const float* __restrict__ sinb,
                     const float* __restrict__ qw, const float* __restrict__ kw) {
    int gw = (blockIdx.x * blockDim.x + threadIdx.x) >> 5;
    int lane = threadIdx.x & 31;
    if (gw >= SEQ * 48) return;
    int s = gw / 48;
    int h = gw % 48;
    int d = lane * 4;

    __nv_bfloat16 *dh, *dl;
    float4 out;

    if (h < 40) {
        const float* base;
        const float* w;
        if (h < NQH) {
            base = g_qkv + (size_t)s * QKVD + h * HD;
            w = qw;
            dh = g_qh + ((size_t)h * SEQ + s) * HD;
            dl = g_ql + ((size_t)h * SEQ + s) * HD;
        } else {
            int kh = h - NQH;
            base = g_qkv + (size_t)s * QKVD + QD + kh * HD;
            w = kw;
            dh = g_kh + ((size_t)kh * SEQ + s) * HD;
            dl = g_kl + ((size_t)kh * SEQ + s) * HD;
        }
        float4 x = *(const float4*)(base + d);
        float ss = x.x * x.x + x.y * x.y + x.z * x.z + x.w * x.w;
        #pragma unroll
        for (int o = 16; o > 0; o >>= 1) ss += __shfl_xor_sync(0xffffffffu, ss, o);
        float r = rsqrtf(ss * (1.0f / 128.0f) + 1e-6f);

        float4 wv = *(const float4*)(w + d);
        float4 xn;
        xn.x = x.x * r * wv.x; xn.y = x.y * r * wv.y;
        xn.z = x.z * r * wv.z; xn.w = x.w * r * wv.w;

        float4 ot;
        ot.x = __shfl_xor_sync(0xffffffffu, xn.x, 16);
        ot.y = __shfl_xor_sync(0xffffffffu, xn.y, 16);
        ot.z = __shfl_xor_sync(0xffffffffu, xn.z, 16);
        ot.w = __shfl_xor_sync(0xffffffffu, xn.w, 16);
        float sgn = (d < 64) ? -1.0f : 1.0f;

        float4 c = *(const float4*)(cosb + (size_t)s * HD + d);
        float4 si = *(const float4*)(sinb + (size_t)s * HD + d);
        out.x = xn.x * c.x + sgn * ot.x * si.x;
        out.y = xn.y * c.y + sgn * ot.y * si.y;
        out.z = xn.z * c.z + sgn * ot.z * si.z;
        out.w = xn.w * c.w + sgn * ot.w * si.w;
        if (h < NQH) {   // fold softmax scale into Q
            const float sc = 0.08838834764831845f;
            out.x *= sc; out.y *= sc; out.z *= sc; out.w *= sc;
        }
    } else {
        int vh = h - 40;
        const float* base = g_qkv + (size_t)s * QKVD + QD + KVD + vh * HD;
        out = *(const float4*)(base + d);
        dh = g_vh + ((size_t)vh * SEQ + s) * HD;
        dl = g_vl + ((size_t)vh * SEQ + s) * HD;
    }

    __nv_bfloat162 h0, h1, l0, l1;
    h0.x = __float2bfloat16(out.x); h0.y = __float2bfloat16(out.y);
    h1.x = __float2bfloat16(out.z); h1.y = __float2bfloat16(out.w);
    l0.x = __float2bfloat16(out.x - __bfloat162float(h0.x));
    l0.y = __float2bfloat16(out.y - __bfloat162float(h0.y));
    l1.x = __float2bfloat16(out.z - __bfloat162float(h1.x));
    l1.y = __float2bfloat16(out.w - __bfloat162float(h1.y));
    *(__nv_bfloat162*)(dh + d)     = h0;
    *(__nv_bfloat162*)(dh + d + 2) = h1;
    *(__nv_bfloat162*)(dl + d)     = l0;
    *(__nv_bfloat162*)(dl + d + 2) = l1;
}

// ---------------------------------------------------------------------------
// Tensor-core flash attention (split-precision bf16), causal, GQA.
// CTA = (head, 64-row q tile), 4 warps. BKV=64.
// S and O MMA issue interleaved across accumulator tiles (RAW distance 2).
// ---------------------------------------------------------------------------
#define ASTR 136               // halves per smem row
#define AMAT (64 * ASTR)       // halves per matrix
#define ATTN_SMEM (6 * AMAT * 2)

__global__ __launch_bounds__(128, 2)
void flash_mma_kernel() {
    extern __shared__ __nv_bfloat16 asm_smem[];
    const uint32_t sb = smem_u32(asm_smem);
    const uint32_t sQh = sb;
    const uint32_t sQl = sQh + AMAT * 2;
    const uint32_t sKh = sQl + AMAT * 2;
    const uint32_t sKl = sKh + AMAT * 2;
    const uint32_t sVh = sKl + AMAT * 2;
    const uint32_t sVl = sVh + AMAT * 2;

    const int h  = blockIdx.x;
    const int q0 = blockIdx.y * 64;
    const int kh = h >> 2;
    const int tid = threadIdx.x;
    const int warp = tid >> 5;
    const int lane = tid & 31;
    const int gid = lane >> 2;
    const int tig = lane & 3;

    // load Q tile (hi/lo)
    {
        const __nv_bfloat16* gh = g_qh + ((size_t)h * SEQ + q0) * HD;
        const __nv_bfloat16* gl = g_ql + ((size_t)h * SEQ + q0) * HD;
        #pragma unroll
        for (int i = 0; i < 8; i++) {
            int ch = tid + i * 128;
            int row = ch >> 4, c = ch & 15;
            uint32_t off = (uint32_t)(row * ASTR) * 2 + c * 16;
            cpa16(sQh + off, gh + (size_t)row * HD + c * 8);
            cpa16(sQl + off, gl + (size_t)row * HD + c * 8);
        }
        cpa_commit();
    }

    float oacc[16][4];
    #pragma unroll
    for (int j = 0; j < 16; j++)
        #pragma unroll
        for (int t = 0; t < 4; t++) oacc[j][t] = 0.0f;
    float mrow[2] = {-1e30f, -1e30f};
    float lrow[2] = {0.0f, 0.0f};

    const uint32_t qoff_row = (uint32_t)((warp * 16 + (lane & 15)) * ASTR) * 2;
    const uint32_t qoff_col = (uint32_t)((lane >> 4) * 8) * 2;
    const uint32_t koff_rowbase = (uint32_t)((lane & 7) * ASTR) * 2;
    const uint32_t koff_col = (uint32_t)(((lane >> 3) & 3) * 8) * 2;
    const uint32_t voff_rowbase = (uint32_t)(((lane & 7) + 8 * ((lane >> 3) & 1)) * ASTR) * 2;
    const uint32_t voff_col = (uint32_t)((lane >> 4) * 8) * 2;

    for (int k0 = 0; k0 <= q0; k0 += 64) {
        // load K,V tiles (hi/lo)
        {
            const __nv_bfloat16* bkh = g_kh + ((size_t)kh * SEQ + k0) * HD;
            const __nv_bfloat16* bkl = g_kl + ((size_t)kh * SEQ + k0) * HD;
            const __nv_bfloat16* bvh = g_vh + ((size_t)kh * SEQ + k0) * HD;
            const __nv_bfloat16* bvl = g_vl + ((size_t)kh * SEQ + k0) * HD;
            #pragma unroll
            for (int i = 0; i < 8; i++) {
                int ch = tid + i * 128;
                int row = ch >> 4, c = ch & 15;
                uint32_t off = (uint32_t)(row * ASTR) * 2 + c * 16;
                size_t goff = (size_t)row * HD + c * 8;
                cpa16(sKh + off, bkh + goff);
                cpa16(sKl + off, bkl + goff);
                cpa16(sVh + off, bvh + goff);
                cpa16(sVl + off, bvl + goff);
            }
            cpa_commit();
            cpa_wait0();
        }
        __syncthreads();

        // ---- S = Q K^T (3-term split), jn pairs interleaved ----
        float sacc[8][4];
        #pragma unroll
        for (int j = 0; j < 8; j++)
            #pragma unroll
            for (int t = 0; t < 4; t++) sacc[j][t] = 0.0f;

        #pragma unroll
        for (int ks2 = 0; ks2 < 4; ks2++) {
            uint32_t ah[2][4], al[2][4];
            #pragma unroll
            for (int e = 0; e < 2; e++) {
                uint32_t off = qoff_row + ((uint32_t)((ks2 * 2 + e) * 16) * 2 + qoff_col);
                ldm_x4(ah[e], sQh + off);
                ldm_x4(al[e], sQl + off);
            }
            #pragma unroll
            for (int jn2 = 0; jn2 < 4; jn2++) {
                const int jA = jn2 * 2, jB = jn2 * 2 + 1;
                const uint32_t kcom = koff_rowbase + (uint32_t)(ks2 * 32) * 2 + koff_col;
                uint32_t offA = (uint32_t)(jA * 8 * ASTR) * 2 + kcom;
                uint32_t offB = (uint32_t)(jB * 8 * ASTR) * 2 + kcom;
                uint32_t khA[4], klA[4], khB[4], klB[4];
                ldm_x4(khA, sKh + offA); ldm_x4(khB, sKh + offB);
                ldm_x4(klA, sKl + offA); ldm_x4(klB, sKl + offB);
                // interleaved: same-acc RAW distance = 2
                mma_bf16(sacc[jA], ah[0], khA);     mma_bf16(sacc[jB], ah[0], khB);
                mma_bf16(sacc[jA], ah[1], khA + 2); mma_bf16(sacc[jB], ah[1], khB + 2);
                mma_bf16(sacc[jA], ah[0], klA);     mma_bf16(sacc[jB], ah[0], klB);
                mma_bf16(sacc[jA], ah[1], klA + 2); mma_bf16(sacc[jB], ah[1], klB + 2);
                mma_bf16(sacc[jA], al[0], khA);     mma_bf16(sacc[jB], al[0], khB);
                mma_bf16(sacc[jA], al[1], khA + 2); mma_bf16(sacc[jB], al[1], khB + 2);
            }
        }

        // ---- causal mask on diagonal tile ----
        if (k0 == q0) {
            int qg0 = q0 + warp * 16 + gid;
            #pragma unroll
            for (int jn = 0; jn < 8; jn++) {
                int kg = k0 + jn * 8 + tig * 2;
                if (kg > qg0)     sacc[jn][0] = -1e30f;
                if (kg + 1 > qg0) sacc[jn][1] = -1e30f;
                if (kg > qg0 + 8)     sacc[jn][2] = -1e30f;
                if (kg + 1 > qg0 + 8) sacc[jn][3] = -1e30f;
            }
        }

        // ---- online softmax (registers) ----
        float mn0 = mrow[0], mn1 = mrow[1];
        #pragma unroll
        for (int jn = 0; jn < 8; jn++) {
            mn0 = fmaxf(mn0, fmaxf(sacc[jn][0], sacc[jn][1]));
            mn1 = fmaxf(mn1, fmaxf(sacc[jn][2], sacc[jn][3]));
        }
        mn0 = fmaxf(mn0, __shfl_xor_sync(0xffffffffu, mn0, 1));
        mn0 = fmaxf(mn0, __shfl_xor_sync(0xffffffffu, mn0, 2));
        mn1 = fmaxf(mn1, __shfl_xor_sync(0xffffffffu, mn1, 1));
        mn1 = fmaxf(mn1, __shfl_xor_sync(0xffffffffu, mn1, 2));
        float al0 = __expf(mrow[0] - mn0);
        float al1 = __expf(mrow[1] - mn1);
        mrow[0] = mn0; mrow[1] = mn1;
        lrow[0] *= al0; lrow[1] *= al1;

        uint32_t ph[8][2], pl[8][2];
        #pragma unroll
        for (int jn = 0; jn < 8; jn++) {
            float p0 = __expf(sacc[jn][0] - mn0);
            float p1 = __expf(sacc[jn][1] - mn0);
            float p2 = __expf(sacc[jn][2] - mn1);
            float p3 = __expf(sacc[jn][3] - mn1);
            lrow[0] += p0 + p1;
            lrow[1] += p2 + p3;
            __nv_bfloat16 b0 = __float2bfloat16(p0), b1 = __float2bfloat16(p1);
            __nv_bfloat16 b2 = __float2bfloat16(p2), b3 = __float2bfloat16(p3);
            __nv_bfloat162 t0; t0.x = b0; t0.y = b1;
            __nv_bfloat162 t1; t1.x = b2; t1.y = b3;
            ph[jn][0] = *(uint32_t*)&t0;
            ph[jn][1] = *(uint32_t*)&t1;
            pl[jn][0] = pack_bf2(p0 - __bfloat162float(b0), p1 - __bfloat162float(b1));
            pl[jn][1] = pack_bf2(p2 - __bfloat162float(b2), p3 - __bfloat162float(b3));
        }
        #pragma unroll
        for (int jd = 0; jd < 16; jd++) {
            oacc[jd][0] *= al0; oacc[jd][1] *= al0;
            oacc[jd][2] *= al1; oacc[jd][3] *= al1;
        }

        // ---- O += P V (3-term split), acc pairs interleaved ----
        #pragma unroll
        for (int kks = 0; kks < 4; kks++) {
            uint32_t aPh[4] = {ph[2 * kks][0], ph[2 * kks][1], ph[2 * kks + 1][0], ph[2 * kks + 1][1]};
            uint32_t aPl[4] = {pl[2 * kks][0], pl[2 * kks][1], pl[2 * kks + 1][0], pl[2 * kks + 1][1]};
            #pragma unroll
            for (int jd2 = 0; jd2 < 8; jd2++) {
                uint32_t off = (uint32_t)(kks * 16 * ASTR) * 2 + voff_rowbase +
                               (uint32_t)(jd2 * 16) * 2 + voff_col;
                uint32_t vh4[4], vl4[4];
                ldm_x4_t(vh4, sVh + off);
                ldm_x4_t(vl4, sVl + off);
                float* o0 = oacc[jd2 * 2];
                float* o1 = oacc[jd2 * 2 + 1];
                // interleaved: same-acc RAW distance = 2
                mma_bf16(o0, aPh, vh4);     mma_bf16(o1, aPh, vh4 + 2);
                mma_bf16(o0, aPh, vl4);     mma_bf16(o1, aPh, vl4 + 2);
                mma_bf16(o0, aPl, vh4);     mma_bf16(o1, aPl, vh4 + 2);
            }
        }
        __syncthreads();
    }

    // final: reduce l across quad, normalize, write bf16 hi/lo
    lrow[0] += __shfl_xor_sync(0xffffffffu, lrow[0], 1);
    lrow[0] += __shfl_xor_sync(0xffffffffu, lrow[0], 2);
    lrow[1] += __shfl_xor_sync(0xffffffffu, lrow[1], 1);
    lrow[1] += __shfl_xor_sync(0xffffffffu, lrow[1], 2);
    float inv0 = 1.0f / lrow[0];
    float inv1 = 1.0f / lrow[1];

    int row0 = q0 + warp * 16 + gid;
    #pragma unroll
    for (int jd = 0; jd < 16; jd++) {
        int col = h * HD + jd * 8 + tig * 2;
        float v0 = oacc[jd][0] * inv0, v1 = oacc[jd][1] * inv0;
        float v2 = oacc[jd][2] * inv1, v3 = oacc[jd][3] * inv1;
        __nv_bfloat162 h0; h0.x = __float2bfloat16(v0); h0.y = __float2bfloat16(v1);
        __nv_bfloat162 h1; h1.x = __float2bfloat16(v2); h1.y = __float2bfloat16(v3);
        *(__nv_bfloat162*)(g_ao_hi + (size_t)row0 * QD + col) = h0;
        *(__nv_bfloat162*)(g_ao_hi + (size_t)(row0 + 8) * QD + col) = h1;
        __nv_bfloat162 l0, l1;
        l0.x = __float2bfloat16(v0 - __bfloat162float(h0.x));
        l0.y = __float2bfloat16(v1 - __bfloat162float(h0.y));
        l1.x = __float2bfloat16(v2 - __bfloat162float(h1.x));
        l1.y = __float2bfloat16(v3 - __bfloat162float(h1.y));
        *(__nv_bfloat162*)(g_ao_lo + (size_t)row0 * QD + col) = l0;
        *(__nv_bfloat162*)(g_ao_lo + (size_t)(row0 + 8) * QD + col) = l1;
    }
}

// ---------------------------------------------------------------------------
// launch
// ---------------------------------------------------------------------------
extern "C" void kernel_launch(void* const* d_in, const int* in_sizes, int n_in,
                              void* d_out, int out_size) {
    const float* hidden = (const float*)d_in[0];
    const float* cosb   = (const float*)d_in[1];
    const float* sinb   = (const float*)d_in[2];
    const float* Wq     = (const float*)d_in[3];
    const float* Wk     = (const float*)d_in[4];
    const float* Wv     = (const float*)d_in[5];
    const float* Wo     = (const float*)d_in[6];
    const float* qw     = (const float*)d_in[7];
    const float* kw     = (const float*)d_in[8];
    float* out = (float*)d_out;

    float* qkv_ptr = nullptr;
    __nv_bfloat16 *hid_hi, *hid_lo, *wqkv_hi, *wqkv_lo, *wo_hi, *wo_lo, *ao_hi, *ao_lo;
    cudaGetSymbolAddress((void**)&qkv_ptr, g_qkv);
    cudaGetSymbolAddress((void**)&hid_hi, g_hid_hi);
    cudaGetSymbolAddress((void**)&hid_lo, g_hid_lo);
    cudaGetSymbolAddress((void**)&wqkv_hi, g_wqkv_hi);
    cudaGetSymbolAddress((void**)&wqkv_lo, g_wqkv_lo);
    cudaGetSymbolAddress((void**)&wo_hi, g_wo_hi);
    cudaGetSymbolAddress((void**)&wo_lo, g_wo_lo);
    cudaGetSymbolAddress((void**)&ao_hi, g_ao_hi);
    cudaGetSymbolAddress((void**)&ao_lo, g_ao_lo);

    cudaFuncSetAttribute(gemm_mma, cudaFuncAttributeMaxDynamicSharedMemorySize, GEMM_SMEM);
    cudaFuncSetAttribute(flash_mma_kernel, cudaFuncAttributeMaxDynamicSharedMemorySize, ATTN_SMEM);

    // fp32 -> bf16 hi/lo conversions
    {
        int n;
        n = SEQ * HID;  cvt_hilo<<<(n / 4 + 255) / 256, 256>>>(hidden, hid_hi, hid_lo, n);
        n = QD * HID;   cvt_hilo<<<(n / 4 + 255) / 256, 256>>>(Wq, wqkv_hi, wqkv_lo, n);
        n = KVD * HID;  cvt_hilo<<<(n / 4 + 255) / 256, 256>>>(Wk, wqkv_hi + (size_t)QD * HID,
                                                               wqkv_lo + (size_t)QD * HID, n);
        n = KVD * HID;  cvt_hilo<<<(n / 4 + 255) / 256, 256>>>(Wv, wqkv_hi + (size_t)(QD + KVD) * HID,
                                                               wqkv_lo + (size_t)(QD + KVD) * HID, n);
        n = HID * QD;   cvt_hilo<<<(n / 4 + 255) / 256, 256>>>(Wo, wo_hi, wo_lo, n);
    }

    // fused QKV projection: g_qkv[2048, 6144] = hidden @ [Wq|Wk|Wv]^T
    gemm_mma<<<dim3(QKVD / 128, SEQ / 128), 256, GEMM_SMEM>>>(
        hid_hi, hid_lo, wqkv_hi, wqkv_lo, qkv_ptr, HID, QKVD);

    // RMSNorm + RoPE + split-convert into [h][s][d] bf16 buffers
    {
        int nwarps = SEQ * 48;
        int nblocks = (nwarps * 32 + 255) / 256;
        rms_rope_kernel<<<nblocks, 256>>>(cosb, sinb, qw, kw);
    }

    // tensor-core causal GQA flash attention -> g_ao_hi/lo
    flash_mma_kernel<<<dim3(NQH, SEQ / 64), 128, ATTN_SMEM>>>();

    // output projection: out[2048, 2560] = O @ Wo^T
    gemm_mma<<<dim3(HID / 128, SEQ / 128), 256, GEMM_SMEM>>>(
        ao_hi, ao_lo, wo_hi, wo_lo, out, QD, HID);
}

// round 7
// speedup vs baseline: 5.0119x; 1.4948x over previous
#include <cuda_runtime.h>
#include <cuda_fp16.h>
#include <cstdint>
#include <cstdio>

#define SEQ   2048
#define HID   2560
#define QD    4096      // 32 heads * 128
#define KVD   1024      // 8 heads * 128
#define QKVD  6144      // QD + 2*KVD
#define HD    128
#define NQH   32
#define NKVH  8

// ---------------------------------------------------------------------------
// Scratch (device globals; no allocation allowed)
// ---------------------------------------------------------------------------
__device__ float g_qkv[(size_t)SEQ * QKVD];   // [s, 6144]: Q | K | V (fp32)

// fp16 operand buffers: A operands split hi/lo, B operands single fp16
__device__ __half g_hid_h[(size_t)SEQ * HID];
__device__ __half g_hid_l[(size_t)SEQ * HID];
__device__ __half g_wqkv_h[(size_t)QKVD * HID];   // Wq|Wk|Wv stacked (B operand)
__device__ __half g_wo_h[(size_t)HID * QD];       // Wo (B operand)
__device__ __half g_ao_h[(size_t)SEQ * QD];       // attn out hi (A of Wo gemm)
__device__ __half g_ao_l[(size_t)SEQ * QD];       // attn out lo

// attention operands, [head][seq][128]
__device__ __half g_qh[(size_t)NQH * SEQ * HD];   // Q hi (A operand, split)
__device__ __half g_ql[(size_t)NQH * SEQ * HD];   // Q lo
__device__ __half g_kh[(size_t)NKVH * SEQ * HD];  // K (B operand, single)
__device__ __half g_vh[(size_t)NKVH * SEQ * HD];  // V (B operand, single)

// ---------------------------------------------------------------------------
// PTX helpers
// ---------------------------------------------------------------------------
__device__ __forceinline__ uint32_t smem_u32(const void* p) {
    uint32_t a;
    asm("{ .reg .u64 t; cvta.to.shared.u64 t, %1; cvt.u32.u64 %0, t; }" : "=r"(a) : "l"(p));
    return a;
}
__device__ __forceinline__ void cpa16(uint32_t s, const void* g) {
    asm volatile("cp.async.cg.shared.global [%0], [%1], 16;" :: "r"(s), "l"(g));
}
__device__ __forceinline__ void cpa_commit() {
    asm volatile("cp.async.commit_group;" ::: "memory");
}
__device__ __forceinline__ void cpa_wait1() {
    asm volatile("cp.async.wait_group 1;" ::: "memory");
}
__device__ __forceinline__ void cpa_wait0() {
    asm volatile("cp.async.wait_group 0;" ::: "memory");
}
__device__ __forceinline__ void ldm_x4(uint32_t* r, uint32_t addr) {
    asm volatile("ldmatrix.sync.aligned.m8n8.x4.shared.b16 {%0,%1,%2,%3}, [%4];"
                 : "=r"(r[0]), "=r"(r[1]), "=r"(r[2]), "=r"(r[3]) : "r"(addr));
}
__device__ __forceinline__ void ldm_x4_t(uint32_t* r, uint32_t addr) {
    asm volatile("ldmatrix.sync.aligned.m8n8.x4.trans.shared.b16 {%0,%1,%2,%3}, [%4];"
                 : "=r"(r[0]), "=r"(r[1]), "=r"(r[2]), "=r"(r[3]) : "r"(addr));
}
__device__ __forceinline__ void mma_f16(float* c, const uint32_t* a, const uint32_t* b) {
    asm volatile(
        "mma.sync.aligned.m16n8k16.row.col.f32.f16.f16.f32 "
        "{%0,%1,%2,%3}, {%4,%5,%6,%7}, {%8,%9}, {%0,%1,%2,%3};"
        : "+f"(c[0]), "+f"(c[1]), "+f"(c[2]), "+f"(c[3])
        : "r"(a[0]), "r"(a[1]), "r"(a[2]), "r"(a[3]), "r"(b[0]), "r"(b[1]));
}
__device__ __forceinline__ uint32_t pack_h2(float x, float y) {
    __half2 t = __floats2half2_rn(x, y);
    return *(uint32_t*)&t;
}

// ---------------------------------------------------------------------------
// conversion kernels
// ---------------------------------------------------------------------------
__global__ __launch_bounds__(256)
void cvt_hilo_h(const float* __restrict__ src, __half* __restrict__ hi,
                __half* __restrict__ lo, int n) {
    int i = (blockIdx.x * blockDim.x + threadIdx.x) * 4;
    if (i >= n) return;
    float4 x = *(const float4*)(src + i);
    __half2 hA = __floats2half2_rn(x.x, x.y);
    __half2 hB = __floats2half2_rn(x.z, x.w);
    *(__half2*)(hi + i)     = hA;
    *(__half2*)(hi + i + 2) = hB;
    __half2 lA = __floats2half2_rn(x.x - __half2float(__low2half(hA)),
                                   x.y - __half2float(__high2half(hA)));
    __half2 lB = __floats2half2_rn(x.z - __half2float(__low2half(hB)),
                                   x.w - __half2float(__high2half(hB)));
    *(__half2*)(lo + i)     = lA;
    *(__half2*)(lo + i + 2) = lB;
}

__global__ __launch_bounds__(256)
void cvt_h(const float* __restrict__ src, __half* __restrict__ dst, int n) {
    int i = (blockIdx.x * blockDim.x + threadIdx.x) * 4;
    if (i >= n) return;
    float4 x = *(const float4*)(src + i);
    *(__half2*)(dst + i)     = __floats2half2_rn(x.x, x.y);
    *(__half2*)(dst + i + 2) = __floats2half2_rn(x.z, x.w);
}

// ---------------------------------------------------------------------------
// mma.sync fp16 2-term GEMM (NT): C[m,n] = sum_k A[m,k]*B[n,k]
// A exact (fp16 hi+lo), B rounded to fp16: C = Ah*B + Al*B, fp32 accum.
// CTA 128x128, BK=32, 8 warps (4x2), warp tile 32x64. Double-buffered.
// ---------------------------------------------------------------------------
#define BK 32
#define LDS_STR 40
#define TILE_H (128 * LDS_STR)
#define STAGE_H (3 * TILE_H)          // Ah | Al | Bh
#define GEMM_SMEM (2 * STAGE_H * 2)   // 61440 B

__global__ __launch_bounds__(256, 2)
void gemm_mma(const __half* __restrict__ Ahi, const __half* __restrict__ Alo,
              const __half* __restrict__ Bh,
              float* __restrict__ C, int K, int ldc) {
    extern __shared__ __half smem[];
    const uint32_t sbase = smem_u32(smem);

    const int tid  = threadIdx.x;
    const int warp = tid >> 5;
    const int lane = tid & 31;
    const int wm   = warp & 3;
    const int wn   = warp >> 2;
    const int bx = blockIdx.x, by = blockIdx.y;

    const __half* gAh = Ahi + (size_t)(by * 128) * K;
    const __half* gAl = Alo + (size_t)(by * 128) * K;
    const __half* gB  = Bh  + (size_t)(bx * 128) * K;

    float acc[2][8][4];
    #pragma unroll
    for (int i = 0; i < 2; i++)
        #pragma unroll
        for (int j = 0; j < 8; j++)
            #pragma unroll
            for (int t = 0; t < 4; t++) acc[i][j][t] = 0.0f;

    const int nchunk = K / BK;
    const int r0 = tid >> 2;
    const int ch0 = (tid & 3) * 8;

    auto load_stage = [&](int c, int s) {
        const size_t koff = (size_t)c * BK;
        uint32_t dst = sbase + (uint32_t)(s * STAGE_H) * 2;
        {
            uint32_t d = dst;
            cpa16(d + (r0 * LDS_STR + ch0) * 2,        gAh + (size_t)r0 * K + koff + ch0);
            cpa16(d + ((r0 + 64) * LDS_STR + ch0) * 2, gAh + (size_t)(r0 + 64) * K + koff + ch0);
        }
        {
            uint32_t d = dst + (uint32_t)TILE_H * 2;
            cpa16(d + (r0 * LDS_STR + ch0) * 2,        gAl + (size_t)r0 * K + koff + ch0);
            cpa16(d + ((r0 + 64) * LDS_STR + ch0) * 2, gAl + (size_t)(r0 + 64) * K + koff + ch0);
        }
        {
            uint32_t d = dst + (uint32_t)(2 * TILE_H) * 2;
            cpa16(d + (r0 * LDS_STR + ch0) * 2,        gB + (size_t)r0 * K + koff + ch0);
            cpa16(d + ((r0 + 64) * LDS_STR + ch0) * 2, gB + (size_t)(r0 + 64) * K + koff + ch0);
        }
    };

    const int a_row = (lane & 7) + ((lane >> 3) & 1) * 8;
    const int a_kof = (lane >> 4) * 8;
    const int b_mat = lane >> 3;
    const int b_row = lane & 7;
    const int b_kof = (b_mat & 1) * 8;
    const int b_jof = (b_mat >> 1);

    load_stage(0, 0);
    cpa_commit();

    for (int c = 0; c < nchunk; c++) {
        if (c + 1 < nchunk) {
            load_stage(c + 1, (c + 1) & 1);
            cpa_commit();
            cpa_wait1();
        } else {
            cpa_wait0();
        }
        __syncthreads();

        const uint32_t st = sbase + (uint32_t)((c & 1) * STAGE_H) * 2;
        const uint32_t sAh = st;
        const uint32_t sAl = st + (uint32_t)TILE_H * 2;
        const uint32_t sB  = st + (uint32_t)(2 * TILE_H) * 2;

        #pragma unroll
        for (int ks = 0; ks < 2; ks++) {
            uint32_t ah[2][4], al[2][4];
            #pragma unroll
            for (int i = 0; i < 2; i++) {
                int m_local = wm * 32 + i * 16 + a_row;
                int k = ks * 16 + a_kof;
                uint32_t off = (uint32_t)(m_local * LDS_STR + k) * 2;
                ldm_x4(ah[i], sAh + off);
                ldm_x4(al[i], sAl + off);
            }
            #pragma unroll
            for (int jp = 0; jp < 4; jp++) {
                int n_local = wn * 64 + (jp * 2 + b_jof) * 8 + b_row;
                int k = ks * 16 + b_kof;
                uint32_t off = (uint32_t)(n_local * LDS_STR + k) * 2;
                uint32_t rh[4];
                ldm_x4(rh, sB + off);
                const int j0 = jp * 2, j1 = jp * 2 + 1;
                mma_f16(acc[0][j0], ah[0], rh);   mma_f16(acc[0][j1], ah[0], rh + 2);
                mma_f16(acc[1][j0], ah[1], rh);   mma_f16(acc[1][j1], ah[1], rh + 2);
                mma_f16(acc[0][j0], al[0], rh);   mma_f16(acc[0][j1], al[0], rh + 2);
                mma_f16(acc[1][j0], al[1], rh);   mma_f16(acc[1][j1], al[1], rh + 2);
            }
        }
        __syncthreads();
    }

    const int gid = lane >> 2;
    const int tgc = (lane & 3) * 2;
    #pragma unroll
    for (int i = 0; i < 2; i++) {
        int row = by * 128 + wm * 32 + i * 16 + gid;
        #pragma unroll
        for (int j = 0; j < 8; j++) {
            int col = bx * 128 + wn * 64 + j * 8 + tgc;
            float2 v0 = {acc[i][j][0], acc[i][j][1]};
            float2 v1 = {acc[i][j][2], acc[i][j][3]};
            *(float2*)(C + (size_t)row * ldc + col)       = v0;
            *(float2*)(C + (size_t)(row + 8) * ldc + col) = v1;
        }
    }
}

// ---------------------------------------------------------------------------
// RMSNorm + RoPE, fp32 g_qkv -> fp16 buffers, [h][s][d] layout.
// heads 0-31: Q (norm+rope+scale, hi/lo). 32-39: K (norm+rope, single fp16).
// 40-47: V (single fp16).
// ---------------------------------------------------------------------------
__global__ __launch_bounds__(256)
void rms_rope_kernel(const float* __restrict__ cosb, const float* __restrict__ sinb,
                     const float* __restrict__ qw, const float* __restrict__ kw) {
    int gw = (blockIdx.x * blockDim.x + threadIdx.x) >> 5;
    int lane = threadIdx.x & 31;
    if (gw >= SEQ * 48) return;
    int s = gw / 48;
    int h = gw % 48;
    int d = lane * 4;

    float4 out;
    __half* dsingle = nullptr;

    if (h < 40) {
        const float* base;
        const float* w;
        if (h < NQH) {
            base = g_qkv + (size_t)s * QKVD + h * HD;
            w = qw;
        } else {
            int kh = h - NQH;
            base = g_qkv + (size_t)s * QKVD + QD + kh * HD;
            w = kw;
            dsingle = g_kh + ((size_t)kh * SEQ + s) * HD;
        }
        float4 x = *(const float4*)(base + d);
        float ss = x.x * x.x + x.y * x.y + x.z * x.z + x.w * x.w;
        #pragma unroll
        for (int o = 16; o > 0; o >>= 1) ss += __shfl_xor_sync(0xffffffffu, ss, o);
        float r = rsqrtf(ss * (1.0f / 128.0f) + 1e-6f);

        float4 wv = *(const float4*)(w + d);
        float4 xn;
        xn.x = x.x * r * wv.x; xn.y = x.y * r * wv.y;
        xn.z = x.z * r * wv.z; xn.w = x.w * r * wv.w;

        float4 ot;
        ot.x = __shfl_xor_sync(0xffffffffu, xn.x, 16);
        ot.y = __shfl_xor_sync(0xffffffffu, xn.y, 16);
        ot.z = __shfl_xor_sync(0xffffffffu, xn.z, 16);
        ot.w = __shfl_xor_sync(0xffffffffu, xn.w, 16);
        float sgn = (d < 64) ? -1.0f : 1.0f;

        float4 c = *(const float4*)(cosb + (size_t)s * HD + d);
        float4 si = *(const float4*)(sinb + (size_t)s * HD + d);
        out.x = xn.x * c.x + sgn * ot.x * si.x;
        out.y = xn.y * c.y + sgn * ot.y * si.y;
        out.z = xn.z * c.z + sgn * ot.z * si.z;
        out.w = xn.w * c.w + sgn * ot.w * si.w;
        if (h < NQH) {
            const float sc = 0.08838834764831845f;   // fold softmax scale
            out.x *= sc; out.y *= sc; out.z *= sc; out.w *= sc;
        }
    } else {
        int vh = h - 40;
        const float* base = g_qkv + (size_t)s * QKVD + QD + KVD + vh * HD;
        out = *(const float4*)(base + d);
        dsingle = g_vh + ((size_t)vh * SEQ + s) * HD;
    }

    if (h < NQH) {
        __half* dh = g_qh + ((size_t)h * SEQ + s) * HD;
        __half* dl = g_ql + ((size_t)h * SEQ + s) * HD;
        __half2 h0 = __floats2half2_rn(out.x, out.y);
        __half2 h1 = __floats2half2_rn(out.z, out.w);
        *(__half2*)(dh + d)     = h0;
        *(__half2*)(dh + d + 2) = h1;
        __half2 l0 = __floats2half2_rn(out.x - __half2float(__low2half(h0)),
                                       out.y - __half2float(__high2half(h0)));
        __half2 l1 = __floats2half2_rn(out.z - __half2float(__low2half(h1)),
                                       out.w - __half2float(__high2half(h1)));
        *(__half2*)(dl + d)     = l0;
        *(__half2*)(dl + d + 2) = l1;
    } else {
        *(__half2*)(dsingle + d)     = __floats2half2_rn(out.x, out.y);
        *(__half2*)(dsingle + d + 2) = __floats2half2_rn(out.z, out.w);
    }
}

// ---------------------------------------------------------------------------
// Tensor-core flash attention (2-term fp16), causal, GQA.
// CTA = (head, 64-row q tile), 4 warps. BKV=64.
// S = Qh*K + Ql*K ; O = Ph*V + Pl*V.
// ---------------------------------------------------------------------------
#define ASTR 136               // halves per smem row
#define AMAT (64 * ASTR)       // halves per matrix
#define ATTN_SMEM (4 * AMAT * 2)   // Qh | Ql | Kh | Vh

__global__ __launch_bounds__(128, 2)
void flash_mma_kernel() {
    extern __shared__ __half asm_smem[];
    const uint32_t sb = smem_u32(asm_smem);
    const uint32_t sQh = sb;
    const uint32_t sQl = sQh + AMAT * 2;
    const uint32_t sKh = sQl + AMAT * 2;
    const uint32_t sVh = sKh + AMAT * 2;

    const int h  = blockIdx.x;
    const int q0 = blockIdx.y * 64;
    const int kh = h >> 2;
    const int tid = threadIdx.x;
    const int warp = tid >> 5;
    const int lane = tid & 31;
    const int gid = lane >> 2;
    const int tig = lane & 3;

    // load Q tile (hi/lo)
    {
        const __half* gh = g_qh + ((size_t)h * SEQ + q0) * HD;
        const __half* gl = g_ql + ((size_t)h * SEQ + q0) * HD;
        #pragma unroll
        for (int i = 0; i < 8; i++) {
            int ch = tid + i * 128;
            int row = ch >> 4, c = ch & 15;
            uint32_t off = (uint32_t)(row * ASTR) * 2 + c * 16;
            cpa16(sQh + off, gh + (size_t)row * HD + c * 8);
            cpa16(sQl + off, gl + (size_t)row * HD + c * 8);
        }
        cpa_commit();
    }

    float oacc[16][4];
    #pragma unroll
    for (int j = 0; j < 16; j++)
        #pragma unroll
        for (int t = 0; t < 4; t++) oacc[j][t] = 0.0f;
    float mrow[2] = {-1e30f, -1e30f};
    float lrow[2] = {0.0f, 0.0f};

    const uint32_t qoff_row = (uint32_t)((warp * 16 + (lane & 15)) * ASTR) * 2;
    const uint32_t qoff_col = (uint32_t)((lane >> 4) * 8) * 2;
    const uint32_t koff_rowbase = (uint32_t)((lane & 7) * ASTR) * 2;
    const uint32_t koff_col = (uint32_t)(((lane >> 3) & 3) * 8) * 2;
    const uint32_t voff_rowbase = (uint32_t)(((lane & 7) + 8 * ((lane >> 3) & 1)) * ASTR) * 2;
    const uint32_t voff_col = (uint32_t)((lane >> 4) * 8) * 2;

    for (int k0 = 0; k0 <= q0; k0 += 64) {
        // load K,V tiles
        {
            const __half* bkh = g_kh + ((size_t)kh * SEQ + k0) * HD;
            const __half* bvh = g_vh + ((size_t)kh * SEQ + k0) * HD;
            #pragma unroll
            for (int i = 0; i < 8; i++) {
                int ch = tid + i * 128;
                int row = ch >> 4, c = ch & 15;
                uint32_t off = (uint32_t)(row * ASTR) * 2 + c * 16;
                size_t goff = (size_t)row * HD + c * 8;
                cpa16(sKh + off, bkh + goff);
                cpa16(sVh + off, bvh + goff);
            }
            cpa_commit();
            cpa_wait0();
        }
        __syncthreads();

        // ---- S = Q K^T (2-term) ----
        float sacc[8][4];
        #pragma unroll
        for (int j = 0; j < 8; j++)
            #pragma unroll
            for (int t = 0; t < 4; t++) sacc[j][t] = 0.0f;

        #pragma unroll
        for (int ks2 = 0; ks2 < 4; ks2++) {
            uint32_t qh2[2][4], ql2[2][4];
            #pragma unroll
            for (int e = 0; e < 2; e++) {
                uint32_t off = qoff_row + ((uint32_t)((ks2 * 2 + e) * 16) * 2 + qoff_col);
                ldm_x4(qh2[e], sQh + off);
                ldm_x4(ql2[e], sQl + off);
            }
            #pragma unroll
            for (int jn2 = 0; jn2 < 4; jn2++) {
                const int jA = jn2 * 2, jB = jn2 * 2 + 1;
                const uint32_t kcom = koff_rowbase + (uint32_t)(ks2 * 32) * 2 + koff_col;
                uint32_t offA = (uint32_t)(jA * 8 * ASTR) * 2 + kcom;
                uint32_t offB = (uint32_t)(jB * 8 * ASTR) * 2 + kcom;
                uint32_t khA[4], khB[4];
                ldm_x4(khA, sKh + offA); ldm_x4(khB, sKh + offB);
                mma_f16(sacc[jA], qh2[0], khA);     mma_f16(sacc[jB], qh2[0], khB);
                mma_f16(sacc[jA], qh2[1], khA + 2); mma_f16(sacc[jB], qh2[1], khB + 2);
                mma_f16(sacc[jA], ql2[0], khA);     mma_f16(sacc[jB], ql2[0], khB);
                mma_f16(sacc[jA], ql2[1], khA + 2); mma_f16(sacc[jB], ql2[1], khB + 2);
            }
        }

        // ---- causal mask on diagonal tile ----
        if (k0 == q0) {
            int qg0 = q0 + warp * 16 + gid;
            #pragma unroll
            for (int jn = 0; jn < 8; jn++) {
                int kg = k0 + jn * 8 + tig * 2;
                if (kg > qg0)     sacc[jn][0] = -1e30f;
                if (kg + 1 > qg0) sacc[jn][1] = -1e30f;
                if (kg > qg0 + 8)     sacc[jn][2] = -1e30f;
                if (kg + 1 > qg0 + 8) sacc[jn][3] = -1e30f;
            }
        }

        // ---- online softmax (registers) ----
        float mn0 = mrow[0], mn1 = mrow[1];
        #pragma unroll
        for (int jn = 0; jn < 8; jn++) {
            mn0 = fmaxf(mn0, fmaxf(sacc[jn][0], sacc[jn][1]));
            mn1 = fmaxf(mn1, fmaxf(sacc[jn][2], sacc[jn][3]));
        }
        mn0 = fmaxf(mn0, __shfl_xor_sync(0xffffffffu, mn0, 1));
        mn0 = fmaxf(mn0, __shfl_xor_sync(0xffffffffu, mn0, 2));
        mn1 = fmaxf(mn1, __shfl_xor_sync(0xffffffffu, mn1, 1));
        mn1 = fmaxf(mn1, __shfl_xor_sync(0xffffffffu, mn1, 2));
        float al0 = __expf(mrow[0] - mn0);
        float al1 = __expf(mrow[1] - mn1);
        mrow[0] = mn0; mrow[1] = mn1;
        lrow[0] *= al0; lrow[1] *= al1;

        uint32_t ph[8][2], pl[8][2];
        #pragma unroll
        for (int jn = 0; jn < 8; jn++) {
            float p0 = __expf(sacc[jn][0] - mn0);
            float p1 = __expf(sacc[jn][1] - mn0);
            float p2 = __expf(sacc[jn][2] - mn1);
            float p3 = __expf(sacc[jn][3] - mn1);
            lrow[0] += p0 + p1;
            lrow[1] += p2 + p3;
            __half2 t0 = __floats2half2_rn(p0, p1);
            __half2 t1 = __floats2half2_rn(p2, p3);
            ph[jn][0] = *(uint32_t*)&t0;
            ph[jn][1] = *(uint32_t*)&t1;
            pl[jn][0] = pack_h2(p0 - __half2float(__low2half(t0)),
                                p1 - __half2float(__high2half(t0)));
            pl[jn][1] = pack_h2(p2 - __half2float(__low2half(t1)),
                                p3 - __half2float(__high2half(t1)));
        }
        #pragma unroll
        for (int jd = 0; jd < 16; jd++) {
            oacc[jd][0] *= al0; oacc[jd][1] *= al0;
            oacc[jd][2] *= al1; oacc[jd][3] *= al1;
        }

        // ---- O += P V (2-term) ----
        #pragma unroll
        for (int kks = 0; kks < 4; kks++) {
            uint32_t aPh[4] = {ph[2 * kks][0], ph[2 * kks][1], ph[2 * kks + 1][0], ph[2 * kks + 1][1]};
            uint32_t aPl[4] = {pl[2 * kks][0], pl[2 * kks][1], pl[2 * kks + 1][0], pl[2 * kks + 1][1]};
            #pragma unroll
            for (int jd2 = 0; jd2 < 8; jd2++) {
                uint32_t off = (uint32_t)(kks * 16 * ASTR) * 2 + voff_rowbase +
                               (uint32_t)(jd2 * 16) * 2 + voff_col;
                uint32_t vh4[4];
                ldm_x4_t(vh4, sVh + off);
                float* o0 = oacc[jd2 * 2];
                float* o1 = oacc[jd2 * 2 + 1];
                mma_f16(o0, aPh, vh4);     mma_f16(o1, aPh, vh4 + 2);
                mma_f16(o0, aPl, vh4);     mma_f16(o1, aPl, vh4 + 2);
            }
        }
        __syncthreads();
    }

    // final: reduce l across quad, normalize, write fp16 hi/lo
    lrow[0] += __shfl_xor_sync(0xffffffffu, lrow[0], 1);
    lrow[0] += __shfl_xor_sync(0xffffffffu, lrow[0], 2);
    lrow[1] += __shfl_xor_sync(0xffffffffu, lrow[1], 1);
    lrow[1] += __shfl_xor_sync(0xffffffffu, lrow[1], 2);
    float inv0 = 1.0f / lrow[0];
    float inv1 = 1.0f / lrow[1];

    int row0 = q0 + warp * 16 + gid;
    #pragma unroll
    for (int jd = 0; jd < 16; jd++) {
        int col = h * HD + jd * 8 + tig * 2;
        float v0 = oacc[jd][0] * inv0, v1 = oacc[jd][1] * inv0;
        float v2 = oacc[jd][2] * inv1, v3 = oacc[jd][3] * inv1;
        __half2 h0 = __floats2half2_rn(v0, v1);
        __half2 h1 = __floats2half2_rn(v2, v3);
        *(__half2*)(g_ao_h + (size_t)row0 * QD + col)       = h0;
        *(__half2*)(g_ao_h + (size_t)(row0 + 8) * QD + col) = h1;
        __half2 l0 = __floats2half2_rn(v0 - __half2float(__low2half(h0)),
                                       v1 - __half2float(__high2half(h0)));
        __half2 l1 = __floats2half2_rn(v2 - __half2float(__low2half(h1)),
                                       v3 - __half2float(__high2half(h1)));
        *(__half2*)(g_ao_l + (size_t)row0 * QD + col)       = l0;
        *(__half2*)(g_ao_l + (size_t)(row0 + 8) * QD + col) = l1;
    }
}

// ---------------------------------------------------------------------------
// launch
// ---------------------------------------------------------------------------
extern "C" void kernel_launch(void* const* d_in, const int* in_sizes, int n_in,
                              void* d_out, int out_size) {
    const float* hidden = (const float*)d_in[0];
    const float* cosb   = (const float*)d_in[1];
    const float* sinb   = (const float*)d_in[2];
    const float* Wq     = (const float*)d_in[3];
    const float* Wk     = (const float*)d_in[4];
    const float* Wv     = (const float*)d_in[5];
    const float* Wo     = (const float*)d_in[6];
    const float* qw     = (const float*)d_in[7];
    const float* kw     = (const float*)d_in[8];
    float* out = (float*)d_out;

    float* qkv_ptr = nullptr;
    __half *hid_h, *hid_l, *wqkv_h, *wo_h, *ao_h, *ao_l;
    cudaGetSymbolAddress((void**)&qkv_ptr, g_qkv);
    cudaGetSymbolAddress((void**)&hid_h, g_hid_h);
    cudaGetSymbolAddress((void**)&hid_l, g_hid_l);
    cudaGetSymbolAddress((void**)&wqkv_h, g_wqkv_h);
    cudaGetSymbolAddress((void**)&wo_h, g_wo_h);
    cudaGetSymbolAddress((void**)&ao_h, g_ao_h);
    cudaGetSymbolAddress((void**)&ao_l, g_ao_l);

    cudaFuncSetAttribute(gemm_mma, cudaFuncAttributeMaxDynamicSharedMemorySize, GEMM_SMEM);
    cudaFuncSetAttribute(flash_mma_kernel, cudaFuncAttributeMaxDynamicSharedMemorySize, ATTN_SMEM);

    // conversions: hidden -> hi/lo (A operand); weights -> single fp16 (B operands)
    {
        int n;
        n = SEQ * HID;  cvt_hilo_h<<<(n / 4 + 255) / 256, 256>>>(hidden, hid_h, hid_l, n);
        n = QD * HID;   cvt_h<<<(n / 4 + 255) / 256, 256>>>(Wq, wqkv_h, n);
        n = KVD * HID;  cvt_h<<<(n / 4 + 255) / 256, 256>>>(Wk, wqkv_h + (size_t)QD * HID, n);
        n = KVD * HID;  cvt_h<<<(n / 4 + 255) / 256, 256>>>(Wv, wqkv_h + (size_t)(QD + KVD) * HID, n);
        n = HID * QD;   cvt_h<<<(n / 4 + 255) / 256, 256>>>(Wo, wo_h, n);
    }

    // fused QKV projection: g_qkv[2048, 6144] = hidden @ [Wq|Wk|Wv]^T
    gemm_mma<<<dim3(QKVD / 128, SEQ / 128), 256, GEMM_SMEM>>>(
        hid_h, hid_l, wqkv_h, qkv_ptr, HID, QKVD);

    // RMSNorm + RoPE + fp16 conversion into [h][s][d] buffers
    {
        int nwarps = SEQ * 48;
        int nblocks = (nwarps * 32 + 255) / 256;
        rms_rope_kernel<<<nblocks, 256>>>(cosb, sinb, qw, kw);
    }

    // tensor-core causal GQA flash attention -> g_ao_h/l
    flash_mma_kernel<<<dim3(NQH, SEQ / 64), 128, ATTN_SMEM>>>();

    // output projection: out[2048, 2560] = O @ Wo^T
    gemm_mma<<<dim3(HID / 128, SEQ / 128), 256, GEMM_SMEM>>>(
        ao_h, ao_l, wo_h, out, QD, HID);
}

// round 8
// speedup vs baseline: 7.2777x; 1.4521x over previous
#include <cuda_runtime.h>
#include <cuda_fp16.h>
#include <cstdint>
#include <cstdio>

#define SEQ   2048
#define HID   2560
#define QD    4096      // 32 heads * 128
#define KVD   1024      // 8 heads * 128
#define QKVD  6144      // QD + 2*KVD
#define HD    128
#define NQH   32
#define NKVH  8

// ---------------------------------------------------------------------------
// Scratch (device globals; no allocation allowed)
// ---------------------------------------------------------------------------
__device__ float g_qkv[(size_t)SEQ * QKVD];   // [s, 6144]: Q | K | V (fp32)

// fp16 operand buffers
__device__ __half g_hid_h[(size_t)SEQ * HID];     // hidden (A of QKV gemm)
__device__ __half g_wqkv_h[(size_t)QKVD * HID];   // Wq|Wk|Wv stacked (B)
__device__ __half g_wo_h[(size_t)HID * QD];       // Wo (B)
__device__ __half g_ao_h[(size_t)SEQ * QD];       // attn out (A of Wo gemm)

// attention operands, [head][seq][128]
__device__ __half g_qh[(size_t)NQH * SEQ * HD];   // Q hi (split A)
__device__ __half g_ql[(size_t)NQH * SEQ * HD];   // Q lo
__device__ __half g_kh[(size_t)NKVH * SEQ * HD];  // K
__device__ __half g_vh[(size_t)NKVH * SEQ * HD];  // V

// ---------------------------------------------------------------------------
// PTX helpers
// ---------------------------------------------------------------------------
__device__ __forceinline__ uint32_t smem_u32(const void* p) {
    uint32_t a;
    asm("{ .reg .u64 t; cvta.to.shared.u64 t, %1; cvt.u32.u64 %0, t; }" : "=r"(a) : "l"(p));
    return a;
}
__device__ __forceinline__ void cpa16(uint32_t s, const void* g) {
    asm volatile("cp.async.cg.shared.global [%0], [%1], 16;" :: "r"(s), "l"(g));
}
__device__ __forceinline__ void cpa_commit() {
    asm volatile("cp.async.commit_group;" ::: "memory");
}
__device__ __forceinline__ void cpa_wait1() {
    asm volatile("cp.async.wait_group 1;" ::: "memory");
}
__device__ __forceinline__ void cpa_wait0() {
    asm volatile("cp.async.wait_group 0;" ::: "memory");
}
__device__ __forceinline__ void ldm_x4(uint32_t* r, uint32_t addr) {
    asm volatile("ldmatrix.sync.aligned.m8n8.x4.shared.b16 {%0,%1,%2,%3}, [%4];"
                 : "=r"(r[0]), "=r"(r[1]), "=r"(r[2]), "=r"(r[3]) : "r"(addr));
}
__device__ __forceinline__ void ldm_x4_t(uint32_t* r, uint32_t addr) {
    asm volatile("ldmatrix.sync.aligned.m8n8.x4.trans.shared.b16 {%0,%1,%2,%3}, [%4];"
                 : "=r"(r[0]), "=r"(r[1]), "=r"(r[2]), "=r"(r[3]) : "r"(addr));
}
__device__ __forceinline__ void mma_f16(float* c, const uint32_t* a, const uint32_t* b) {
    asm volatile(
        "mma.sync.aligned.m16n8k16.row.col.f32.f16.f16.f32 "
        "{%0,%1,%2,%3}, {%4,%5,%6,%7}, {%8,%9}, {%0,%1,%2,%3};"
        : "+f"(c[0]), "+f"(c[1]), "+f"(c[2]), "+f"(c[3])
        : "r"(a[0]), "r"(a[1]), "r"(a[2]), "r"(a[3]), "r"(b[0]), "r"(b[1]));
}

// ---------------------------------------------------------------------------
// conversion kernel (fp32 -> fp16)
// ---------------------------------------------------------------------------
__global__ __launch_bounds__(256)
void cvt_h(const float* __restrict__ src, __half* __restrict__ dst, int n) {
    int i = (blockIdx.x * blockDim.x + threadIdx.x) * 4;
    if (i >= n) return;
    float4 x = *(const float4*)(src + i);
    *(__half2*)(dst + i)     = __floats2half2_rn(x.x, x.y);
    *(__half2*)(dst + i + 2) = __floats2half2_rn(x.z, x.w);
}

// ---------------------------------------------------------------------------
// mma.sync fp16 GEMM (NT): C[m,n] = sum_k A[m,k]*B[n,k], fp32 accum.
// CTA 128x128, BK=32, 8 warps (4x2), warp tile 32x64. Double-buffered.
// ---------------------------------------------------------------------------
#define BK 32
#define LDS_STR 40
#define TILE_H (128 * LDS_STR)
#define STAGE_H (2 * TILE_H)          // A | B
#define GEMM_SMEM (2 * STAGE_H * 2)   // 40960 B

__global__ __launch_bounds__(256, 2)
void gemm_mma(const __half* __restrict__ Ah, const __half* __restrict__ Bh,
              float* __restrict__ C, int K, int ldc) {
    extern __shared__ __half smem[];
    const uint32_t sbase = smem_u32(smem);

    const int tid  = threadIdx.x;
    const int warp = tid >> 5;
    const int lane = tid & 31;
    const int wm   = warp & 3;
    const int wn   = warp >> 2;
    const int bx = blockIdx.x, by = blockIdx.y;

    const __half* gA = Ah + (size_t)(by * 128) * K;
    const __half* gB = Bh + (size_t)(bx * 128) * K;

    float acc[2][8][4];
    #pragma unroll
    for (int i = 0; i < 2; i++)
        #pragma unroll
        for (int j = 0; j < 8; j++)
            #pragma unroll
            for (int t = 0; t < 4; t++) acc[i][j][t] = 0.0f;

    const int nchunk = K / BK;
    const int r0 = tid >> 2;
    const int ch0 = (tid & 3) * 8;

    auto load_stage = [&](int c, int s) {
        const size_t koff = (size_t)c * BK;
        uint32_t dst = sbase + (uint32_t)(s * STAGE_H) * 2;
        {
            uint32_t d = dst;
            cpa16(d + (r0 * LDS_STR + ch0) * 2,        gA + (size_t)r0 * K + koff + ch0);
            cpa16(d + ((r0 + 64) * LDS_STR + ch0) * 2, gA + (size_t)(r0 + 64) * K + koff + ch0);
        }
        {
            uint32_t d = dst + (uint32_t)TILE_H * 2;
            cpa16(d + (r0 * LDS_STR + ch0) * 2,        gB + (size_t)r0 * K + koff + ch0);
            cpa16(d + ((r0 + 64) * LDS_STR + ch0) * 2, gB + (size_t)(r0 + 64) * K + koff + ch0);
        }
    };

    const int a_row = (lane & 7) + ((lane >> 3) & 1) * 8;
    const int a_kof = (lane >> 4) * 8;
    const int b_mat = lane >> 3;
    const int b_row = lane & 7;
    const int b_kof = (b_mat & 1) * 8;
    const int b_jof = (b_mat >> 1);

    load_stage(0, 0);
    cpa_commit();

    for (int c = 0; c < nchunk; c++) {
        if (c + 1 < nchunk) {
            load_stage(c + 1, (c + 1) & 1);
            cpa_commit();
            cpa_wait1();
        } else {
            cpa_wait0();
        }
        __syncthreads();

        const uint32_t st = sbase + (uint32_t)((c & 1) * STAGE_H) * 2;
        const uint32_t sA = st;
        const uint32_t sB = st + (uint32_t)TILE_H * 2;

        #pragma unroll
        for (int ks = 0; ks < 2; ks++) {
            uint32_t ah[2][4];
            #pragma unroll
            for (int i = 0; i < 2; i++) {
                int m_local = wm * 32 + i * 16 + a_row;
                int k = ks * 16 + a_kof;
                uint32_t off = (uint32_t)(m_local * LDS_STR + k) * 2;
                ldm_x4(ah[i], sA + off);
            }
            #pragma unroll
            for (int jp = 0; jp < 4; jp++) {
                int n_local = wn * 64 + (jp * 2 + b_jof) * 8 + b_row;
                int k = ks * 16 + b_kof;
                uint32_t off = (uint32_t)(n_local * LDS_STR + k) * 2;
                uint32_t rh[4];
                ldm_x4(rh, sB + off);
                const int j0 = jp * 2, j1 = jp * 2 + 1;
                mma_f16(acc[0][j0], ah[0], rh);   mma_f16(acc[0][j1], ah[0], rh + 2);
                mma_f16(acc[1][j0], ah[1], rh);   mma_f16(acc[1][j1], ah[1], rh + 2);
            }
        }
        __syncthreads();
    }

    const int gid = lane >> 2;
    const int tgc = (lane & 3) * 2;
    #pragma unroll
    for (int i = 0; i < 2; i++) {
        int row = by * 128 + wm * 32 + i * 16 + gid;
        #pragma unroll
        for (int j = 0; j < 8; j++) {
            int col = bx * 128 + wn * 64 + j * 8 + tgc;
            float2 v0 = {acc[i][j][0], acc[i][j][1]};
            float2 v1 = {acc[i][j][2], acc[i][j][3]};
            *(float2*)(C + (size_t)row * ldc + col)       = v0;
            *(float2*)(C + (size_t)(row + 8) * ldc + col) = v1;
        }
    }
}

// ---------------------------------------------------------------------------
// RMSNorm + RoPE, fp32 g_qkv -> fp16 buffers, [h][s][d] layout.
// heads 0-31: Q (norm+rope+scale, hi/lo). 32-39: K (norm+rope, single fp16).
// 40-47: V (single fp16).
// ---------------------------------------------------------------------------
__global__ __launch_bounds__(256)
void rms_rope_kernel(const float* __restrict__ cosb, const float* __restrict__ sinb,
                     const float* __restrict__ qw, const float* __restrict__ kw) {
    int gw = (blockIdx.x * blockDim.x + threadIdx.x) >> 5;
    int lane = threadIdx.x & 31;
    if (gw >= SEQ * 48) return;
    int s = gw / 48;
    int h = gw % 48;
    int d = lane * 4;

    float4 out;
    __half* dsingle = nullptr;

    if (h < 40) {
        const float* base;
        const float* w;
        if (h < NQH) {
            base = g_qkv + (size_t)s * QKVD + h * HD;
            w = qw;
        } else {
            int kh = h - NQH;
            base = g_qkv + (size_t)s * QKVD + QD + kh * HD;
            w = kw;
            dsingle = g_kh + ((size_t)kh * SEQ + s) * HD;
        }
        float4 x = *(const float4*)(base + d);
        float ss = x.x * x.x + x.y * x.y + x.z * x.z + x.w * x.w;
        #pragma unroll
        for (int o = 16; o > 0; o >>= 1) ss += __shfl_xor_sync(0xffffffffu, ss, o);
        float r = rsqrtf(ss * (1.0f / 128.0f) + 1e-6f);

        float4 wv = *(const float4*)(w + d);
        float4 xn;
        xn.x = x.x * r * wv.x; xn.y = x.y * r * wv.y;
        xn.z = x.z * r * wv.z; xn.w = x.w * r * wv.w;

        float4 ot;
        ot.x = __shfl_xor_sync(0xffffffffu, xn.x, 16);
        ot.y = __shfl_xor_sync(0xffffffffu, xn.y, 16);
        ot.z = __shfl_xor_sync(0xffffffffu, xn.z, 16);
        ot.w = __shfl_xor_sync(0xffffffffu, xn.w, 16);
        float sgn = (d < 64) ? -1.0f : 1.0f;

        float4 c = *(const float4*)(cosb + (size_t)s * HD + d);
        float4 si = *(const float4*)(sinb + (size_t)s * HD + d);
        out.x = xn.x * c.x + sgn * ot.x * si.x;
        out.y = xn.y * c.y + sgn * ot.y * si.y;
        out.z = xn.z * c.z + sgn * ot.z * si.z;
        out.w = xn.w * c.w + sgn * ot.w * si.w;
        if (h < NQH) {
            const float sc = 0.08838834764831845f;   // fold softmax scale
            out.x *= sc; out.y *= sc; out.z *= sc; out.w *= sc;
        }
    } else {
        int vh = h - 40;
        const float* base = g_qkv + (size_t)s * QKVD + QD + KVD + vh * HD;
        out = *(const float4*)(base + d);
        dsingle = g_vh + ((size_t)vh * SEQ + s) * HD;
    }

    if (h < NQH) {
        __half* dh = g_qh + ((size_t)h * SEQ + s) * HD;
        __half* dl = g_ql + ((size_t)h * SEQ + s) * HD;
        __half2 h0 = __floats2half2_rn(out.x, out.y);
        __half2 h1 = __floats2half2_rn(out.z, out.w);
        *(__half2*)(dh + d)     = h0;
        *(__half2*)(dh + d + 2) = h1;
        __half2 l0 = __floats2half2_rn(out.x - __half2float(__low2half(h0)),
                                       out.y - __half2float(__high2half(h0)));
        __half2 l1 = __floats2half2_rn(out.z - __half2float(__low2half(h1)),
                                       out.w - __half2float(__high2half(h1)));
        *(__half2*)(dl + d)     = l0;
        *(__half2*)(dl + d + 2) = l1;
    } else {
        *(__half2*)(dsingle + d)     = __floats2half2_rn(out.x, out.y);
        *(__half2*)(dsingle + d + 2) = __floats2half2_rn(out.z, out.w);
    }
}

// ---------------------------------------------------------------------------
// Tensor-core flash attention, causal, GQA.
// S = Qh*K + Ql*K (2-term, softmax amplification insurance);
// O = P*V (1-term). CTA = (head, 64-row q tile), 4 warps. BKV=64.
// ---------------------------------------------------------------------------
#define ASTR 136               // halves per smem row
#define AMAT (64 * ASTR)       // halves per matrix
#define ATTN_SMEM (4 * AMAT * 2)   // Qh | Ql | Kh | Vh

__global__ __launch_bounds__(128, 2)
void flash_mma_kernel() {
    extern __shared__ __half asm_smem[];
    const uint32_t sb = smem_u32(asm_smem);
    const uint32_t sQh = sb;
    const uint32_t sQl = sQh + AMAT * 2;
    const uint32_t sKh = sQl + AMAT * 2;
    const uint32_t sVh = sKh + AMAT * 2;

    const int h  = blockIdx.x;
    const int q0 = blockIdx.y * 64;
    const int kh = h >> 2;
    const int tid = threadIdx.x;
    const int warp = tid >> 5;
    const int lane = tid & 31;
    const int gid = lane >> 2;
    const int tig = lane & 3;

    // load Q tile (hi/lo)
    {
        const __half* gh = g_qh + ((size_t)h * SEQ + q0) * HD;
        const __half* gl = g_ql + ((size_t)h * SEQ + q0) * HD;
        #pragma unroll
        for (int i = 0; i < 8; i++) {
            int ch = tid + i * 128;
            int row = ch >> 4, c = ch & 15;
            uint32_t off = (uint32_t)(row * ASTR) * 2 + c * 16;
            cpa16(sQh + off, gh + (size_t)row * HD + c * 8);
            cpa16(sQl + off, gl + (size_t)row * HD + c * 8);
        }
        cpa_commit();
    }

    float oacc[16][4];
    #pragma unroll
    for (int j = 0; j < 16; j++)
        #pragma unroll
        for (int t = 0; t < 4; t++) oacc[j][t] = 0.0f;
    float mrow[2] = {-1e30f, -1e30f};
    float lrow[2] = {0.0f, 0.0f};

    const uint32_t qoff_row = (uint32_t)((warp * 16 + (lane & 15)) * ASTR) * 2;
    const uint32_t qoff_col = (uint32_t)((lane >> 4) * 8) * 2;
    const uint32_t koff_rowbase = (uint32_t)((lane & 7) * ASTR) * 2;
    const uint32_t koff_col = (uint32_t)(((lane >> 3) & 3) * 8) * 2;
    const uint32_t voff_rowbase = (uint32_t)(((lane & 7) + 8 * ((lane >> 3) & 1)) * ASTR) * 2;
    const uint32_t voff_col = (uint32_t)((lane >> 4) * 8) * 2;

    for (int k0 = 0; k0 <= q0; k0 += 64) {
        // load K,V tiles
        {
            const __half* bkh = g_kh + ((size_t)kh * SEQ + k0) * HD;
            const __half* bvh = g_vh + ((size_t)kh * SEQ + k0) * HD;
            #pragma unroll
            for (int i = 0; i < 8; i++) {
                int ch = tid + i * 128;
                int row = ch >> 4, c = ch & 15;
                uint32_t off = (uint32_t)(row * ASTR) * 2 + c * 16;
                size_t goff = (size_t)row * HD + c * 8;
                cpa16(sKh + off, bkh + goff);
                cpa16(sVh + off, bvh + goff);
            }
            cpa_commit();
            cpa_wait0();
        }
        __syncthreads();

        // ---- S = Q K^T (2-term) ----
        float sacc[8][4];
        #pragma unroll
        for (int j = 0; j < 8; j++)
            #pragma unroll
            for (int t = 0; t < 4; t++) sacc[j][t] = 0.0f;

        #pragma unroll
        for (int ks2 = 0; ks2 < 4; ks2++) {
            uint32_t qh2[2][4], ql2[2][4];
            #pragma unroll
            for (int e = 0; e < 2; e++) {
                uint32_t off = qoff_row + ((uint32_t)((ks2 * 2 + e) * 16) * 2 + qoff_col);
                ldm_x4(qh2[e], sQh + off);
                ldm_x4(ql2[e], sQl + off);
            }
            #pragma unroll
            for (int jn2 = 0; jn2 < 4; jn2++) {
                const int jA = jn2 * 2, jB = jn2 * 2 + 1;
                const uint32_t kcom = koff_rowbase + (uint32_t)(ks2 * 32) * 2 + koff_col;
                uint32_t offA = (uint32_t)(jA * 8 * ASTR) * 2 + kcom;
                uint32_t offB = (uint32_t)(jB * 8 * ASTR) * 2 + kcom;
                uint32_t khA[4], khB[4];
                ldm_x4(khA, sKh + offA); ldm_x4(khB, sKh + offB);
                mma_f16(sacc[jA], qh2[0], khA);     mma_f16(sacc[jB], qh2[0], khB);
                mma_f16(sacc[jA], qh2[1], khA + 2); mma_f16(sacc[jB], qh2[1], khB + 2);
                mma_f16(sacc[jA], ql2[0], khA);     mma_f16(sacc[jB], ql2[0], khB);
                mma_f16(sacc[jA], ql2[1], khA + 2); mma_f16(sacc[jB], ql2[1], khB + 2);
            }
        }

        // ---- causal mask on diagonal tile ----
        if (k0 == q0) {
            int qg0 = q0 + warp * 16 + gid;
            #pragma unroll
            for (int jn = 0; jn < 8; jn++) {
                int kg = k0 + jn * 8 + tig * 2;
                if (kg > qg0)     sacc[jn][0] = -1e30f;
                if (kg + 1 > qg0) sacc[jn][1] = -1e30f;
                if (kg > qg0 + 8)     sacc[jn][2] = -1e30f;
                if (kg + 1 > qg0 + 8) sacc[jn][3] = -1e30f;
            }
        }

        // ---- online softmax (registers) ----
        float mn0 = mrow[0], mn1 = mrow[1];
        #pragma unroll
        for (int jn = 0; jn < 8; jn++) {
            mn0 = fmaxf(mn0, fmaxf(sacc[jn][0], sacc[jn][1]));
            mn1 = fmaxf(mn1, fmaxf(sacc[jn][2], sacc[jn][3]));
        }
        mn0 = fmaxf(mn0, __shfl_xor_sync(0xffffffffu, mn0, 1));
        mn0 = fmaxf(mn0, __shfl_xor_sync(0xffffffffu, mn0, 2));
        mn1 = fmaxf(mn1, __shfl_xor_sync(0xffffffffu, mn1, 1));
        mn1 = fmaxf(mn1, __shfl_xor_sync(0xffffffffu, mn1, 2));
        float al0 = __expf(mrow[0] - mn0);
        float al1 = __expf(mrow[1] - mn1);
        mrow[0] = mn0; mrow[1] = mn1;
        lrow[0] *= al0; lrow[1] *= al1;

        uint32_t ph[8][2];
        #pragma unroll
        for (int jn = 0; jn < 8; jn++) {
            float p0 = __expf(sacc[jn][0] - mn0);
            float p1 = __expf(sacc[jn][1] - mn0);
            float p2 = __expf(sacc[jn][2] - mn1);
            float p3 = __expf(sacc[jn][3] - mn1);
            lrow[0] += p0 + p1;
            lrow[1] += p2 + p3;
            __half2 t0 = __floats2half2_rn(p0, p1);
            __half2 t1 = __floats2half2_rn(p2, p3);
            ph[jn][0] = *(uint32_t*)&t0;
            ph[jn][1] = *(uint32_t*)&t1;
        }
        #pragma unroll
        for (int jd = 0; jd < 16; jd++) {
            oacc[jd][0] *= al0; oacc[jd][1] *= al0;
            oacc[jd][2] *= al1; oacc[jd][3] *= al1;
        }

        // ---- O += P V (1-term) ----
        #pragma unroll
        for (int kks = 0; kks < 4; kks++) {
            uint32_t aPh[4] = {ph[2 * kks][0], ph[2 * kks][1], ph[2 * kks + 1][0], ph[2 * kks + 1][1]};
            #pragma unroll
            for (int jd2 = 0; jd2 < 8; jd2++) {
                uint32_t off = (uint32_t)(kks * 16 * ASTR) * 2 + voff_rowbase +
                               (uint32_t)(jd2 * 16) * 2 + voff_col;
                uint32_t vh4[4];
                ldm_x4_t(vh4, sVh + off);
                mma_f16(oacc[jd2 * 2], aPh, vh4);
                mma_f16(oacc[jd2 * 2 + 1], aPh, vh4 + 2);
            }
        }
        __syncthreads();
    }

    // final: reduce l across quad, normalize, write fp16
    lrow[0] += __shfl_xor_sync(0xffffffffu, lrow[0], 1);
    lrow[0] += __shfl_xor_sync(0xffffffffu, lrow[0], 2);
    lrow[1] += __shfl_xor_sync(0xffffffffu, lrow[1], 1);
    lrow[1] += __shfl_xor_sync(0xffffffffu, lrow[1], 2);
    float inv0 = 1.0f / lrow[0];
    float inv1 = 1.0f / lrow[1];

    int row0 = q0 + warp * 16 + gid;
    #pragma unroll
    for (int jd = 0; jd < 16; jd++) {
        int col = h * HD + jd * 8 + tig * 2;
        __half2 h0 = __floats2half2_rn(oacc[jd][0] * inv0, oacc[jd][1] * inv0);
        __half2 h1 = __floats2half2_rn(oacc[jd][2] * inv1, oacc[jd][3] * inv1);
        *(__half2*)(g_ao_h + (size_t)row0 * QD + col)       = h0;
        *(__half2*)(g_ao_h + (size_t)(row0 + 8) * QD + col) = h1;
    }
}

// ---------------------------------------------------------------------------
// launch
// ---------------------------------------------------------------------------
extern "C" void kernel_launch(void* const* d_in, const int* in_sizes, int n_in,
                              void* d_out, int out_size) {
    const float* hidden = (const float*)d_in[0];
    const float* cosb   = (const float*)d_in[1];
    const float* sinb   = (const float*)d_in[2];
    const float* Wq     = (const float*)d_in[3];
    const float* Wk     = (const float*)d_in[4];
    const float* Wv     = (const float*)d_in[5];
    const float* Wo     = (const float*)d_in[6];
    const float* qw     = (const float*)d_in[7];
    const float* kw     = (const float*)d_in[8];
    float* out = (float*)d_out;

    float* qkv_ptr = nullptr;
    __half *hid_h, *wqkv_h, *wo_h, *ao_h;
    cudaGetSymbolAddress((void**)&qkv_ptr, g_qkv);
    cudaGetSymbolAddress((void**)&hid_h, g_hid_h);
    cudaGetSymbolAddress((void**)&wqkv_h, g_wqkv_h);
    cudaGetSymbolAddress((void**)&wo_h, g_wo_h);
    cudaGetSymbolAddress((void**)&ao_h, g_ao_h);

    cudaFuncSetAttribute(gemm_mma, cudaFuncAttributeMaxDynamicSharedMemorySize, GEMM_SMEM);
    cudaFuncSetAttribute(flash_mma_kernel, cudaFuncAttributeMaxDynamicSharedMemorySize, ATTN_SMEM);

    // conversions to fp16
    {
        int n;
        n = SEQ * HID;  cvt_h<<<(n / 4 + 255) / 256, 256>>>(hidden, hid_h, n);
        n = QD * HID;   cvt_h<<<(n / 4 + 255) / 256, 256>>>(Wq, wqkv_h, n);
        n = KVD * HID;  cvt_h<<<(n / 4 + 255) / 256, 256>>>(Wk, wqkv_h + (size_t)QD * HID, n);
        n = KVD * HID;  cvt_h<<<(n / 4 + 255) / 256, 256>>>(Wv, wqkv_h + (size_t)(QD + KVD) * HID, n);
        n = HID * QD;   cvt_h<<<(n / 4 + 255) / 256, 256>>>(Wo, wo_h, n);
    }

    // fused QKV projection: g_qkv[2048, 6144] = hidden @ [Wq|Wk|Wv]^T
    gemm_mma<<<dim3(QKVD / 128, SEQ / 128), 256, GEMM_SMEM>>>(
        hid_h, wqkv_h, qkv_ptr, HID, QKVD);

    // RMSNorm + RoPE + fp16 conversion into [h][s][d] buffers
    {
        int nwarps = SEQ * 48;
        int nblocks = (nwarps * 32 + 255) / 256;
        rms_rope_kernel<<<nblocks, 256>>>(cosb, sinb, qw, kw);
    }

    // tensor-core causal GQA flash attention -> g_ao_h
    flash_mma_kernel<<<dim3(NQH, SEQ / 64), 128, ATTN_SMEM>>>();

    // output projection: out[2048, 2560] = O @ Wo^T
    gemm_mma<<<dim3(HID / 128, SEQ / 128), 256, GEMM_SMEM>>>(
        ao_h, wo_h, out, QD, HID);
}

// round 9
// speedup vs baseline: 7.3340x; 1.0077x over previous
#include <cuda_runtime.h>
#include <cuda_fp16.h>
#include <cstdint>
#include <cstdio>

#define SEQ   2048
#define HID   2560
#define QD    4096      // 32 heads * 128
#define KVD   1024      // 8 heads * 128
#define QKVD  6144      // QD + 2*KVD
#define HD    128
#define NQH   32
#define NKVH  8

// ---------------------------------------------------------------------------
// Scratch (device globals; no allocation allowed)
// ---------------------------------------------------------------------------
__device__ float g_qkv[(size_t)SEQ * QKVD];   // [s, 6144]: Q | K | V (fp32)

// fp16 operand buffers
__device__ __half g_hid_h[(size_t)SEQ * HID];     // hidden (A of QKV gemm)
__device__ __half g_wqkv_h[(size_t)QKVD * HID];   // Wq|Wk|Wv stacked (B)
__device__ __half g_wo_h[(size_t)HID * QD];       // Wo (B)
__device__ __half g_ao_h[(size_t)SEQ * QD];       // attn out (A of Wo gemm)

// attention operands, [head][seq][128]
__device__ __half g_qh[(size_t)NQH * SEQ * HD];   // Q hi (split A, scale*log2e folded)
__device__ __half g_ql[(size_t)NQH * SEQ * HD];   // Q lo
__device__ __half g_kh[(size_t)NKVH * SEQ * HD];  // K
__device__ __half g_vh[(size_t)NKVH * SEQ * HD];  // V

// ---------------------------------------------------------------------------
// PTX helpers
// ---------------------------------------------------------------------------
__device__ __forceinline__ uint32_t smem_u32(const void* p) {
    uint32_t a;
    asm("{ .reg .u64 t; cvta.to.shared.u64 t, %1; cvt.u32.u64 %0, t; }" : "=r"(a) : "l"(p));
    return a;
}
__device__ __forceinline__ void cpa16(uint32_t s, const void* g) {
    asm volatile("cp.async.cg.shared.global [%0], [%1], 16;" :: "r"(s), "l"(g));
}
__device__ __forceinline__ void cpa_commit() {
    asm volatile("cp.async.commit_group;" ::: "memory");
}
__device__ __forceinline__ void cpa_wait1() {
    asm volatile("cp.async.wait_group 1;" ::: "memory");
}
__device__ __forceinline__ void cpa_wait0() {
    asm volatile("cp.async.wait_group 0;" ::: "memory");
}
__device__ __forceinline__ void ldm_x4(uint32_t* r, uint32_t addr) {
    asm volatile("ldmatrix.sync.aligned.m8n8.x4.shared.b16 {%0,%1,%2,%3}, [%4];"
                 : "=r"(r[0]), "=r"(r[1]), "=r"(r[2]), "=r"(r[3]) : "r"(addr));
}
__device__ __forceinline__ void ldm_x4_t(uint32_t* r, uint32_t addr) {
    asm volatile("ldmatrix.sync.aligned.m8n8.x4.trans.shared.b16 {%0,%1,%2,%3}, [%4];"
                 : "=r"(r[0]), "=r"(r[1]), "=r"(r[2]), "=r"(r[3]) : "r"(addr));
}
__device__ __forceinline__ void mma_f16(float* c, const uint32_t* a, const uint32_t* b) {
    asm volatile(
        "mma.sync.aligned.m16n8k16.row.col.f32.f16.f16.f32 "
        "{%0,%1,%2,%3}, {%4,%5,%6,%7}, {%8,%9}, {%0,%1,%2,%3};"
        : "+f"(c[0]), "+f"(c[1]), "+f"(c[2]), "+f"(c[3])
        : "r"(a[0]), "r"(a[1]), "r"(a[2]), "r"(a[3]), "r"(b[0]), "r"(b[1]));
}
__device__ __forceinline__ uint32_t ex2_h2(float a, float b) {
    __half2 t = __floats2half2_rn(a, b);
    uint32_t in = *(uint32_t*)&t, out;
    asm("ex2.approx.f16x2 %0, %1;" : "=r"(out) : "r"(in));
    return out;
}

// ---------------------------------------------------------------------------
// fused fp32 -> fp16 conversion over all 5 input regions (one launch)
// ---------------------------------------------------------------------------
__global__ __launch_bounds__(256)
void cvt_all(const float* __restrict__ hid, const float* __restrict__ wq,
             const float* __restrict__ wk, const float* __restrict__ wv,
             const float* __restrict__ wo) {
    size_t i = ((size_t)blockIdx.x * blockDim.x + threadIdx.x) * 4;
    const size_t n0 = (size_t)SEQ * HID;   // 5,242,880
    const size_t n1 = (size_t)QD * HID;    // 10,485,760
    const size_t n2 = (size_t)KVD * HID;   // 2,621,440
    const size_t n4 = (size_t)HID * QD;    // 10,485,760

    const float* src;
    __half* dst;
    if (i < n0)                { src = hid; dst = g_hid_h + i; }
    else if ((i -= n0) < n1)   { src = wq;  dst = g_wqkv_h + i; }
    else if ((i -= n1) < n2)   { src = wk;  dst = g_wqkv_h + n1 + i; }
    else if ((i -= n2) < n2)   { src = wv;  dst = g_wqkv_h + n1 + n2 + i; }
    else if ((i -= n2) < n4)   { src = wo;  dst = g_wo_h + i; }
    else return;

    float4 x = *(const float4*)(src + i);
    *(__half2*)(dst)     = __floats2half2_rn(x.x, x.y);
    *(__half2*)(dst + 2) = __floats2half2_rn(x.z, x.w);
}

// ---------------------------------------------------------------------------
// mma.sync fp16 GEMM (NT): C[m,n] = sum_k A[m,k]*B[n,k], fp32 accum.
// CTA 128x128, BK=32, 8 warps (4x2), warp tile 32x64. Double-buffered.
// ---------------------------------------------------------------------------
#define BK 32
#define LDS_STR 40
#define TILE_H (128 * LDS_STR)
#define STAGE_H (2 * TILE_H)          // A | B
#define GEMM_SMEM (2 * STAGE_H * 2)   // 40960 B

__global__ __launch_bounds__(256, 2)
void gemm_mma(const __half* __restrict__ Ah, const __half* __restrict__ Bh,
              float* __restrict__ C, int K, int ldc) {
    extern __shared__ __half smem[];
    const uint32_t sbase = smem_u32(smem);

    const int tid  = threadIdx.x;
    const int warp = tid >> 5;
    const int lane = tid & 31;
    const int wm   = warp & 3;
    const int wn   = warp >> 2;
    const int bx = blockIdx.x, by = blockIdx.y;

    const __half* gA = Ah + (size_t)(by * 128) * K;
    const __half* gB = Bh + (size_t)(bx * 128) * K;

    float acc[2][8][4];
    #pragma unroll
    for (int i = 0; i < 2; i++)
        #pragma unroll
        for (int j = 0; j < 8; j++)
            #pragma unroll
            for (int t = 0; t < 4; t++) acc[i][j][t] = 0.0f;

    const int nchunk = K / BK;
    const int r0 = tid >> 2;
    const int ch0 = (tid & 3) * 8;

    auto load_stage = [&](int c, int s) {
        const size_t koff = (size_t)c * BK;
        uint32_t dst = sbase + (uint32_t)(s * STAGE_H) * 2;
        {
            uint32_t d = dst;
            cpa16(d + (r0 * LDS_STR + ch0) * 2,        gA + (size_t)r0 * K + koff + ch0);
            cpa16(d + ((r0 + 64) * LDS_STR + ch0) * 2, gA + (size_t)(r0 + 64) * K + koff + ch0);
        }
        {
            uint32_t d = dst + (uint32_t)TILE_H * 2;
            cpa16(d + (r0 * LDS_STR + ch0) * 2,        gB + (size_t)r0 * K + koff + ch0);
            cpa16(d + ((r0 + 64) * LDS_STR + ch0) * 2, gB + (size_t)(r0 + 64) * K + koff + ch0);
        }
    };

    const int a_row = (lane & 7) + ((lane >> 3) & 1) * 8;
    const int a_kof = (lane >> 4) * 8;
    const int b_mat = lane >> 3;
    const int b_row = lane & 7;
    const int b_kof = (b_mat & 1) * 8;
    const int b_jof = (b_mat >> 1);

    load_stage(0, 0);
    cpa_commit();

    for (int c = 0; c < nchunk; c++) {
        if (c + 1 < nchunk) {
            load_stage(c + 1, (c + 1) & 1);
            cpa_commit();
            cpa_wait1();
        } else {
            cpa_wait0();
        }
        __syncthreads();

        const uint32_t st = sbase + (uint32_t)((c & 1) * STAGE_H) * 2;
        const uint32_t sA = st;
        const uint32_t sB = st + (uint32_t)TILE_H * 2;

        #pragma unroll
        for (int ks = 0; ks < 2; ks++) {
            uint32_t ah[2][4];
            #pragma unroll
            for (int i = 0; i < 2; i++) {
                int m_local = wm * 32 + i * 16 + a_row;
                int k = ks * 16 + a_kof;
                uint32_t off = (uint32_t)(m_local * LDS_STR + k) * 2;
                ldm_x4(ah[i], sA + off);
            }
            #pragma unroll
            for (int jp = 0; jp < 4; jp++) {
                int n_local = wn * 64 + (jp * 2 + b_jof) * 8 + b_row;
                int k = ks * 16 + b_kof;
                uint32_t off = (uint32_t)(n_local * LDS_STR + k) * 2;
                uint32_t rh[4];
                ldm_x4(rh, sB + off);
                const int j0 = jp * 2, j1 = jp * 2 + 1;
                mma_f16(acc[0][j0], ah[0], rh);   mma_f16(acc[0][j1], ah[0], rh + 2);
                mma_f16(acc[1][j0], ah[1], rh);   mma_f16(acc[1][j1], ah[1], rh + 2);
            }
        }
        __syncthreads();
    }

    const int gid = lane >> 2;
    const int tgc = (lane & 3) * 2;
    #pragma unroll
    for (int i = 0; i < 2; i++) {
        int row = by * 128 + wm * 32 + i * 16 + gid;
        #pragma unroll
        for (int j = 0; j < 8; j++) {
            int col = bx * 128 + wn * 64 + j * 8 + tgc;
            float2 v0 = {acc[i][j][0], acc[i][j][1]};
            float2 v1 = {acc[i][j][2], acc[i][j][3]};
            *(float2*)(C + (size_t)row * ldc + col)       = v0;
            *(float2*)(C + (size_t)(row + 8) * ldc + col) = v1;
        }
    }
}

// ---------------------------------------------------------------------------
// RMSNorm + RoPE, fp32 g_qkv -> fp16 buffers, [h][s][d] layout.
// Q heads get scale = (1/sqrt(128)) * log2(e) folded in (softmax in log2).
// ---------------------------------------------------------------------------
__global__ __launch_bounds__(256)
void rms_rope_kernel(const float* __restrict__ cosb, const float* __restrict__ sinb,
                     const float* __restrict__ qw, const float* __restrict__ kw) {
    int gw = (blockIdx.x * blockDim.x + threadIdx.x) >> 5;
    int lane = threadIdx.x & 31;
    if (gw >= SEQ * 48) return;
    int s = gw / 48;
    int h = gw % 48;
    int d = lane * 4;

    float4 out;
    __half* dsingle = nullptr;

    if (h < 40) {
        const float* base;
        const float* w;
        if (h < NQH) {
            base = g_qkv + (size_t)s * QKVD + h * HD;
            w = qw;
        } else {
            int kh = h - NQH;
            base = g_qkv + (size_t)s * QKVD + QD + kh * HD;
            w = kw;
            dsingle = g_kh + ((size_t)kh * SEQ + s) * HD;
        }
        float4 x = *(const float4*)(base + d);
        float ss = x.x * x.x + x.y * x.y + x.z * x.z + x.w * x.w;
        #pragma unroll
        for (int o = 16; o > 0; o >>= 1) ss += __shfl_xor_sync(0xffffffffu, ss, o);
        float r = rsqrtf(ss * (1.0f / 128.0f) + 1e-6f);

        float4 wv = *(const float4*)(w + d);
        float4 xn;
        xn.x = x.x * r * wv.x; xn.y = x.y * r * wv.y;
        xn.z = x.z * r * wv.z; xn.w = x.w * r * wv.w;

        float4 ot;
        ot.x = __shfl_xor_sync(0xffffffffu, xn.x, 16);
        ot.y = __shfl_xor_sync(0xffffffffu, xn.y, 16);
        ot.z = __shfl_xor_sync(0xffffffffu, xn.z, 16);
        ot.w = __shfl_xor_sync(0xffffffffu, xn.w, 16);
        float sgn = (d < 64) ? -1.0f : 1.0f;

        float4 c = *(const float4*)(cosb + (size_t)s * HD + d);
        float4 si = *(const float4*)(sinb + (size_t)s * HD + d);
        out.x = xn.x * c.x + sgn * ot.x * si.x;
        out.y = xn.y * c.y + sgn * ot.y * si.y;
        out.z = xn.z * c.z + sgn * ot.z * si.z;
        out.w = xn.w * c.w + sgn * ot.w * si.w;
        if (h < NQH) {
            // fold softmax scale AND log2(e): S ends up in log2 domain
            const float sc = 0.12751743f;   // (1/sqrt(128)) * log2(e)
            out.x *= sc; out.y *= sc; out.z *= sc; out.w *= sc;
        }
    } else {
        int vh = h - 40;
        const float* base = g_qkv + (size_t)s * QKVD + QD + KVD + vh * HD;
        out = *(const float4*)(base + d);
        dsingle = g_vh + ((size_t)vh * SEQ + s) * HD;
    }

    if (h < NQH) {
        __half* dh = g_qh + ((size_t)h * SEQ + s) * HD;
        __half* dl = g_ql + ((size_t)h * SEQ + s) * HD;
        __half2 h0 = __floats2half2_rn(out.x, out.y);
        __half2 h1 = __floats2half2_rn(out.z, out.w);
        *(__half2*)(dh + d)     = h0;
        *(__half2*)(dh + d + 2) = h1;
        __half2 l0 = __floats2half2_rn(out.x - __half2float(__low2half(h0)),
                                       out.y - __half2float(__high2half(h0)));
        __half2 l1 = __floats2half2_rn(out.z - __half2float(__low2half(h1)),
                                       out.w - __half2float(__high2half(h1)));
        *(__half2*)(dl + d)     = l0;
        *(__half2*)(dl + d + 2) = l1;
    } else {
        *(__half2*)(dsingle + d)     = __floats2half2_rn(out.x, out.y);
        *(__half2*)(dsingle + d + 2) = __floats2half2_rn(out.z, out.w);
    }
}

// ---------------------------------------------------------------------------
// Tensor-core flash attention, causal, GQA. Softmax in log2 domain via
// ex2.approx.f16x2 (2 P elements per MUFU op; output IS the fp16 fragment).
// S = Qh*K + Ql*K (2-term); O = P*V. CTA = (head, 64 q rows), 4 warps.
// ---------------------------------------------------------------------------
#define ASTR 136               // halves per smem row
#define AMAT (64 * ASTR)       // halves per matrix
#define ATTN_SMEM (4 * AMAT * 2)   // Qh | Ql | Kh | Vh

__global__ __launch_bounds__(128, 2)
void flash_mma_kernel() {
    extern __shared__ __half asm_smem[];
    const uint32_t sb = smem_u32(asm_smem);
    const uint32_t sQh = sb;
    const uint32_t sQl = sQh + AMAT * 2;
    const uint32_t sKh = sQl + AMAT * 2;
    const uint32_t sVh = sKh + AMAT * 2;

    const int h  = blockIdx.x;
    const int q0 = blockIdx.y * 64;
    const int kh = h >> 2;
    const int tid = threadIdx.x;
    const int warp = tid >> 5;
    const int lane = tid & 31;
    const int gid = lane >> 2;
    const int tig = lane & 3;

    // load Q tile (hi/lo)
    {
        const __half* gh = g_qh + ((size_t)h * SEQ + q0) * HD;
        const __half* gl = g_ql + ((size_t)h * SEQ + q0) * HD;
        #pragma unroll
        for (int i = 0; i < 8; i++) {
            int ch = tid + i * 128;
            int row = ch >> 4, c = ch & 15;
            uint32_t off = (uint32_t)(row * ASTR) * 2 + c * 16;
            cpa16(sQh + off, gh + (size_t)row * HD + c * 8);
            cpa16(sQl + off, gl + (size_t)row * HD + c * 8);
        }
        cpa_commit();
    }

    float oacc[16][4];
    #pragma unroll
    for (int j = 0; j < 16; j++)
        #pragma unroll
        for (int t = 0; t < 4; t++) oacc[j][t] = 0.0f;
    float mrow[2] = {-1e30f, -1e30f};
    float lrow[2] = {0.0f, 0.0f};

    const uint32_t qoff_row = (uint32_t)((warp * 16 + (lane & 15)) * ASTR) * 2;
    const uint32_t qoff_col = (uint32_t)((lane >> 4) * 8) * 2;
    const uint32_t koff_rowbase = (uint32_t)((lane & 7) * ASTR) * 2;
    const uint32_t koff_col = (uint32_t)(((lane >> 3) & 3) * 8) * 2;
    const uint32_t voff_rowbase = (uint32_t)(((lane & 7) + 8 * ((lane >> 3) & 1)) * ASTR) * 2;
    const uint32_t voff_col = (uint32_t)((lane >> 4) * 8) * 2;

    for (int k0 = 0; k0 <= q0; k0 += 64) {
        // load K,V tiles
        {
            const __half* bkh = g_kh + ((size_t)kh * SEQ + k0) * HD;
            const __half* bvh = g_vh + ((size_t)kh * SEQ + k0) * HD;
            #pragma unroll
            for (int i = 0; i < 8; i++) {
                int ch = tid + i * 128;
                int row = ch >> 4, c = ch & 15;
                uint32_t off = (uint32_t)(row * ASTR) * 2 + c * 16;
                size_t goff = (size_t)row * HD + c * 8;
                cpa16(sKh + off, bkh + goff);
                cpa16(sVh + off, bvh + goff);
            }
            cpa_commit();
            cpa_wait0();
        }
        __syncthreads();

        // ---- S = Q K^T (2-term, log2 domain) ----
        float sacc[8][4];
        #pragma unroll
        for (int j = 0; j < 8; j++)
            #pragma unroll
            for (int t = 0; t < 4; t++) sacc[j][t] = 0.0f;

        #pragma unroll
        for (int ks2 = 0; ks2 < 4; ks2++) {
            uint32_t qh2[2][4], ql2[2][4];
            #pragma unroll
            for (int e = 0; e < 2; e++) {
                uint32_t off = qoff_row + ((uint32_t)((ks2 * 2 + e) * 16) * 2 + qoff_col);
                ldm_x4(qh2[e], sQh + off);
                ldm_x4(ql2[e], sQl + off);
            }
            #pragma unroll
            for (int jn2 = 0; jn2 < 4; jn2++) {
                const int jA = jn2 * 2, jB = jn2 * 2 + 1;
                const uint32_t kcom = koff_rowbase + (uint32_t)(ks2 * 32) * 2 + koff_col;
                uint32_t offA = (uint32_t)(jA * 8 * ASTR) * 2 + kcom;
                uint32_t offB = (uint32_t)(jB * 8 * ASTR) * 2 + kcom;
                uint32_t khA[4], khB[4];
                ldm_x4(khA, sKh + offA); ldm_x4(khB, sKh + offB);
                mma_f16(sacc[jA], qh2[0], khA);     mma_f16(sacc[jB], qh2[0], khB);
                mma_f16(sacc[jA], qh2[1], khA + 2); mma_f16(sacc[jB], qh2[1], khB + 2);
                mma_f16(sacc[jA], ql2[0], khA);     mma_f16(sacc[jB], ql2[0], khB);
                mma_f16(sacc[jA], ql2[1], khA + 2); mma_f16(sacc[jB], ql2[1], khB + 2);
            }
        }

        // ---- causal mask on diagonal tile ----
        if (k0 == q0) {
            int qg0 = q0 + warp * 16 + gid;
            #pragma unroll
            for (int jn = 0; jn < 8; jn++) {
                int kg = k0 + jn * 8 + tig * 2;
                if (kg > qg0)     sacc[jn][0] = -1e30f;
                if (kg + 1 > qg0) sacc[jn][1] = -1e30f;
                if (kg > qg0 + 8)     sacc[jn][2] = -1e30f;
                if (kg + 1 > qg0 + 8) sacc[jn][3] = -1e30f;
            }
        }

        // ---- online softmax (log2 domain, fp16x2 ex2) ----
        float mn0 = mrow[0], mn1 = mrow[1];
        #pragma unroll
        for (int jn = 0; jn < 8; jn++) {
            mn0 = fmaxf(mn0, fmaxf(sacc[jn][0], sacc[jn][1]));
            mn1 = fmaxf(mn1, fmaxf(sacc[jn][2], sacc[jn][3]));
        }
        mn0 = fmaxf(mn0, __shfl_xor_sync(0xffffffffu, mn0, 1));
        mn0 = fmaxf(mn0, __shfl_xor_sync(0xffffffffu, mn0, 2));
        mn1 = fmaxf(mn1, __shfl_xor_sync(0xffffffffu, mn1, 1));
        mn1 = fmaxf(mn1, __shfl_xor_sync(0xffffffffu, mn1, 2));
        float al0 = exp2f(mrow[0] - mn0);
        float al1 = exp2f(mrow[1] - mn1);
        mrow[0] = mn0; mrow[1] = mn1;
        lrow[0] *= al0; lrow[1] *= al1;

        uint32_t ph[8][2];
        float lacc0 = 0.0f, lacc1 = 0.0f;
        #pragma unroll
        for (int jn = 0; jn < 8; jn++) {
            uint32_t p0 = ex2_h2(sacc[jn][0] - mn0, sacc[jn][1] - mn0);
            uint32_t p1 = ex2_h2(sacc[jn][2] - mn1, sacc[jn][3] - mn1);
            ph[jn][0] = p0;
            ph[jn][1] = p1;
            float2 f0 = __half22float2(*(__half2*)&p0);
            float2 f1 = __half22float2(*(__half2*)&p1);
            lacc0 += f0.x + f0.y;
            lacc1 += f1.x + f1.y;
        }
        lrow[0] += lacc0;
        lrow[1] += lacc1;

        #pragma unroll
        for (int jd = 0; jd < 16; jd++) {
            oacc[jd][0] *= al0; oacc[jd][1] *= al0;
            oacc[jd][2] *= al1; oacc[jd][3] *= al1;
        }

        // ---- O += P V ----
        #pragma unroll
        for (int kks = 0; kks < 4; kks++) {
            uint32_t aPh[4] = {ph[2 * kks][0], ph[2 * kks][1], ph[2 * kks + 1][0], ph[2 * kks + 1][1]};
            #pragma unroll
            for (int jd2 = 0; jd2 < 8; jd2++) {
                uint32_t off = (uint32_t)(kks * 16 * ASTR) * 2 + voff_rowbase +
                               (uint32_t)(jd2 * 16) * 2 + voff_col;
                uint32_t vh4[4];
                ldm_x4_t(vh4, sVh + off);
                mma_f16(oacc[jd2 * 2], aPh, vh4);
                mma_f16(oacc[jd2 * 2 + 1], aPh, vh4 + 2);
            }
        }
        __syncthreads();
    }

    // final: reduce l across quad, normalize, write fp16
    lrow[0] += __shfl_xor_sync(0xffffffffu, lrow[0], 1);
    lrow[0] += __shfl_xor_sync(0xffffffffu, lrow[0], 2);
    lrow[1] += __shfl_xor_sync(0xffffffffu, lrow[1], 1);
    lrow[1] += __shfl_xor_sync(0xffffffffu, lrow[1], 2);
    float inv0 = 1.0f / lrow[0];
    float inv1 = 1.0f / lrow[1];

    int row0 = q0 + warp * 16 + gid;
    #pragma unroll
    for (int jd = 0; jd < 16; jd++) {
        int col = h * HD + jd * 8 + tig * 2;
        __half2 h0 = __floats2half2_rn(oacc[jd][0] * inv0, oacc[jd][1] * inv0);
        __half2 h1 = __floats2half2_rn(oacc[jd][2] * inv1, oacc[jd][3] * inv1);
        *(__half2*)(g_ao_h + (size_t)row0 * QD + col)       = h0;
        *(__half2*)(g_ao_h + (size_t)(row0 + 8) * QD + col) = h1;
    }
}

// ---------------------------------------------------------------------------
// launch
// ---------------------------------------------------------------------------
extern "C" void kernel_launch(void* const* d_in, const int* in_sizes, int n_in,
                              void* d_out, int out_size) {
    const float* hidden = (const float*)d_in[0];
    const float* cosb   = (const float*)d_in[1];
    const float* sinb   = (const float*)d_in[2];
    const float* Wq     = (const float*)d_in[3];
    const float* Wk     = (const float*)d_in[4];
    const float* Wv     = (const float*)d_in[5];
    const float* Wo     = (const float*)d_in[6];
    const float* qw     = (const float*)d_in[7];
    const float* kw     = (const float*)d_in[8];
    float* out = (float*)d_out;

    float* qkv_ptr = nullptr;
    __half *hid_h, *wqkv_h, *wo_h, *ao_h;
    cudaGetSymbolAddress((void**)&qkv_ptr, g_qkv);
    cudaGetSymbolAddress((void**)&hid_h, g_hid_h);
    cudaGetSymbolAddress((void**)&wqkv_h, g_wqkv_h);
    cudaGetSymbolAddress((void**)&wo_h, g_wo_h);
    cudaGetSymbolAddress((void**)&ao_h, g_ao_h);

    cudaFuncSetAttribute(gemm_mma, cudaFuncAttributeMaxDynamicSharedMemorySize, GEMM_SMEM);
    cudaFuncSetAttribute(flash_mma_kernel, cudaFuncAttributeMaxDynamicSharedMemorySize, ATTN_SMEM);

    // fused conversions to fp16 (one launch)
    {
        size_t total = (size_t)SEQ * HID + (size_t)QD * HID + 2 * (size_t)KVD * HID +
                       (size_t)HID * QD;           // 31,457,280
        int nthreads4 = (int)(total / 4);
        cvt_all<<<(nthreads4 + 255) / 256, 256>>>(hidden, Wq, Wk, Wv, Wo);
    }

    // fused QKV projection: g_qkv[2048, 6144] = hidden @ [Wq|Wk|Wv]^T
    gemm_mma<<<dim3(QKVD / 128, SEQ / 128), 256, GEMM_SMEM>>>(
        hid_h, wqkv_h, qkv_ptr, HID, QKVD);

    // RMSNorm + RoPE + fp16 conversion into [h][s][d] buffers
    {
        int nwarps = SEQ * 48;
        int nblocks = (nwarps * 32 + 255) / 256;
        rms_rope_kernel<<<nblocks, 256>>>(cosb, sinb, qw, kw);
    }

    // tensor-core causal GQA flash attention -> g_ao_h
    flash_mma_kernel<<<dim3(NQH, SEQ / 64), 128, ATTN_SMEM>>>();

    // output projection: out[2048, 2560] = O @ Wo^T
    gemm_mma<<<dim3(HID / 128, SEQ / 128), 256, GEMM_SMEM>>>(
        ao_h, wo_h, out, QD, HID);
}

// round 10
// speedup vs baseline: 7.5917x; 1.0351x over previous
#include <cuda_runtime.h>
#include <cuda_fp16.h>
#include <cstdint>
#include <cstdio>

#define SEQ   2048
#define HID   2560
#define QD    4096      // 32 heads * 128
#define KVD   1024      // 8 heads * 128
#define QKVD  6144      // QD + 2*KVD
#define HD    128
#define NQH   32
#define NKVH  8

// ---------------------------------------------------------------------------
// Scratch (device globals; no allocation allowed)
// ---------------------------------------------------------------------------
__device__ float g_qkv[(size_t)SEQ * QKVD];   // [s, 6144]: Q | K | V (fp32)

// fp16 operand buffers
__device__ __half g_hid_h[(size_t)SEQ * HID];     // hidden (A of QKV gemm)
__device__ __half g_wqkv_h[(size_t)QKVD * HID];   // Wq|Wk|Wv stacked (B)
__device__ __half g_wo_h[(size_t)HID * QD];       // Wo (B)
__device__ __half g_ao_h[(size_t)SEQ * QD];       // attn out (A of Wo gemm)

// attention operands, [head][seq][128]
__device__ __half g_qh[(size_t)NQH * SEQ * HD];   // Q hi (split A, scale*log2e folded)
__device__ __half g_ql[(size_t)NQH * SEQ * HD];   // Q lo
__device__ __half g_kh[(size_t)NKVH * SEQ * HD];  // K
__device__ __half g_vh[(size_t)NKVH * SEQ * HD];  // V

// ---------------------------------------------------------------------------
// PTX helpers
// ---------------------------------------------------------------------------
__device__ __forceinline__ uint32_t smem_u32(const void* p) {
    uint32_t a;
    asm("{ .reg .u64 t; cvta.to.shared.u64 t, %1; cvt.u32.u64 %0, t; }" : "=r"(a) : "l"(p));
    return a;
}
__device__ __forceinline__ void cpa16(uint32_t s, const void* g) {
    asm volatile("cp.async.cg.shared.global [%0], [%1], 16;" :: "r"(s), "l"(g));
}
__device__ __forceinline__ void cpa_commit() {
    asm volatile("cp.async.commit_group;" ::: "memory");
}
__device__ __forceinline__ void cpa_wait1() {
    asm volatile("cp.async.wait_group 1;" ::: "memory");
}
__device__ __forceinline__ void cpa_wait0() {
    asm volatile("cp.async.wait_group 0;" ::: "memory");
}
__device__ __forceinline__ void ldm_x4(uint32_t* r, uint32_t addr) {
    asm volatile("ldmatrix.sync.aligned.m8n8.x4.shared.b16 {%0,%1,%2,%3}, [%4];"
                 : "=r"(r[0]), "=r"(r[1]), "=r"(r[2]), "=r"(r[3]) : "r"(addr));
}
__device__ __forceinline__ void ldm_x4_t(uint32_t* r, uint32_t addr) {
    asm volatile("ldmatrix.sync.aligned.m8n8.x4.trans.shared.b16 {%0,%1,%2,%3}, [%4];"
                 : "=r"(r[0]), "=r"(r[1]), "=r"(r[2]), "=r"(r[3]) : "r"(addr));
}
__device__ __forceinline__ void mma_f16(float* c, const uint32_t* a, const uint32_t* b) {
    asm volatile(
        "mma.sync.aligned.m16n8k16.row.col.f32.f16.f16.f32 "
        "{%0,%1,%2,%3}, {%4,%5,%6,%7}, {%8,%9}, {%0,%1,%2,%3};"
        : "+f"(c[0]), "+f"(c[1]), "+f"(c[2]), "+f"(c[3])
        : "r"(a[0]), "r"(a[1]), "r"(a[2]), "r"(a[3]), "r"(b[0]), "r"(b[1]));
}
__device__ __forceinline__ uint32_t ex2_h2(float a, float b) {
    __half2 t = __floats2half2_rn(a, b);
    uint32_t in = *(uint32_t*)&t, out;
    asm("ex2.approx.f16x2 %0, %1;" : "=r"(out) : "r"(in));
    return out;
}

// ---------------------------------------------------------------------------
// fused fp32 -> fp16 conversion over all 5 input regions (one launch)
// ---------------------------------------------------------------------------
__global__ __launch_bounds__(256)
void cvt_all(const float* __restrict__ hid, const float* __restrict__ wq,
             const float* __restrict__ wk, const float* __restrict__ wv,
             const float* __restrict__ wo) {
    size_t i = ((size_t)blockIdx.x * blockDim.x + threadIdx.x) * 4;
    const size_t n0 = (size_t)SEQ * HID;
    const size_t n1 = (size_t)QD * HID;
    const size_t n2 = (size_t)KVD * HID;
    const size_t n4 = (size_t)HID * QD;

    const float* src;
    __half* dst;
    if (i < n0)                { src = hid; dst = g_hid_h + i; }
    else if ((i -= n0) < n1)   { src = wq;  dst = g_wqkv_h + i; }
    else if ((i -= n1) < n2)   { src = wk;  dst = g_wqkv_h + n1 + i; }
    else if ((i -= n2) < n2)   { src = wv;  dst = g_wqkv_h + n1 + n2 + i; }
    else if ((i -= n2) < n4)   { src = wo;  dst = g_wo_h + i; }
    else return;

    float4 x = *(const float4*)(src + i);
    *(__half2*)(dst)     = __floats2half2_rn(x.x, x.y);
    *(__half2*)(dst + 2) = __floats2half2_rn(x.z, x.w);
}

// ---------------------------------------------------------------------------
// mma.sync fp16 GEMM (NT): C[m,n] = sum_k A[m,k]*B[n,k], fp32 accum.
// CTA 128x128, BK=64 (fewer barriers), 8 warps (4x2), warp tile 32x64.
// Double-buffered cp.async.
// ---------------------------------------------------------------------------
#define BK 64
#define LDS_STR 72                    // 64 halves + 8 pad (144B stride, conflict-free)
#define TILE_H (128 * LDS_STR)        // 9216 halves per matrix
#define STAGE_H (2 * TILE_H)          // A | B
#define GEMM_SMEM (2 * STAGE_H * 2)   // 73728 B

__global__ __launch_bounds__(256, 2)
void gemm_mma(const __half* __restrict__ Ah, const __half* __restrict__ Bh,
              float* __restrict__ C, int K, int ldc) {
    extern __shared__ __half smem[];
    const uint32_t sbase = smem_u32(smem);

    const int tid  = threadIdx.x;
    const int warp = tid >> 5;
    const int lane = tid & 31;
    const int wm   = warp & 3;
    const int wn   = warp >> 2;
    const int bx = blockIdx.x, by = blockIdx.y;

    const __half* gA = Ah + (size_t)(by * 128) * K;
    const __half* gB = Bh + (size_t)(bx * 128) * K;

    float acc[2][8][4];
    #pragma unroll
    for (int i = 0; i < 2; i++)
        #pragma unroll
        for (int j = 0; j < 8; j++)
            #pragma unroll
            for (int t = 0; t < 4; t++) acc[i][j][t] = 0.0f;

    const int nchunk = K / BK;
    const int r0 = tid >> 2;              // 0..63
    const int ch0 = (tid & 3) * 8;        // 0,8,16,24

    auto load_stage = [&](int c, int s) {
        const size_t koff = (size_t)c * BK;
        uint32_t dst = sbase + (uint32_t)(s * STAGE_H) * 2;
        {
            const __half* a0 = gA + (size_t)r0 * K + koff;
            const __half* a1 = gA + (size_t)(r0 + 64) * K + koff;
            cpa16(dst + (r0 * LDS_STR + ch0) * 2,              a0 + ch0);
            cpa16(dst + (r0 * LDS_STR + ch0 + 32) * 2,         a0 + ch0 + 32);
            cpa16(dst + ((r0 + 64) * LDS_STR + ch0) * 2,       a1 + ch0);
            cpa16(dst + ((r0 + 64) * LDS_STR + ch0 + 32) * 2,  a1 + ch0 + 32);
        }
        {
            uint32_t d = dst + (uint32_t)TILE_H * 2;
            const __half* b0 = gB + (size_t)r0 * K + koff;
            const __half* b1 = gB + (size_t)(r0 + 64) * K + koff;
            cpa16(d + (r0 * LDS_STR + ch0) * 2,              b0 + ch0);
            cpa16(d + (r0 * LDS_STR + ch0 + 32) * 2,         b0 + ch0 + 32);
            cpa16(d + ((r0 + 64) * LDS_STR + ch0) * 2,       b1 + ch0);
            cpa16(d + ((r0 + 64) * LDS_STR + ch0 + 32) * 2,  b1 + ch0 + 32);
        }
    };

    const int a_row = (lane & 7) + ((lane >> 3) & 1) * 8;
    const int a_kof = (lane >> 4) * 8;
    const int b_mat = lane >> 3;
    const int b_row = lane & 7;
    const int b_kof = (b_mat & 1) * 8;
    const int b_jof = (b_mat >> 1);

    load_stage(0, 0);
    cpa_commit();

    for (int c = 0; c < nchunk; c++) {
        if (c + 1 < nchunk) {
            load_stage(c + 1, (c + 1) & 1);
            cpa_commit();
            cpa_wait1();
        } else {
            cpa_wait0();
        }
        __syncthreads();

        const uint32_t st = sbase + (uint32_t)((c & 1) * STAGE_H) * 2;
        const uint32_t sA = st;
        const uint32_t sB = st + (uint32_t)TILE_H * 2;

        #pragma unroll
        for (int ks = 0; ks < 4; ks++) {
            uint32_t ah[2][4];
            #pragma unroll
            for (int i = 0; i < 2; i++) {
                int m_local = wm * 32 + i * 16 + a_row;
                int k = ks * 16 + a_kof;
                uint32_t off = (uint32_t)(m_local * LDS_STR + k) * 2;
                ldm_x4(ah[i], sA + off);
            }
            #pragma unroll
            for (int jp = 0; jp < 4; jp++) {
                int n_local = wn * 64 + (jp * 2 + b_jof) * 8 + b_row;
                int k = ks * 16 + b_kof;
                uint32_t off = (uint32_t)(n_local * LDS_STR + k) * 2;
                uint32_t rh[4];
                ldm_x4(rh, sB + off);
                const int j0 = jp * 2, j1 = jp * 2 + 1;
                mma_f16(acc[0][j0], ah[0], rh);   mma_f16(acc[0][j1], ah[0], rh + 2);
                mma_f16(acc[1][j0], ah[1], rh);   mma_f16(acc[1][j1], ah[1], rh + 2);
            }
        }
        __syncthreads();
    }

    const int gid = lane >> 2;
    const int tgc = (lane & 3) * 2;
    #pragma unroll
    for (int i = 0; i < 2; i++) {
        int row = by * 128 + wm * 32 + i * 16 + gid;
        #pragma unroll
        for (int j = 0; j < 8; j++) {
            int col = bx * 128 + wn * 64 + j * 8 + tgc;
            float2 v0 = {acc[i][j][0], acc[i][j][1]};
            float2 v1 = {acc[i][j][2], acc[i][j][3]};
            *(float2*)(C + (size_t)row * ldc + col)       = v0;
            *(float2*)(C + (size_t)(row + 8) * ldc + col) = v1;
        }
    }
}

// ---------------------------------------------------------------------------
// RMSNorm + RoPE, fp32 g_qkv -> fp16 buffers, [h][s][d] layout.
// Q heads get scale = (1/sqrt(128)) * log2(e) folded in (softmax in log2).
// ---------------------------------------------------------------------------
__global__ __launch_bounds__(256)
void rms_rope_kernel(const float* __restrict__ cosb, const float* __restrict__ sinb,
                     const float* __restrict__ qw, const float* __restrict__ kw) {
    int gw = (blockIdx.x * blockDim.x + threadIdx.x) >> 5;
    int lane = threadIdx.x & 31;
    if (gw >= SEQ * 48) return;
    int s = gw / 48;
    int h = gw % 48;
    int d = lane * 4;

    float4 out;
    __half* dsingle = nullptr;

    if (h < 40) {
        const float* base;
        const float* w;
        if (h < NQH) {
            base = g_qkv + (size_t)s * QKVD + h * HD;
            w = qw;
        } else {
            int kh = h - NQH;
            base = g_qkv + (size_t)s * QKVD + QD + kh * HD;
            w = kw;
            dsingle = g_kh + ((size_t)kh * SEQ + s) * HD;
        }
        float4 x = *(const float4*)(base + d);
        float ss = x.x * x.x + x.y * x.y + x.z * x.z + x.w * x.w;
        #pragma unroll
        for (int o = 16; o > 0; o >>= 1) ss += __shfl_xor_sync(0xffffffffu, ss, o);
        float r = rsqrtf(ss * (1.0f / 128.0f) + 1e-6f);

        float4 wv = *(const float4*)(w + d);
        float4 xn;
        xn.x = x.x * r * wv.x; xn.y = x.y * r * wv.y;
        xn.z = x.z * r * wv.z; xn.w = x.w * r * wv.w;

        float4 ot;
        ot.x = __shfl_xor_sync(0xffffffffu, xn.x, 16);
        ot.y = __shfl_xor_sync(0xffffffffu, xn.y, 16);
        ot.z = __shfl_xor_sync(0xffffffffu, xn.z, 16);
        ot.w = __shfl_xor_sync(0xffffffffu, xn.w, 16);
        float sgn = (d < 64) ? -1.0f : 1.0f;

        float4 c = *(const float4*)(cosb + (size_t)s * HD + d);
        float4 si = *(const float4*)(sinb + (size_t)s * HD + d);
        out.x = xn.x * c.x + sgn * ot.x * si.x;
        out.y = xn.y * c.y + sgn * ot.y * si.y;
        out.z = xn.z * c.z + sgn * ot.z * si.z;
        out.w = xn.w * c.w + sgn * ot.w * si.w;
        if (h < NQH) {
            // fold softmax scale AND log2(e): S ends up in log2 domain
            const float sc = 0.12751743f;   // (1/sqrt(128)) * log2(e)
            out.x *= sc; out.y *= sc; out.z *= sc; out.w *= sc;
        }
    } else {
        int vh = h - 40;
        const float* base = g_qkv + (size_t)s * QKVD + QD + KVD + vh * HD;
        out = *(const float4*)(base + d);
        dsingle = g_vh + ((size_t)vh * SEQ + s) * HD;
    }

    if (h < NQH) {
        __half* dh = g_qh + ((size_t)h * SEQ + s) * HD;
        __half* dl = g_ql + ((size_t)h * SEQ + s) * HD;
        __half2 h0 = __floats2half2_rn(out.x, out.y);
        __half2 h1 = __floats2half2_rn(out.z, out.w);
        *(__half2*)(dh + d)     = h0;
        *(__half2*)(dh + d + 2) = h1;
        __half2 l0 = __floats2half2_rn(out.x - __half2float(__low2half(h0)),
                                       out.y - __half2float(__high2half(h0)));
        __half2 l1 = __floats2half2_rn(out.z - __half2float(__low2half(h1)),
                                       out.w - __half2float(__high2half(h1)));
        *(__half2*)(dl + d)     = l0;
        *(__half2*)(dl + d + 2) = l1;
    } else {
        *(__half2*)(dsingle + d)     = __floats2half2_rn(out.x, out.y);
        *(__half2*)(dsingle + d + 2) = __floats2half2_rn(out.z, out.w);
    }
}

// ---------------------------------------------------------------------------
// Tensor-core flash attention, causal, GQA. log2-domain softmax (ex2.f16x2).
// S = Qh*K + Ql*K (2-term); O = P*V. CTA = (head, 64 q rows), 4 warps.
// KV tiles double-buffered: prefetch tile it+1 while computing tile it.
// ---------------------------------------------------------------------------
#define ASTR 136               // halves per smem row
#define AMAT (64 * ASTR)       // halves per matrix
#define ATTN_SMEM (6 * AMAT * 2)   // Qh | Ql | K0 | V0 | K1 | V1

__global__ __launch_bounds__(128, 2)
void flash_mma_kernel() {
    extern __shared__ __half asm_smem[];
    const uint32_t sb = smem_u32(asm_smem);
    const uint32_t sQh = sb;
    const uint32_t sQl = sQh + AMAT * 2;
    const uint32_t sK[2] = { sQl + AMAT * 2, sQl + 3 * AMAT * 2 };
    const uint32_t sV[2] = { sQl + 2 * AMAT * 2, sQl + 4 * AMAT * 2 };

    const int h  = blockIdx.x;
    const int q0 = blockIdx.y * 64;
    const int kh = h >> 2;
    const int tid = threadIdx.x;
    const int warp = tid >> 5;
    const int lane = tid & 31;
    const int gid = lane >> 2;
    const int tig = lane & 3;

    const __half* bkh = g_kh + (size_t)kh * SEQ * HD;
    const __half* bvh = g_vh + (size_t)kh * SEQ * HD;

    auto load_kv = [&](int it, int buf) {
        const __half* pk = bkh + (size_t)(it * 64) * HD;
        const __half* pv = bvh + (size_t)(it * 64) * HD;
        #pragma unroll
        for (int i = 0; i < 8; i++) {
            int ch = tid + i * 128;
            int row = ch >> 4, c = ch & 15;
            uint32_t off = (uint32_t)(row * ASTR) * 2 + c * 16;
            size_t goff = (size_t)row * HD + c * 8;
            cpa16(sK[buf] + off, pk + goff);
            cpa16(sV[buf] + off, pv + goff);
        }
    };

    // prefetch: Q tile + KV tile 0, one commit group
    {
        const __half* gh = g_qh + ((size_t)h * SEQ + q0) * HD;
        const __half* gl = g_ql + ((size_t)h * SEQ + q0) * HD;
        #pragma unroll
        for (int i = 0; i < 8; i++) {
            int ch = tid + i * 128;
            int row = ch >> 4, c = ch & 15;
            uint32_t off = (uint32_t)(row * ASTR) * 2 + c * 16;
            cpa16(sQh + off, gh + (size_t)row * HD + c * 8);
            cpa16(sQl + off, gl + (size_t)row * HD + c * 8);
        }
        load_kv(0, 0);
        cpa_commit();
    }

    float oacc[16][4];
    #pragma unroll
    for (int j = 0; j < 16; j++)
        #pragma unroll
        for (int t = 0; t < 4; t++) oacc[j][t] = 0.0f;
    float mrow[2] = {-1e30f, -1e30f};
    float lrow[2] = {0.0f, 0.0f};

    const uint32_t qoff_row = (uint32_t)((warp * 16 + (lane & 15)) * ASTR) * 2;
    const uint32_t qoff_col = (uint32_t)((lane >> 4) * 8) * 2;
    const uint32_t koff_rowbase = (uint32_t)((lane & 7) * ASTR) * 2;
    const uint32_t koff_col = (uint32_t)(((lane >> 3) & 3) * 8) * 2;
    const uint32_t voff_rowbase = (uint32_t)(((lane & 7) + 8 * ((lane >> 3) & 1)) * ASTR) * 2;
    const uint32_t voff_col = (uint32_t)((lane >> 4) * 8) * 2;

    const int nit = q0 / 64;                 // iterations 0..nit
    for (int it = 0; it <= nit; it++) {
        const int cur = it & 1;
        cpa_wait0();
        __syncthreads();
        if (it < nit) {                      // prefetch next KV tile
            load_kv(it + 1, cur ^ 1);
            cpa_commit();
        }
        const uint32_t sKc = sK[cur];
        const uint32_t sVc = sV[cur];

        // ---- S = Q K^T (2-term, log2 domain) ----
        float sacc[8][4];
        #pragma unroll
        for (int j = 0; j < 8; j++)
            #pragma unroll
            for (int t = 0; t < 4; t++) sacc[j][t] = 0.0f;

        #pragma unroll
        for (int ks2 = 0; ks2 < 4; ks2++) {
            uint32_t qh2[2][4], ql2[2][4];
            #pragma unroll
            for (int e = 0; e < 2; e++) {
                uint32_t off = qoff_row + ((uint32_t)((ks2 * 2 + e) * 16) * 2 + qoff_col);
                ldm_x4(qh2[e], sQh + off);
                ldm_x4(ql2[e], sQl + off);
            }
            #pragma unroll
            for (int jn2 = 0; jn2 < 4; jn2++) {
                const int jA = jn2 * 2, jB = jn2 * 2 + 1;
                const uint32_t kcom = koff_rowbase + (uint32_t)(ks2 * 32) * 2 + koff_col;
                uint32_t offA = (uint32_t)(jA * 8 * ASTR) * 2 + kcom;
                uint32_t offB = (uint32_t)(jB * 8 * ASTR) * 2 + kcom;
                uint32_t khA[4], khB[4];
                ldm_x4(khA, sKc + offA); ldm_x4(khB, sKc + offB);
                mma_f16(sacc[jA], qh2[0], khA);     mma_f16(sacc[jB], qh2[0], khB);
                mma_f16(sacc[jA], qh2[1], khA + 2); mma_f16(sacc[jB], qh2[1], khB + 2);
                mma_f16(sacc[jA], ql2[0], khA);     mma_f16(sacc[jB], ql2[0], khB);
                mma_f16(sacc[jA], ql2[1], khA + 2); mma_f16(sacc[jB], ql2[1], khB + 2);
            }
        }

        // ---- causal mask on diagonal tile ----
        if (it == nit) {
            int qg0 = q0 + warp * 16 + gid;
            #pragma unroll
            for (int jn = 0; jn < 8; jn++) {
                int kg = q0 + jn * 8 + tig * 2;
                if (kg > qg0)     sacc[jn][0] = -1e30f;
                if (kg + 1 > qg0) sacc[jn][1] = -1e30f;
                if (kg > qg0 + 8)     sacc[jn][2] = -1e30f;
                if (kg + 1 > qg0 + 8) sacc[jn][3] = -1e30f;
            }
        }

        // ---- online softmax (log2 domain, fp16x2 ex2) ----
        float mn0 = mrow[0], mn1 = mrow[1];
        #pragma unroll
        for (int jn = 0; jn < 8; jn++) {
            mn0 = fmaxf(mn0, fmaxf(sacc[jn][0], sacc[jn][1]));
            mn1 = fmaxf(mn1, fmaxf(sacc[jn][2], sacc[jn][3]));
        }
        mn0 = fmaxf(mn0, __shfl_xor_sync(0xffffffffu, mn0, 1));
        mn0 = fmaxf(mn0, __shfl_xor_sync(0xffffffffu, mn0, 2));
        mn1 = fmaxf(mn1, __shfl_xor_sync(0xffffffffu, mn1, 1));
        mn1 = fmaxf(mn1, __shfl_xor_sync(0xffffffffu, mn1, 2));
        float al0 = exp2f(mrow[0] - mn0);
        float al1 = exp2f(mrow[1] - mn1);
        mrow[0] = mn0; mrow[1] = mn1;
        lrow[0] *= al0; lrow[1] *= al1;

        uint32_t ph[8][2];
        float lacc0 = 0.0f, lacc1 = 0.0f;
        #pragma unroll
        for (int jn = 0; jn < 8; jn++) {
            uint32_t p0 = ex2_h2(sacc[jn][0] - mn0, sacc[jn][1] - mn0);
            uint32_t p1 = ex2_h2(sacc[jn][2] - mn1, sacc[jn][3] - mn1);
            ph[jn][0] = p0;
            ph[jn][1] = p1;
            float2 f0 = __half22float2(*(__half2*)&p0);
            float2 f1 = __half22float2(*(__half2*)&p1);
            lacc0 += f0.x + f0.y;
            lacc1 += f1.x + f1.y;
        }
        lrow[0] += lacc0;
        lrow[1] += lacc1;

        #pragma unroll
        for (int jd = 0; jd < 16; jd++) {
            oacc[jd][0] *= al0; oacc[jd][1] *= al0;
            oacc[jd][2] *= al1; oacc[jd][3] *= al1;
        }

        // ---- O += P V ----
        #pragma unroll
        for (int kks = 0; kks < 4; kks++) {
            uint32_t aPh[4] = {ph[2 * kks][0], ph[2 * kks][1], ph[2 * kks + 1][0], ph[2 * kks + 1][1]};
            #pragma unroll
            for (int jd2 = 0; jd2 < 8; jd2++) {
                uint32_t off = (uint32_t)(kks * 16 * ASTR) * 2 + voff_rowbase +
                               (uint32_t)(jd2 * 16) * 2 + voff_col;
                uint32_t vh4[4];
                ldm_x4_t(vh4, sVc + off);
                mma_f16(oacc[jd2 * 2], aPh, vh4);
                mma_f16(oacc[jd2 * 2 + 1], aPh, vh4 + 2);
            }
        }
    }

    // final: reduce l across quad, normalize, write fp16
    lrow[0] += __shfl_xor_sync(0xffffffffu, lrow[0], 1);
    lrow[0] += __shfl_xor_sync(0xffffffffu, lrow[0], 2);
    lrow[1] += __shfl_xor_sync(0xffffffffu, lrow[1], 1);
    lrow[1] += __shfl_xor_sync(0xffffffffu, lrow[1], 2);
    float inv0 = 1.0f / lrow[0];
    float inv1 = 1.0f / lrow[1];

    int row0 = q0 + warp * 16 + gid;
    #pragma unroll
    for (int jd = 0; jd < 16; jd++) {
        int col = h * HD + jd * 8 + tig * 2;
        __half2 h0 = __floats2half2_rn(oacc[jd][0] * inv0, oacc[jd][1] * inv0);
        __half2 h1 = __floats2half2_rn(oacc[jd][2] * inv1, oacc[jd][3] * inv1);
        *(__half2*)(g_ao_h + (size_t)row0 * QD + col)       = h0;
        *(__half2*)(g_ao_h + (size_t)(row0 + 8) * QD + col) = h1;
    }
}

// ---------------------------------------------------------------------------
// launch
// ---------------------------------------------------------------------------
extern "C" void kernel_launch(void* const* d_in, const int* in_sizes, int n_in,
                              void* d_out, int out_size) {
    const float* hidden = (const float*)d_in[0];
    const float* cosb   = (const float*)d_in[1];
    const float* sinb   = (const float*)d_in[2];
    const float* Wq     = (const float*)d_in[3];
    const float* Wk     = (const float*)d_in[4];
    const float* Wv     = (const float*)d_in[5];
    const float* Wo     = (const float*)d_in[6];
    const float* qw     = (const float*)d_in[7];
    const float* kw     = (const float*)d_in[8];
    float* out = (float*)d_out;

    float* qkv_ptr = nullptr;
    __half *hid_h, *wqkv_h, *wo_h, *ao_h;
    cudaGetSymbolAddress((void**)&qkv_ptr, g_qkv);
    cudaGetSymbolAddress((void**)&hid_h, g_hid_h);
    cudaGetSymbolAddress((void**)&wqkv_h, g_wqkv_h);
    cudaGetSymbolAddress((void**)&wo_h, g_wo_h);
    cudaGetSymbolAddress((void**)&ao_h, g_ao_h);

    cudaFuncSetAttribute(gemm_mma, cudaFuncAttributeMaxDynamicSharedMemorySize, GEMM_SMEM);
    cudaFuncSetAttribute(flash_mma_kernel, cudaFuncAttributeMaxDynamicSharedMemorySize, ATTN_SMEM);

    // fused conversions to fp16 (one launch)
    {
        size_t total = (size_t)SEQ * HID + (size_t)QD * HID + 2 * (size_t)KVD * HID +
                       (size_t)HID * QD;
        int nthreads4 = (int)(total / 4);
        cvt_all<<<(nthreads4 + 255) / 256, 256>>>(hidden, Wq, Wk, Wv, Wo);
    }

    // fused QKV projection: g_qkv[2048, 6144] = hidden @ [Wq|Wk|Wv]^T
    gemm_mma<<<dim3(QKVD / 128, SEQ / 128), 256, GEMM_SMEM>>>(
        hid_h, wqkv_h, qkv_ptr, HID, QKVD);

    // RMSNorm + RoPE + fp16 conversion into [h][s][d] buffers
    {
        int nwarps = SEQ * 48;
        int nblocks = (nwarps * 32 + 255) / 256;
        rms_rope_kernel<<<nblocks, 256>>>(cosb, sinb, qw, kw);
    }

    // tensor-core causal GQA flash attention -> g_ao_h
    flash_mma_kernel<<<dim3(NQH, SEQ / 64), 128, ATTN_SMEM>>>();

    // output projection: out[2048, 2560] = O @ Wo^T
    gemm_mma<<<dim3(HID / 128, SEQ / 128), 256, GEMM_SMEM>>>(
        ao_h, wo_h, out, QD, HID);
}

// round 11
// speedup vs baseline: 7.7136x; 1.0161x over previous
#include <cuda_runtime.h>
#include <cuda_fp16.h>
#include <cstdint>
#include <cstdio>

#define SEQ   2048
#define HID   2560
#define QD    4096      // 32 heads * 128
#define KVD   1024      // 8 heads * 128
#define QKVD  6144      // QD + 2*KVD
#define HD    128
#define NQH   32
#define NKVH  8

// ---------------------------------------------------------------------------
// Scratch (device globals; no allocation allowed)
// ---------------------------------------------------------------------------
__device__ float g_qkv[(size_t)SEQ * QKVD];   // [s, 6144]: Q | K | V (fp32)

// fp16 operand buffers
__device__ __half g_hid_h[(size_t)SEQ * HID];     // hidden (A of QKV gemm)
__device__ __half g_wqkv_h[(size_t)QKVD * HID];   // Wq|Wk|Wv stacked (B)
__device__ __half g_wo_h[(size_t)HID * QD];       // Wo (B)
__device__ __half g_ao_h[(size_t)SEQ * QD];       // attn out (A of Wo gemm)

// attention operands, [head][seq][128]
__device__ __half g_qh[(size_t)NQH * SEQ * HD];   // Q hi (split A, scale*log2e folded)
__device__ __half g_ql[(size_t)NQH * SEQ * HD];   // Q lo
__device__ __half g_kh[(size_t)NKVH * SEQ * HD];  // K
__device__ __half g_vh[(size_t)NKVH * SEQ * HD];  // V

// ---------------------------------------------------------------------------
// PTX helpers
// ---------------------------------------------------------------------------
__device__ __forceinline__ uint32_t smem_u32(const void* p) {
    uint32_t a;
    asm("{ .reg .u64 t; cvta.to.shared.u64 t, %1; cvt.u32.u64 %0, t; }" : "=r"(a) : "l"(p));
    return a;
}
__device__ __forceinline__ void cpa16(uint32_t s, const void* g) {
    asm volatile("cp.async.cg.shared.global [%0], [%1], 16;" :: "r"(s), "l"(g));
}
__device__ __forceinline__ void cpa_commit() {
    asm volatile("cp.async.commit_group;" ::: "memory");
}
__device__ __forceinline__ void cpa_wait1() {
    asm volatile("cp.async.wait_group 1;" ::: "memory");
}
__device__ __forceinline__ void cpa_wait0() {
    asm volatile("cp.async.wait_group 0;" ::: "memory");
}
__device__ __forceinline__ void ldm_x4(uint32_t* r, uint32_t addr) {
    asm volatile("ldmatrix.sync.aligned.m8n8.x4.shared.b16 {%0,%1,%2,%3}, [%4];"
                 : "=r"(r[0]), "=r"(r[1]), "=r"(r[2]), "=r"(r[3]) : "r"(addr));
}
__device__ __forceinline__ void ldm_x4_t(uint32_t* r, uint32_t addr) {
    asm volatile("ldmatrix.sync.aligned.m8n8.x4.trans.shared.b16 {%0,%1,%2,%3}, [%4];"
                 : "=r"(r[0]), "=r"(r[1]), "=r"(r[2]), "=r"(r[3]) : "r"(addr));
}
__device__ __forceinline__ void mma_f16(float* c, const uint32_t* a, const uint32_t* b) {
    asm volatile(
        "mma.sync.aligned.m16n8k16.row.col.f32.f16.f16.f32 "
        "{%0,%1,%2,%3}, {%4,%5,%6,%7}, {%8,%9}, {%0,%1,%2,%3};"
        : "+f"(c[0]), "+f"(c[1]), "+f"(c[2]), "+f"(c[3])
        : "r"(a[0]), "r"(a[1]), "r"(a[2]), "r"(a[3]), "r"(b[0]), "r"(b[1]));
}
__device__ __forceinline__ uint32_t ex2_h2(float a, float b) {
    __half2 t = __floats2half2_rn(a, b);
    uint32_t in = *(uint32_t*)&t, out;
    asm("ex2.approx.f16x2 %0, %1;" : "=r"(out) : "r"(in));
    return out;
}

// ---------------------------------------------------------------------------
// fused fp32 -> fp16 conversion over all 5 input regions (one launch)
// ---------------------------------------------------------------------------
__global__ __launch_bounds__(256)
void cvt_all(const float* __restrict__ hid, const float* __restrict__ wq,
             const float* __restrict__ wk, const float* __restrict__ wv,
             const float* __restrict__ wo) {
    size_t i = ((size_t)blockIdx.x * blockDim.x + threadIdx.x) * 4;
    const size_t n0 = (size_t)SEQ * HID;
    const size_t n1 = (size_t)QD * HID;
    const size_t n2 = (size_t)KVD * HID;
    const size_t n4 = (size_t)HID * QD;

    const float* src;
    __half* dst;
    if (i < n0)                { src = hid; dst = g_hid_h + i; }
    else if ((i -= n0) < n1)   { src = wq;  dst = g_wqkv_h + i; }
    else if ((i -= n1) < n2)   { src = wk;  dst = g_wqkv_h + n1 + i; }
    else if ((i -= n2) < n2)   { src = wv;  dst = g_wqkv_h + n1 + n2 + i; }
    else if ((i -= n2) < n4)   { src = wo;  dst = g_wo_h + i; }
    else return;

    float4 x = *(const float4*)(src + i);
    *(__half2*)(dst)     = __floats2half2_rn(x.x, x.y);
    *(__half2*)(dst + 2) = __floats2half2_rn(x.z, x.w);
}

// ---------------------------------------------------------------------------
// mma.sync fp16 GEMM (NT): C[m,n] = sum_k A[m,k]*B[n,k], fp32 accum.
// CTA 128x128, BK=64, 8 warps (4x2), warp tile 32x64. Double-buffered.
// ---------------------------------------------------------------------------
#define BK 64
#define LDS_STR 72                    // 64 halves + 8 pad (144B stride, conflict-free)
#define TILE_H (128 * LDS_STR)
#define STAGE_H (2 * TILE_H)          // A | B
#define GEMM_SMEM (2 * STAGE_H * 2)   // 73728 B

__global__ __launch_bounds__(256, 2)
void gemm_mma(const __half* __restrict__ Ah, const __half* __restrict__ Bh,
              float* __restrict__ C, int K, int ldc) {
    extern __shared__ __half smem[];
    const uint32_t sbase = smem_u32(smem);

    const int tid  = threadIdx.x;
    const int warp = tid >> 5;
    const int lane = tid & 31;
    const int wm   = warp & 3;
    const int wn   = warp >> 2;
    const int bx = blockIdx.x, by = blockIdx.y;

    const __half* gA = Ah + (size_t)(by * 128) * K;
    const __half* gB = Bh + (size_t)(bx * 128) * K;

    float acc[2][8][4];
    #pragma unroll
    for (int i = 0; i < 2; i++)
        #pragma unroll
        for (int j = 0; j < 8; j++)
            #pragma unroll
            for (int t = 0; t < 4; t++) acc[i][j][t] = 0.0f;

    const int nchunk = K / BK;
    const int r0 = tid >> 2;
    const int ch0 = (tid & 3) * 8;

    auto load_stage = [&](int c, int s) {
        const size_t koff = (size_t)c * BK;
        uint32_t dst = sbase + (uint32_t)(s * STAGE_H) * 2;
        {
            const __half* a0 = gA + (size_t)r0 * K + koff;
            const __half* a1 = gA + (size_t)(r0 + 64) * K + koff;
            cpa16(dst + (r0 * LDS_STR + ch0) * 2,              a0 + ch0);
            cpa16(dst + (r0 * LDS_STR + ch0 + 32) * 2,         a0 + ch0 + 32);
            cpa16(dst + ((r0 + 64) * LDS_STR + ch0) * 2,       a1 + ch0);
            cpa16(dst + ((r0 + 64) * LDS_STR + ch0 + 32) * 2,  a1 + ch0 + 32);
        }
        {
            uint32_t d = dst + (uint32_t)TILE_H * 2;
            const __half* b0 = gB + (size_t)r0 * K + koff;
            const __half* b1 = gB + (size_t)(r0 + 64) * K + koff;
            cpa16(d + (r0 * LDS_STR + ch0) * 2,              b0 + ch0);
            cpa16(d + (r0 * LDS_STR + ch0 + 32) * 2,         b0 + ch0 + 32);
            cpa16(d + ((r0 + 64) * LDS_STR + ch0) * 2,       b1 + ch0);
            cpa16(d + ((r0 + 64) * LDS_STR + ch0 + 32) * 2,  b1 + ch0 + 32);
        }
    };

    const int a_row = (lane & 7) + ((lane >> 3) & 1) * 8;
    const int a_kof = (lane >> 4) * 8;
    const int b_mat = lane >> 3;
    const int b_row = lane & 7;
    const int b_kof = (b_mat & 1) * 8;
    const int b_jof = (b_mat >> 1);

    load_stage(0, 0);
    cpa_commit();

    for (int c = 0; c < nchunk; c++) {
        if (c + 1 < nchunk) {
            load_stage(c + 1, (c + 1) & 1);
            cpa_commit();
            cpa_wait1();
        } else {
            cpa_wait0();
        }
        __syncthreads();

        const uint32_t st = sbase + (uint32_t)((c & 1) * STAGE_H) * 2;
        const uint32_t sA = st;
        const uint32_t sB = st + (uint32_t)TILE_H * 2;

        #pragma unroll
        for (int ks = 0; ks < 4; ks++) {
            uint32_t ah[2][4];
            #pragma unroll
            for (int i = 0; i < 2; i++) {
                int m_local = wm * 32 + i * 16 + a_row;
                int k = ks * 16 + a_kof;
                uint32_t off = (uint32_t)(m_local * LDS_STR + k) * 2;
                ldm_x4(ah[i], sA + off);
            }
            #pragma unroll
            for (int jp = 0; jp < 4; jp++) {
                int n_local = wn * 64 + (jp * 2 + b_jof) * 8 + b_row;
                int k = ks * 16 + b_kof;
                uint32_t off = (uint32_t)(n_local * LDS_STR + k) * 2;
                uint32_t rh[4];
                ldm_x4(rh, sB + off);
                const int j0 = jp * 2, j1 = jp * 2 + 1;
                mma_f16(acc[0][j0], ah[0], rh);   mma_f16(acc[0][j1], ah[0], rh + 2);
                mma_f16(acc[1][j0], ah[1], rh);   mma_f16(acc[1][j1], ah[1], rh + 2);
            }
        }
        __syncthreads();
    }

    const int gid = lane >> 2;
    const int tgc = (lane & 3) * 2;
    #pragma unroll
    for (int i = 0; i < 2; i++) {
        int row = by * 128 + wm * 32 + i * 16 + gid;
        #pragma unroll
        for (int j = 0; j < 8; j++) {
            int col = bx * 128 + wn * 64 + j * 8 + tgc;
            float2 v0 = {acc[i][j][0], acc[i][j][1]};
            float2 v1 = {acc[i][j][2], acc[i][j][3]};
            *(float2*)(C + (size_t)row * ldc + col)       = v0;
            *(float2*)(C + (size_t)(row + 8) * ldc + col) = v1;
        }
    }
}

// ---------------------------------------------------------------------------
// RMSNorm + RoPE, fp32 g_qkv -> fp16 buffers, [h][s][d] layout.
// Q heads get scale = (1/sqrt(128)) * log2(e) folded in (softmax in log2).
// ---------------------------------------------------------------------------
__global__ __launch_bounds__(256)
void rms_rope_kernel(const float* __restrict__ cosb, const float* __restrict__ sinb,
                     const float* __restrict__ qw, const float* __restrict__ kw) {
    int gw = (blockIdx.x * blockDim.x + threadIdx.x) >> 5;
    int lane = threadIdx.x & 31;
    if (gw >= SEQ * 48) return;
    int s = gw / 48;
    int h = gw % 48;
    int d = lane * 4;

    float4 out;
    __half* dsingle = nullptr;

    if (h < 40) {
        const float* base;
        const float* w;
        if (h < NQH) {
            base = g_qkv + (size_t)s * QKVD + h * HD;
            w = qw;
        } else {
            int kh = h - NQH;
            base = g_qkv + (size_t)s * QKVD + QD + kh * HD;
            w = kw;
            dsingle = g_kh + ((size_t)kh * SEQ + s) * HD;
        }
        float4 x = *(const float4*)(base + d);
        float ss = x.x * x.x + x.y * x.y + x.z * x.z + x.w * x.w;
        #pragma unroll
        for (int o = 16; o > 0; o >>= 1) ss += __shfl_xor_sync(0xffffffffu, ss, o);
        float r = rsqrtf(ss * (1.0f / 128.0f) + 1e-6f);

        float4 wv = *(const float4*)(w + d);
        float4 xn;
        xn.x = x.x * r * wv.x; xn.y = x.y * r * wv.y;
        xn.z = x.z * r * wv.z; xn.w = x.w * r * wv.w;

        float4 ot;
        ot.x = __shfl_xor_sync(0xffffffffu, xn.x, 16);
        ot.y = __shfl_xor_sync(0xffffffffu, xn.y, 16);
        ot.z = __shfl_xor_sync(0xffffffffu, xn.z, 16);
        ot.w = __shfl_xor_sync(0xffffffffu, xn.w, 16);
        float sgn = (d < 64) ? -1.0f : 1.0f;

        float4 c = *(const float4*)(cosb + (size_t)s * HD + d);
        float4 si = *(const float4*)(sinb + (size_t)s * HD + d);
        out.x = xn.x * c.x + sgn * ot.x * si.x;
        out.y = xn.y * c.y + sgn * ot.y * si.y;
        out.z = xn.z * c.z + sgn * ot.z * si.z;
        out.w = xn.w * c.w + sgn * ot.w * si.w;
        if (h < NQH) {
            // fold softmax scale AND log2(e): S ends up in log2 domain
            const float sc = 0.12751743f;   // (1/sqrt(128)) * log2(e)
            out.x *= sc; out.y *= sc; out.z *= sc; out.w *= sc;
        }
    } else {
        int vh = h - 40;
        const float* base = g_qkv + (size_t)s * QKVD + QD + KVD + vh * HD;
        out = *(const float4*)(base + d);
        dsingle = g_vh + ((size_t)vh * SEQ + s) * HD;
    }

    if (h < NQH) {
        __half* dh = g_qh + ((size_t)h * SEQ + s) * HD;
        __half* dl = g_ql + ((size_t)h * SEQ + s) * HD;
        __half2 h0 = __floats2half2_rn(out.x, out.y);
        __half2 h1 = __floats2half2_rn(out.z, out.w);
        *(__half2*)(dh + d)     = h0;
        *(__half2*)(dh + d + 2) = h1;
        __half2 l0 = __floats2half2_rn(out.x - __half2float(__low2half(h0)),
                                       out.y - __half2float(__high2half(h0)));
        __half2 l1 = __floats2half2_rn(out.z - __half2float(__low2half(h1)),
                                       out.w - __half2float(__high2half(h1)));
        *(__half2*)(dl + d)     = l0;
        *(__half2*)(dl + d + 2) = l1;
    } else {
        *(__half2*)(dsingle + d)     = __floats2half2_rn(out.x, out.y);
        *(__half2*)(dsingle + d + 2) = __floats2half2_rn(out.z, out.w);
    }
}

// ---------------------------------------------------------------------------
// Tensor-core flash attention, causal, GQA. log2-domain softmax (ex2.f16x2).
// CTA = (head, 128-row q tile), 8 warps (warp w owns rows 16w..16w+15).
// KV tiles (64 rows) double-buffered and shared by all 8 warps.
// Tile order reversed (longest first) to kill the causal-imbalance tail.
// ---------------------------------------------------------------------------
#define ASTR 136                   // halves per smem row
#define AKV  (64 * ASTR)           // halves per KV matrix
#define AQ   (128 * ASTR)          // halves per Q matrix
#define ATTN_SMEM ((2 * AQ + 4 * AKV) * 2)   // 139264 B

__global__ __launch_bounds__(256, 1)
void flash_mma_kernel() {
    extern __shared__ __half asm_smem[];
    const uint32_t sb = smem_u32(asm_smem);
    const uint32_t sQh = sb;
    const uint32_t sQl = sQh + AQ * 2;
    const uint32_t kvb = sQl + AQ * 2;
    const uint32_t sK[2] = { kvb,            kvb + 2 * AKV * 2 };
    const uint32_t sV[2] = { kvb + AKV * 2,  kvb + 3 * AKV * 2 };

    const int h  = blockIdx.x;
    const int qt = gridDim.y - 1 - blockIdx.y;   // longest tiles first
    const int q0 = qt * 128;
    const int kh = h >> 2;
    const int tid = threadIdx.x;
    const int warp = tid >> 5;
    const int lane = tid & 31;
    const int gid = lane >> 2;
    const int tig = lane & 3;

    const __half* bkh = g_kh + (size_t)kh * SEQ * HD;
    const __half* bvh = g_vh + (size_t)kh * SEQ * HD;

    auto load_kv = [&](int it, int buf) {
        const __half* pk = bkh + (size_t)(it * 64) * HD;
        const __half* pv = bvh + (size_t)(it * 64) * HD;
        #pragma unroll
        for (int i = 0; i < 4; i++) {
            int ch = tid + i * 256;            // 1024 chunks: 64 rows x 16
            int row = ch >> 4, c = ch & 15;
            uint32_t off = (uint32_t)(row * ASTR) * 2 + c * 16;
            size_t goff = (size_t)row * HD + c * 8;
            cpa16(sK[buf] + off, pk + goff);
            cpa16(sV[buf] + off, pv + goff);
        }
    };

    // prefetch: Q tile (128 rows, hi/lo) + KV tile 0
    {
        const __half* gh = g_qh + ((size_t)h * SEQ + q0) * HD;
        const __half* gl = g_ql + ((size_t)h * SEQ + q0) * HD;
        #pragma unroll
        for (int i = 0; i < 8; i++) {
            int ch = tid + i * 256;            // 2048 chunks: 128 rows x 16
            int row = ch >> 4, c = ch & 15;
            uint32_t off = (uint32_t)(row * ASTR) * 2 + c * 16;
            cpa16(sQh + off, gh + (size_t)row * HD + c * 8);
            cpa16(sQl + off, gl + (size_t)row * HD + c * 8);
        }
        load_kv(0, 0);
        cpa_commit();
    }

    float oacc[16][4];
    #pragma unroll
    for (int j = 0; j < 16; j++)
        #pragma unroll
        for (int t = 0; t < 4; t++) oacc[j][t] = 0.0f;
    float mrow[2] = {-1e30f, -1e30f};
    float lrow[2] = {0.0f, 0.0f};

    const uint32_t qoff_row = (uint32_t)((warp * 16 + (lane & 15)) * ASTR) * 2;
    const uint32_t qoff_col = (uint32_t)((lane >> 4) * 8) * 2;
    const uint32_t koff_rowbase = (uint32_t)((lane & 7) * ASTR) * 2;
    const uint32_t koff_col = (uint32_t)(((lane >> 3) & 3) * 8) * 2;
    const uint32_t voff_rowbase = (uint32_t)(((lane & 7) + 8 * ((lane >> 3) & 1)) * ASTR) * 2;
    const uint32_t voff_col = (uint32_t)((lane >> 4) * 8) * 2;

    const int nit = 2 * qt + 1;              // KV tiles 0..nit (kg up to q0+127)
    for (int it = 0; it <= nit; it++) {
        const int cur = it & 1;
        cpa_wait0();
        __syncthreads();
        if (it < nit) {
            load_kv(it + 1, cur ^ 1);
            cpa_commit();
        }
        // upper-half warps are fully masked in the last diagonal tile
        const bool active = !(it == nit && warp < 4);
        if (active) {
            const uint32_t sKc = sK[cur];
            const uint32_t sVc = sV[cur];

            // ---- S = Q K^T (2-term, log2 domain) ----
            float sacc[8][4];
            #pragma unroll
            for (int j = 0; j < 8; j++)
                #pragma unroll
                for (int t = 0; t < 4; t++) sacc[j][t] = 0.0f;

            #pragma unroll
            for (int ks2 = 0; ks2 < 4; ks2++) {
                uint32_t qh2[2][4], ql2[2][4];
                #pragma unroll
                for (int e = 0; e < 2; e++) {
                    uint32_t off = qoff_row + ((uint32_t)((ks2 * 2 + e) * 16) * 2 + qoff_col);
                    ldm_x4(qh2[e], sQh + off);
                    ldm_x4(ql2[e], sQl + off);
                }
                #pragma unroll
                for (int jn2 = 0; jn2 < 4; jn2++) {
                    const int jA = jn2 * 2, jB = jn2 * 2 + 1;
                    const uint32_t kcom = koff_rowbase + (uint32_t)(ks2 * 32) * 2 + koff_col;
                    uint32_t offA = (uint32_t)(jA * 8 * ASTR) * 2 + kcom;
                    uint32_t offB = (uint32_t)(jB * 8 * ASTR) * 2 + kcom;
                    uint32_t khA[4], khB[4];
                    ldm_x4(khA, sKc + offA); ldm_x4(khB, sKc + offB);
                    mma_f16(sacc[jA], qh2[0], khA);     mma_f16(sacc[jB], qh2[0], khB);
                    mma_f16(sacc[jA], qh2[1], khA + 2); mma_f16(sacc[jB], qh2[1], khB + 2);
                    mma_f16(sacc[jA], ql2[0], khA);     mma_f16(sacc[jB], ql2[0], khB);
                    mma_f16(sacc[jA], ql2[1], khA + 2); mma_f16(sacc[jB], ql2[1], khB + 2);
                }
            }

            // ---- causal mask (last two KV tiles overlap the diagonal) ----
            if (it >= 2 * qt) {
                int qg0 = q0 + warp * 16 + gid;
                #pragma unroll
                for (int jn = 0; jn < 8; jn++) {
                    int kg = it * 64 + jn * 8 + tig * 2;
                    if (kg > qg0)     sacc[jn][0] = -1e30f;
                    if (kg + 1 > qg0) sacc[jn][1] = -1e30f;
                    if (kg > qg0 + 8)     sacc[jn][2] = -1e30f;
                    if (kg + 1 > qg0 + 8) sacc[jn][3] = -1e30f;
                }
            }

            // ---- online softmax (log2 domain, fp16x2 ex2) ----
            float mn0 = mrow[0], mn1 = mrow[1];
            #pragma unroll
            for (int jn = 0; jn < 8; jn++) {
                mn0 = fmaxf(mn0, fmaxf(sacc[jn][0], sacc[jn][1]));
                mn1 = fmaxf(mn1, fmaxf(sacc[jn][2], sacc[jn][3]));
            }
            mn0 = fmaxf(mn0, __shfl_xor_sync(0xffffffffu, mn0, 1));
            mn0 = fmaxf(mn0, __shfl_xor_sync(0xffffffffu, mn0, 2));
            mn1 = fmaxf(mn1, __shfl_xor_sync(0xffffffffu, mn1, 1));
            mn1 = fmaxf(mn1, __shfl_xor_sync(0xffffffffu, mn1, 2));
            float al0 = exp2f(mrow[0] - mn0);
            float al1 = exp2f(mrow[1] - mn1);
            mrow[0] = mn0; mrow[1] = mn1;
            lrow[0] *= al0; lrow[1] *= al1;

            uint32_t ph[8][2];
            float lacc0 = 0.0f, lacc1 = 0.0f;
            #pragma unroll
            for (int jn = 0; jn < 8; jn++) {
                uint32_t p0 = ex2_h2(sacc[jn][0] - mn0, sacc[jn][1] - mn0);
                uint32_t p1 = ex2_h2(sacc[jn][2] - mn1, sacc[jn][3] - mn1);
                ph[jn][0] = p0;
                ph[jn][1] = p1;
                float2 f0 = __half22float2(*(__half2*)&p0);
                float2 f1 = __half22float2(*(__half2*)&p1);
                lacc0 += f0.x + f0.y;
                lacc1 += f1.x + f1.y;
            }
            lrow[0] += lacc0;
            lrow[1] += lacc1;

            #pragma unroll
            for (int jd = 0; jd < 16; jd++) {
                oacc[jd][0] *= al0; oacc[jd][1] *= al0;
                oacc[jd][2] *= al1; oacc[jd][3] *= al1;
            }

            // ---- O += P V ----
            #pragma unroll
            for (int kks = 0; kks < 4; kks++) {
                uint32_t aPh[4] = {ph[2 * kks][0], ph[2 * kks][1],
                                   ph[2 * kks + 1][0], ph[2 * kks + 1][1]};
                #pragma unroll
                for (int jd2 = 0; jd2 < 8; jd2++) {
                    uint32_t off = (uint32_t)(kks * 16 * ASTR) * 2 + voff_rowbase +
                                   (uint32_t)(jd2 * 16) * 2 + voff_col;
                    uint32_t vh4[4];
                    ldm_x4_t(vh4, sVc + off);
                    mma_f16(oacc[jd2 * 2], aPh, vh4);
                    mma_f16(oacc[jd2 * 2 + 1], aPh, vh4 + 2);
                }
            }
        }
    }

    // final: reduce l across quad, normalize, write fp16
    lrow[0] += __shfl_xor_sync(0xffffffffu, lrow[0], 1);
    lrow[0] += __shfl_xor_sync(0xffffffffu, lrow[0], 2);
    lrow[1] += __shfl_xor_sync(0xffffffffu, lrow[1], 1);
    lrow[1] += __shfl_xor_sync(0xffffffffu, lrow[1], 2);
    float inv0 = 1.0f / lrow[0];
    float inv1 = 1.0f / lrow[1];

    int row0 = q0 + warp * 16 + gid;
    #pragma unroll
    for (int jd = 0; jd < 16; jd++) {
        int col = h * HD + jd * 8 + tig * 2;
        __half2 h0 = __floats2half2_rn(oacc[jd][0] * inv0, oacc[jd][1] * inv0);
        __half2 h1 = __floats2half2_rn(oacc[jd][2] * inv1, oacc[jd][3] * inv1);
        *(__half2*)(g_ao_h + (size_t)row0 * QD + col)       = h0;
        *(__half2*)(g_ao_h + (size_t)(row0 + 8) * QD + col) = h1;
    }
}

// ---------------------------------------------------------------------------
// launch
// ---------------------------------------------------------------------------
extern "C" void kernel_launch(void* const* d_in, const int* in_sizes, int n_in,
                              void* d_out, int out_size) {
    const float* hidden = (const float*)d_in[0];
    const float* cosb   = (const float*)d_in[1];
    const float* sinb   = (const float*)d_in[2];
    const float* Wq     = (const float*)d_in[3];
    const float* Wk     = (const float*)d_in[4];
    const float* Wv     = (const float*)d_in[5];
    const float* Wo     = (const float*)d_in[6];
    const float* qw     = (const float*)d_in[7];
    const float* kw     = (const float*)d_in[8];
    float* out = (float*)d_out;

    float* qkv_ptr = nullptr;
    __half *hid_h, *wqkv_h, *wo_h, *ao_h;
    cudaGetSymbolAddress((void**)&qkv_ptr, g_qkv);
    cudaGetSymbolAddress((void**)&hid_h, g_hid_h);
    cudaGetSymbolAddress((void**)&wqkv_h, g_wqkv_h);
    cudaGetSymbolAddress((void**)&wo_h, g_wo_h);
    cudaGetSymbolAddress((void**)&ao_h, g_ao_h);

    cudaFuncSetAttribute(gemm_mma, cudaFuncAttributeMaxDynamicSharedMemorySize, GEMM_SMEM);
    cudaFuncSetAttribute(flash_mma_kernel, cudaFuncAttributeMaxDynamicSharedMemorySize, ATTN_SMEM);

    // fused conversions to fp16 (one launch)
    {
        size_t total = (size_t)SEQ * HID + (size_t)QD * HID + 2 * (size_t)KVD * HID +
                       (size_t)HID * QD;
        int nthreads4 = (int)(total / 4);
        cvt_all<<<(nthreads4 + 255) / 256, 256>>>(hidden, Wq, Wk, Wv, Wo);
    }

    // fused QKV projection: g_qkv[2048, 6144] = hidden @ [Wq|Wk|Wv]^T
    gemm_mma<<<dim3(QKVD / 128, SEQ / 128), 256, GEMM_SMEM>>>(
        hid_h, wqkv_h, qkv_ptr, HID, QKVD);

    // RMSNorm + RoPE + fp16 conversion into [h][s][d] buffers
    {
        int nwarps = SEQ * 48;
        int nblocks = (nwarps * 32 + 255) / 256;
        rms_rope_kernel<<<nblocks, 256>>>(cosb, sinb, qw, kw);
    }

    // tensor-core causal GQA flash attention -> g_ao_h
    flash_mma_kernel<<<dim3(NQH, SEQ / 128), 256, ATTN_SMEM>>>();

    // output projection: out[2048, 2560] = O @ Wo^T
    gemm_mma<<<dim3(HID / 128, SEQ / 128), 256, GEMM_SMEM>>>(
        ao_h, wo_h, out, QD, HID);
}

// round 12
// speedup vs baseline: 8.0731x; 1.0466x over previous
#include <cuda_runtime.h>
#include <cuda_fp16.h>
#include <cstdint>
#include <cstdio>

#define SEQ   2048
#define HID   2560
#define QD    4096      // 32 heads * 128
#define KVD   1024      // 8 heads * 128
#define QKVD  6144      // QD + 2*KVD
#define HD    128
#define NQH   32
#define NKVH  8

// ---------------------------------------------------------------------------
// Scratch (device globals; no allocation allowed)
// ---------------------------------------------------------------------------
__device__ float g_qkv[(size_t)SEQ * QKVD];   // [s, 6144]: Q | K | V (fp32)

// fp16 operand buffers
__device__ __half g_hid_h[(size_t)SEQ * HID];     // hidden (A of QKV gemm)
__device__ __half g_wqkv_h[(size_t)QKVD * HID];   // Wq|Wk|Wv stacked (B)
__device__ __half g_wo_h[(size_t)HID * QD];       // Wo (B)
__device__ __half g_ao_h[(size_t)SEQ * QD];       // attn out (A of Wo gemm)

// attention operands, [head][seq][128]
__device__ __half g_qh[(size_t)NQH * SEQ * HD];   // Q (scale*log2e folded)
__device__ __half g_kh[(size_t)NKVH * SEQ * HD];  // K
__device__ __half g_vh[(size_t)NKVH * SEQ * HD];  // V

// ---------------------------------------------------------------------------
// PTX helpers
// ---------------------------------------------------------------------------
__device__ __forceinline__ uint32_t smem_u32(const void* p) {
    uint32_t a;
    asm("{ .reg .u64 t; cvta.to.shared.u64 t, %1; cvt.u32.u64 %0, t; }" : "=r"(a) : "l"(p));
    return a;
}
__device__ __forceinline__ void cpa16(uint32_t s, const void* g) {
    asm volatile("cp.async.cg.shared.global [%0], [%1], 16;" :: "r"(s), "l"(g));
}
__device__ __forceinline__ void cpa_commit() {
    asm volatile("cp.async.commit_group;" ::: "memory");
}
__device__ __forceinline__ void cpa_wait1() {
    asm volatile("cp.async.wait_group 1;" ::: "memory");
}
__device__ __forceinline__ void cpa_wait0() {
    asm volatile("cp.async.wait_group 0;" ::: "memory");
}
__device__ __forceinline__ void ldm_x4(uint32_t* r, uint32_t addr) {
    asm volatile("ldmatrix.sync.aligned.m8n8.x4.shared.b16 {%0,%1,%2,%3}, [%4];"
                 : "=r"(r[0]), "=r"(r[1]), "=r"(r[2]), "=r"(r[3]) : "r"(addr));
}
__device__ __forceinline__ void ldm_x4_t(uint32_t* r, uint32_t addr) {
    asm volatile("ldmatrix.sync.aligned.m8n8.x4.trans.shared.b16 {%0,%1,%2,%3}, [%4];"
                 : "=r"(r[0]), "=r"(r[1]), "=r"(r[2]), "=r"(r[3]) : "r"(addr));
}
__device__ __forceinline__ void mma_f16(float* c, const uint32_t* a, const uint32_t* b) {
    asm volatile(
        "mma.sync.aligned.m16n8k16.row.col.f32.f16.f16.f32 "
        "{%0,%1,%2,%3}, {%4,%5,%6,%7}, {%8,%9}, {%0,%1,%2,%3};"
        : "+f"(c[0]), "+f"(c[1]), "+f"(c[2]), "+f"(c[3])
        : "r"(a[0]), "r"(a[1]), "r"(a[2]), "r"(a[3]), "r"(b[0]), "r"(b[1]));
}
__device__ __forceinline__ uint32_t ex2_h2(float a, float b) {
    __half2 t = __floats2half2_rn(a, b);
    uint32_t in = *(uint32_t*)&t, out;
    asm("ex2.approx.f16x2 %0, %1;" : "=r"(out) : "r"(in));
    return out;
}

// ---------------------------------------------------------------------------
// fused fp32 -> fp16 conversion over all 5 input regions (one launch)
// ---------------------------------------------------------------------------
__global__ __launch_bounds__(256)
void cvt_all(const float* __restrict__ hid, const float* __restrict__ wq,
             const float* __restrict__ wk, const float* __restrict__ wv,
             const float* __restrict__ wo) {
    size_t i = ((size_t)blockIdx.x * blockDim.x + threadIdx.x) * 4;
    const size_t n0 = (size_t)SEQ * HID;
    const size_t n1 = (size_t)QD * HID;
    const size_t n2 = (size_t)KVD * HID;
    const size_t n4 = (size_t)HID * QD;

    const float* src;
    __half* dst;
    if (i < n0)                { src = hid; dst = g_hid_h + i; }
    else if ((i -= n0) < n1)   { src = wq;  dst = g_wqkv_h + i; }
    else if ((i -= n1) < n2)   { src = wk;  dst = g_wqkv_h + n1 + i; }
    else if ((i -= n2) < n2)   { src = wv;  dst = g_wqkv_h + n1 + n2 + i; }
    else if ((i -= n2) < n4)   { src = wo;  dst = g_wo_h + i; }
    else return;

    float4 x = *(const float4*)(src + i);
    *(__half2*)(dst)     = __floats2half2_rn(x.x, x.y);
    *(__half2*)(dst + 2) = __floats2half2_rn(x.z, x.w);
}

// ---------------------------------------------------------------------------
// mma.sync fp16 GEMM (NT): C[m,n] = sum_k A[m,k]*B[n,k], fp32 accum.
// CTA 128x128, BK=64, 8 warps (4x2), warp tile 32x64. Double-buffered.
// ---------------------------------------------------------------------------
#define BK 64
#define LDS_STR 72                    // 64 halves + 8 pad (144B stride, conflict-free)
#define TILE_H (128 * LDS_STR)
#define STAGE_H (2 * TILE_H)          // A | B
#define GEMM_SMEM (2 * STAGE_H * 2)   // 73728 B

__global__ __launch_bounds__(256, 2)
void gemm_mma(const __half* __restrict__ Ah, const __half* __restrict__ Bh,
              float* __restrict__ C, int K, int ldc) {
    extern __shared__ __half smem[];
    const uint32_t sbase = smem_u32(smem);

    const int tid  = threadIdx.x;
    const int warp = tid >> 5;
    const int lane = tid & 31;
    const int wm   = warp & 3;
    const int wn   = warp >> 2;
    const int bx = blockIdx.x, by = blockIdx.y;

    const __half* gA = Ah + (size_t)(by * 128) * K;
    const __half* gB = Bh + (size_t)(bx * 128) * K;

    float acc[2][8][4];
    #pragma unroll
    for (int i = 0; i < 2; i++)
        #pragma unroll
        for (int j = 0; j < 8; j++)
            #pragma unroll
            for (int t = 0; t < 4; t++) acc[i][j][t] = 0.0f;

    const int nchunk = K / BK;
    const int r0 = tid >> 2;
    const int ch0 = (tid & 3) * 8;

    auto load_stage = [&](int c, int s) {
        const size_t koff = (size_t)c * BK;
        uint32_t dst = sbase + (uint32_t)(s * STAGE_H) * 2;
        {
            const __half* a0 = gA + (size_t)r0 * K + koff;
            const __half* a1 = gA + (size_t)(r0 + 64) * K + koff;
            cpa16(dst + (r0 * LDS_STR + ch0) * 2,              a0 + ch0);
            cpa16(dst + (r0 * LDS_STR + ch0 + 32) * 2,         a0 + ch0 + 32);
            cpa16(dst + ((r0 + 64) * LDS_STR + ch0) * 2,       a1 + ch0);
            cpa16(dst + ((r0 + 64) * LDS_STR + ch0 + 32) * 2,  a1 + ch0 + 32);
        }
        {
            uint32_t d = dst + (uint32_t)TILE_H * 2;
            const __half* b0 = gB + (size_t)r0 * K + koff;
            const __half* b1 = gB + (size_t)(r0 + 64) * K + koff;
            cpa16(d + (r0 * LDS_STR + ch0) * 2,              b0 + ch0);
            cpa16(d + (r0 * LDS_STR + ch0 + 32) * 2,         b0 + ch0 + 32);
            cpa16(d + ((r0 + 64) * LDS_STR + ch0) * 2,       b1 + ch0);
            cpa16(d + ((r0 + 64) * LDS_STR + ch0 + 32) * 2,  b1 + ch0 + 32);
        }
    };

    const int a_row = (lane & 7) + ((lane >> 3) & 1) * 8;
    const int a_kof = (lane >> 4) * 8;
    const int b_mat = lane >> 3;
    const int b_row = lane & 7;
    const int b_kof = (b_mat & 1) * 8;
    const int b_jof = (b_mat >> 1);

    load_stage(0, 0);
    cpa_commit();

    for (int c = 0; c < nchunk; c++) {
        if (c + 1 < nchunk) {
            load_stage(c + 1, (c + 1) & 1);
            cpa_commit();
            cpa_wait1();
        } else {
            cpa_wait0();
        }
        __syncthreads();

        const uint32_t st = sbase + (uint32_t)((c & 1) * STAGE_H) * 2;
        const uint32_t sA = st;
        const uint32_t sB = st + (uint32_t)TILE_H * 2;

        #pragma unroll
        for (int ks = 0; ks < 4; ks++) {
            uint32_t ah[2][4];
            #pragma unroll
            for (int i = 0; i < 2; i++) {
                int m_local = wm * 32 + i * 16 + a_row;
                int k = ks * 16 + a_kof;
                uint32_t off = (uint32_t)(m_local * LDS_STR + k) * 2;
                ldm_x4(ah[i], sA + off);
            }
            #pragma unroll
            for (int jp = 0; jp < 4; jp++) {
                int n_local = wn * 64 + (jp * 2 + b_jof) * 8 + b_row;
                int k = ks * 16 + b_kof;
                uint32_t off = (uint32_t)(n_local * LDS_STR + k) * 2;
                uint32_t rh[4];
                ldm_x4(rh, sB + off);
                const int j0 = jp * 2, j1 = jp * 2 + 1;
                mma_f16(acc[0][j0], ah[0], rh);   mma_f16(acc[0][j1], ah[0], rh + 2);
                mma_f16(acc[1][j0], ah[1], rh);   mma_f16(acc[1][j1], ah[1], rh + 2);
            }
        }
        __syncthreads();
    }

    const int gid = lane >> 2;
    const int tgc = (lane & 3) * 2;
    #pragma unroll
    for (int i = 0; i < 2; i++) {
        int row = by * 128 + wm * 32 + i * 16 + gid;
        #pragma unroll
        for (int j = 0; j < 8; j++) {
            int col = bx * 128 + wn * 64 + j * 8 + tgc;
            float2 v0 = {acc[i][j][0], acc[i][j][1]};
            float2 v1 = {acc[i][j][2], acc[i][j][3]};
            *(float2*)(C + (size_t)row * ldc + col)       = v0;
            *(float2*)(C + (size_t)(row + 8) * ldc + col) = v1;
        }
    }
}

// ---------------------------------------------------------------------------
// RMSNorm + RoPE, fp32 g_qkv -> fp16 buffers, [h][s][d] layout.
// Q heads: norm+rope, scale = (1/sqrt(128))*log2(e) folded, single fp16.
// K heads: norm+rope. V heads: plain convert.
// ---------------------------------------------------------------------------
__global__ __launch_bounds__(256)
void rms_rope_kernel(const float* __restrict__ cosb, const float* __restrict__ sinb,
                     const float* __restrict__ qw, const float* __restrict__ kw) {
    int gw = (blockIdx.x * blockDim.x + threadIdx.x) >> 5;
    int lane = threadIdx.x & 31;
    if (gw >= SEQ * 48) return;
    int s = gw / 48;
    int h = gw % 48;
    int d = lane * 4;

    float4 out;
    __half* dsingle;

    if (h < 40) {
        const float* base;
        const float* w;
        if (h < NQH) {
            base = g_qkv + (size_t)s * QKVD + h * HD;
            w = qw;
            dsingle = g_qh + ((size_t)h * SEQ + s) * HD;
        } else {
            int kh = h - NQH;
            base = g_qkv + (size_t)s * QKVD + QD + kh * HD;
            w = kw;
            dsingle = g_kh + ((size_t)kh * SEQ + s) * HD;
        }
        float4 x = *(const float4*)(base + d);
        float ss = x.x * x.x + x.y * x.y + x.z * x.z + x.w * x.w;
        #pragma unroll
        for (int o = 16; o > 0; o >>= 1) ss += __shfl_xor_sync(0xffffffffu, ss, o);
        float r = rsqrtf(ss * (1.0f / 128.0f) + 1e-6f);

        float4 wv = *(const float4*)(w + d);
        float4 xn;
        xn.x = x.x * r * wv.x; xn.y = x.y * r * wv.y;
        xn.z = x.z * r * wv.z; xn.w = x.w * r * wv.w;

        float4 ot;
        ot.x = __shfl_xor_sync(0xffffffffu, xn.x, 16);
        ot.y = __shfl_xor_sync(0xffffffffu, xn.y, 16);
        ot.z = __shfl_xor_sync(0xffffffffu, xn.z, 16);
        ot.w = __shfl_xor_sync(0xffffffffu, xn.w, 16);
        float sgn = (d < 64) ? -1.0f : 1.0f;

        float4 c = *(const float4*)(cosb + (size_t)s * HD + d);
        float4 si = *(const float4*)(sinb + (size_t)s * HD + d);
        out.x = xn.x * c.x + sgn * ot.x * si.x;
        out.y = xn.y * c.y + sgn * ot.y * si.y;
        out.z = xn.z * c.z + sgn * ot.z * si.z;
        out.w = xn.w * c.w + sgn * ot.w * si.w;
        if (h < NQH) {
            // fold softmax scale AND log2(e): S ends up in log2 domain
            const float sc = 0.12751743f;   // (1/sqrt(128)) * log2(e)
            out.x *= sc; out.y *= sc; out.z *= sc; out.w *= sc;
        }
    } else {
        int vh = h - 40;
        const float* base = g_qkv + (size_t)s * QKVD + QD + KVD + vh * HD;
        out = *(const float4*)(base + d);
        dsingle = g_vh + ((size_t)vh * SEQ + s) * HD;
    }

    *(__half2*)(dsingle + d)     = __floats2half2_rn(out.x, out.y);
    *(__half2*)(dsingle + d + 2) = __floats2half2_rn(out.z, out.w);
}

// ---------------------------------------------------------------------------
// Tensor-core flash attention, causal, GQA. log2-domain softmax (ex2.f16x2).
// CTA = (head, 128-row q tile), 8 warps. Single-term S (Q fp16) and P*V.
// KV tiles (64 rows) in a 3-stage cp.async pipeline (2-deep prefetch).
// Tile order reversed (longest first) to kill the causal-imbalance tail.
// ---------------------------------------------------------------------------
#define ASTR 136                   // halves per smem row
#define AKV  (64 * ASTR)           // halves per KV matrix
#define AQ   (128 * ASTR)          // halves per Q matrix
#define ATTN_SMEM ((AQ + 6 * AKV) * 2)   // 139264 B

__global__ __launch_bounds__(256, 1)
void flash_mma_kernel() {
    extern __shared__ __half asm_smem[];
    const uint32_t sb = smem_u32(asm_smem);
    const uint32_t sQ = sb;
    const uint32_t kvb = sQ + AQ * 2;
    const uint32_t sK[3] = { kvb, kvb + 2 * AKV * 2, kvb + 4 * AKV * 2 };
    const uint32_t sV[3] = { kvb + AKV * 2, kvb + 3 * AKV * 2, kvb + 5 * AKV * 2 };

    const int h  = blockIdx.x;
    const int qt = gridDim.y - 1 - blockIdx.y;   // longest tiles first
    const int q0 = qt * 128;
    const int kh = h >> 2;
    const int tid = threadIdx.x;
    const int warp = tid >> 5;
    const int lane = tid & 31;
    const int gid = lane >> 2;
    const int tig = lane & 3;

    const __half* bkh = g_kh + (size_t)kh * SEQ * HD;
    const __half* bvh = g_vh + (size_t)kh * SEQ * HD;

    auto load_kv = [&](int it, int buf) {
        const __half* pk = bkh + (size_t)(it * 64) * HD;
        const __half* pv = bvh + (size_t)(it * 64) * HD;
        #pragma unroll
        for (int i = 0; i < 4; i++) {
            int ch = tid + i * 256;            // 1024 chunks: 64 rows x 16
            int row = ch >> 4, c = ch & 15;
            uint32_t off = (uint32_t)(row * ASTR) * 2 + c * 16;
            size_t goff = (size_t)row * HD + c * 8;
            cpa16(sK[buf] + off, pk + goff);
            cpa16(sV[buf] + off, pv + goff);
        }
    };

    const int nit = 2 * qt + 1;              // KV tiles 0..nit

    // prologue: {Q + KV0} commit, {KV1} commit  (nit >= 1 always)
    {
        const __half* gq = g_qh + ((size_t)h * SEQ + q0) * HD;
        #pragma unroll
        for (int i = 0; i < 8; i++) {
            int ch = tid + i * 256;            // 2048 chunks: 128 rows x 16
            int row = ch >> 4, c = ch & 15;
            uint32_t off = (uint32_t)(row * ASTR) * 2 + c * 16;
            cpa16(sQ + off, gq + (size_t)row * HD + c * 8);
        }
        load_kv(0, 0);
        cpa_commit();
        load_kv(1, 1);
        cpa_commit();
    }

    float oacc[16][4];
    #pragma unroll
    for (int j = 0; j < 16; j++)
        #pragma unroll
        for (int t = 0; t < 4; t++) oacc[j][t] = 0.0f;
    float mrow[2] = {-1e30f, -1e30f};
    float lrow[2] = {0.0f, 0.0f};

    const uint32_t qoff_row = (uint32_t)((warp * 16 + (lane & 15)) * ASTR) * 2;
    const uint32_t qoff_col = (uint32_t)((lane >> 4) * 8) * 2;
    const uint32_t koff_rowbase = (uint32_t)((lane & 7) * ASTR) * 2;
    const uint32_t koff_col = (uint32_t)(((lane >> 3) & 3) * 8) * 2;
    const uint32_t voff_rowbase = (uint32_t)(((lane & 7) + 8 * ((lane >> 3) & 1)) * ASTR) * 2;
    const uint32_t voff_col = (uint32_t)((lane >> 4) * 8) * 2;

    for (int it = 0; it <= nit; it++) {
        const int cur = it % 3;
        cpa_wait1();                 // tile `it` resident (only it+1 may be pending)
        __syncthreads();
        if (it + 1 < nit) {          // prefetch tile it+2 into buffer (it+2)%3
            load_kv(it + 2, (it + 2) % 3);
            cpa_commit();
        }
        // upper-half warps are fully masked in the last diagonal tile
        const bool active = !(it == nit && warp < 4);
        if (active) {
            const uint32_t sKc = sK[cur];
            const uint32_t sVc = sV[cur];

            // ---- S = Q K^T (log2 domain) ----
            float sacc[8][4];
            #pragma unroll
            for (int j = 0; j < 8; j++)
                #pragma unroll
                for (int t = 0; t < 4; t++) sacc[j][t] = 0.0f;

            #pragma unroll
            for (int ks2 = 0; ks2 < 4; ks2++) {
                uint32_t qf[2][4];
                #pragma unroll
                for (int e = 0; e < 2; e++) {
                    uint32_t off = qoff_row + ((uint32_t)((ks2 * 2 + e) * 16) * 2 + qoff_col);
                    ldm_x4(qf[e], sQ + off);
                }
                #pragma unroll
                for (int jn2 = 0; jn2 < 4; jn2++) {
                    const int jA = jn2 * 2, jB = jn2 * 2 + 1;
                    const uint32_t kcom = koff_rowbase + (uint32_t)(ks2 * 32) * 2 + koff_col;
                    uint32_t offA = (uint32_t)(jA * 8 * ASTR) * 2 + kcom;
                    uint32_t offB = (uint32_t)(jB * 8 * ASTR) * 2 + kcom;
                    uint32_t khA[4], khB[4];
                    ldm_x4(khA, sKc + offA); ldm_x4(khB, sKc + offB);
                    mma_f16(sacc[jA], qf[0], khA);     mma_f16(sacc[jB], qf[0], khB);
                    mma_f16(sacc[jA], qf[1], khA + 2); mma_f16(sacc[jB], qf[1], khB + 2);
                }
            }

            // ---- causal mask (last two KV tiles overlap the diagonal) ----
            if (it >= 2 * qt) {
                int qg0 = q0 + warp * 16 + gid;
                #pragma unroll
                for (int jn = 0; jn < 8; jn++) {
                    int kg = it * 64 + jn * 8 + tig * 2;
                    if (kg > qg0)     sacc[jn][0] = -1e30f;
                    if (kg + 1 > qg0) sacc[jn][1] = -1e30f;
                    if (kg > qg0 + 8)     sacc[jn][2] = -1e30f;
                    if (kg + 1 > qg0 + 8) sacc[jn][3] = -1e30f;
                }
            }

            // ---- online softmax (log2 domain, fp16x2 ex2) ----
            float mn0 = mrow[0], mn1 = mrow[1];
            #pragma unroll
            for (int jn = 0; jn < 8; jn++) {
                mn0 = fmaxf(mn0, fmaxf(sacc[jn][0], sacc[jn][1]));
                mn1 = fmaxf(mn1, fmaxf(sacc[jn][2], sacc[jn][3]));
            }
            mn0 = fmaxf(mn0, __shfl_xor_sync(0xffffffffu, mn0, 1));
            mn0 = fmaxf(mn0, __shfl_xor_sync(0xffffffffu, mn0, 2));
            mn1 = fmaxf(mn1, __shfl_xor_sync(0xffffffffu, mn1, 1));
            mn1 = fmaxf(mn1, __shfl_xor_sync(0xffffffffu, mn1, 2));
            float al0 = exp2f(mrow[0] - mn0);
            float al1 = exp2f(mrow[1] - mn1);
            mrow[0] = mn0; mrow[1] = mn1;
            lrow[0] *= al0; lrow[1] *= al1;

            uint32_t ph[8][2];
            float lacc0 = 0.0f, lacc1 = 0.0f;
            #pragma unroll
            for (int jn = 0; jn < 8; jn++) {
                uint32_t p0 = ex2_h2(sacc[jn][0] - mn0, sacc[jn][1] - mn0);
                uint32_t p1 = ex2_h2(sacc[jn][2] - mn1, sacc[jn][3] - mn1);
                ph[jn][0] = p0;
                ph[jn][1] = p1;
                float2 f0 = __half22float2(*(__half2*)&p0);
                float2 f1 = __half22float2(*(__half2*)&p1);
                lacc0 += f0.x + f0.y;
                lacc1 += f1.x + f1.y;
            }
            lrow[0] += lacc0;
            lrow[1] += lacc1;

            #pragma unroll
            for (int jd = 0; jd < 16; jd++) {
                oacc[jd][0] *= al0; oacc[jd][1] *= al0;
                oacc[jd][2] *= al1; oacc[jd][3] *= al1;
            }

            // ---- O += P V ----
            #pragma unroll
            for (int kks = 0; kks < 4; kks++) {
                uint32_t aPh[4] = {ph[2 * kks][0], ph[2 * kks][1],
                                   ph[2 * kks + 1][0], ph[2 * kks + 1][1]};
                #pragma unroll
                for (int jd2 = 0; jd2 < 8; jd2++) {
                    uint32_t off = (uint32_t)(kks * 16 * ASTR) * 2 + voff_rowbase +
                                   (uint32_t)(jd2 * 16) * 2 + voff_col;
                    uint32_t vh4[4];
                    ldm_x4_t(vh4, sVc + off);
                    mma_f16(oacc[jd2 * 2], aPh, vh4);
                    mma_f16(oacc[jd2 * 2 + 1], aPh, vh4 + 2);
                }
            }
        }
    }

    // final: reduce l across quad, normalize, write fp16
    lrow[0] += __shfl_xor_sync(0xffffffffu, lrow[0], 1);
    lrow[0] += __shfl_xor_sync(0xffffffffu, lrow[0], 2);
    lrow[1] += __shfl_xor_sync(0xffffffffu, lrow[1], 1);
    lrow[1] += __shfl_xor_sync(0xffffffffu, lrow[1], 2);
    float inv0 = 1.0f / lrow[0];
    float inv1 = 1.0f / lrow[1];

    int row0 = q0 + warp * 16 + gid;
    #pragma unroll
    for (int jd = 0; jd < 16; jd++) {
        int col = h * HD + jd * 8 + tig * 2;
        __half2 h0 = __floats2half2_rn(oacc[jd][0] * inv0, oacc[jd][1] * inv0);
        __half2 h1 = __floats2half2_rn(oacc[jd][2] * inv1, oacc[jd][3] * inv1);
        *(__half2*)(g_ao_h + (size_t)row0 * QD + col)       = h0;
        *(__half2*)(g_ao_h + (size_t)(row0 + 8) * QD + col) = h1;
    }
}

// ---------------------------------------------------------------------------
// launch
// ---------------------------------------------------------------------------
extern "C" void kernel_launch(void* const* d_in, const int* in_sizes, int n_in,
                              void* d_out, int out_size) {
    const float* hidden = (const float*)d_in[0];
    const float* cosb   = (const float*)d_in[1];
    const float* sinb   = (const float*)d_in[2];
    const float* Wq     = (const float*)d_in[3];
    const float* Wk     = (const float*)d_in[4];
    const float* Wv     = (const float*)d_in[5];
    const float* Wo     = (const float*)d_in[6];
    const float* qw     = (const float*)d_in[7];
    const float* kw     = (const float*)d_in[8];
    float* out = (float*)d_out;

    float* qkv_ptr = nullptr;
    __half *hid_h, *wqkv_h, *wo_h, *ao_h;
    cudaGetSymbolAddress((void**)&qkv_ptr, g_qkv);
    cudaGetSymbolAddress((void**)&hid_h, g_hid_h);
    cudaGetSymbolAddress((void**)&wqkv_h, g_wqkv_h);
    cudaGetSymbolAddress((void**)&wo_h, g_wo_h);
    cudaGetSymbolAddress((void**)&ao_h, g_ao_h);

    cudaFuncSetAttribute(gemm_mma, cudaFuncAttributeMaxDynamicSharedMemorySize, GEMM_SMEM);
    cudaFuncSetAttribute(flash_mma_kernel, cudaFuncAttributeMaxDynamicSharedMemorySize, ATTN_SMEM);

    // fused conversions to fp16 (one launch)
    {
        size_t total = (size_t)SEQ * HID + (size_t)QD * HID + 2 * (size_t)KVD * HID +
                       (size_t)HID * QD;
        int nthreads4 = (int)(total / 4);
        cvt_all<<<(nthreads4 + 255) / 256, 256>>>(hidden, Wq, Wk, Wv, Wo);
    }

    // fused QKV projection: g_qkv[2048, 6144] = hidden @ [Wq|Wk|Wv]^T
    gemm_mma<<<dim3(QKVD / 128, SEQ / 128), 256, GEMM_SMEM>>>(
        hid_h, wqkv_h, qkv_ptr, HID, QKVD);

    // RMSNorm + RoPE + fp16 conversion into [h][s][d] buffers
    {
        int nwarps = SEQ * 48;
        int nblocks = (nwarps * 32 + 255) / 256;
        rms_rope_kernel<<<nblocks, 256>>>(cosb, sinb, qw, kw);
    }

    // tensor-core causal GQA flash attention -> g_ao_h
    flash_mma_kernel<<<dim3(NQH, SEQ / 128), 256, ATTN_SMEM>>>();

    // output projection: out[2048, 2560] = O @ Wo^T
    gemm_mma<<<dim3(HID / 128, SEQ / 128), 256, GEMM_SMEM>>>(
        ao_h, wo_h, out, QD, HID);
}

// round 13
// speedup vs baseline: 8.1871x; 1.0141x over previous
#include <cuda_runtime.h>
#include <cuda_fp16.h>
#include <cstdint>
#include <cstdio>

#define SEQ   2048
#define HID   2560
#define QD    4096      // 32 heads * 128
#define KVD   1024      // 8 heads * 128
#define QKVD  6144      // QD + 2*KVD
#define HD    128
#define NQH   32
#define NKVH  8

// ---------------------------------------------------------------------------
// Scratch (device globals; no allocation allowed)
// ---------------------------------------------------------------------------
__device__ float g_qkv[(size_t)SEQ * QKVD];   // [s, 6144]: Q | K | V (fp32)

// fp16 operand buffers
__device__ __half g_hid_h[(size_t)SEQ * HID];     // hidden (A of QKV gemm)
__device__ __half g_wqkv_h[(size_t)QKVD * HID];   // Wq|Wk|Wv stacked (B)
__device__ __half g_wo_h[(size_t)HID * QD];       // Wo (B)
__device__ __half g_ao_h[(size_t)SEQ * QD];       // attn out (A of Wo gemm)

// attention operands, [head][seq][128]
__device__ __half g_qh[(size_t)NQH * SEQ * HD];   // Q (scale*log2e folded)
__device__ __half g_kh[(size_t)NKVH * SEQ * HD];  // K
__device__ __half g_vh[(size_t)NKVH * SEQ * HD];  // V

// ---------------------------------------------------------------------------
// PTX helpers
// ---------------------------------------------------------------------------
__device__ __forceinline__ uint32_t smem_u32(const void* p) {
    uint32_t a;
    asm("{ .reg .u64 t; cvta.to.shared.u64 t, %1; cvt.u32.u64 %0, t; }" : "=r"(a) : "l"(p));
    return a;
}
__device__ __forceinline__ void cpa16(uint32_t s, const void* g) {
    asm volatile("cp.async.cg.shared.global [%0], [%1], 16;" :: "r"(s), "l"(g));
}
__device__ __forceinline__ void cpa_commit() {
    asm volatile("cp.async.commit_group;" ::: "memory");
}
__device__ __forceinline__ void cpa_wait1() {
    asm volatile("cp.async.wait_group 1;" ::: "memory");
}
__device__ __forceinline__ void cpa_wait0() {
    asm volatile("cp.async.wait_group 0;" ::: "memory");
}
__device__ __forceinline__ void ldm_x4(uint32_t* r, uint32_t addr) {
    asm volatile("ldmatrix.sync.aligned.m8n8.x4.shared.b16 {%0,%1,%2,%3}, [%4];"
                 : "=r"(r[0]), "=r"(r[1]), "=r"(r[2]), "=r"(r[3]) : "r"(addr));
}
__device__ __forceinline__ void ldm_x4_t(uint32_t* r, uint32_t addr) {
    asm volatile("ldmatrix.sync.aligned.m8n8.x4.trans.shared.b16 {%0,%1,%2,%3}, [%4];"
                 : "=r"(r[0]), "=r"(r[1]), "=r"(r[2]), "=r"(r[3]) : "r"(addr));
}
__device__ __forceinline__ void mma_f16(float* c, const uint32_t* a, const uint32_t* b) {
    asm volatile(
        "mma.sync.aligned.m16n8k16.row.col.f32.f16.f16.f32 "
        "{%0,%1,%2,%3}, {%4,%5,%6,%7}, {%8,%9}, {%0,%1,%2,%3};"
        : "+f"(c[0]), "+f"(c[1]), "+f"(c[2]), "+f"(c[3])
        : "r"(a[0]), "r"(a[1]), "r"(a[2]), "r"(a[3]), "r"(b[0]), "r"(b[1]));
}
__device__ __forceinline__ uint32_t ex2_h2(float a, float b) {
    __half2 t = __floats2half2_rn(a, b);
    uint32_t in = *(uint32_t*)&t, out;
    asm("ex2.approx.f16x2 %0, %1;" : "=r"(out) : "r"(in));
    return out;
}

// ---------------------------------------------------------------------------
// fused fp32 -> fp16 conversion over all 5 input regions (one launch)
// ---------------------------------------------------------------------------
__global__ __launch_bounds__(256)
void cvt_all(const float* __restrict__ hid, const float* __restrict__ wq,
             const float* __restrict__ wk, const float* __restrict__ wv,
             const float* __restrict__ wo) {
    size_t i = ((size_t)blockIdx.x * blockDim.x + threadIdx.x) * 4;
    const size_t n0 = (size_t)SEQ * HID;
    const size_t n1 = (size_t)QD * HID;
    const size_t n2 = (size_t)KVD * HID;
    const size_t n4 = (size_t)HID * QD;

    const float* src;
    __half* dst;
    if (i < n0)                { src = hid; dst = g_hid_h + i; }
    else if ((i -= n0) < n1)   { src = wq;  dst = g_wqkv_h + i; }
    else if ((i -= n1) < n2)   { src = wk;  dst = g_wqkv_h + n1 + i; }
    else if ((i -= n2) < n2)   { src = wv;  dst = g_wqkv_h + n1 + n2 + i; }
    else if ((i -= n2) < n4)   { src = wo;  dst = g_wo_h + i; }
    else return;

    float4 x = *(const float4*)(src + i);
    *(__half2*)(dst)     = __floats2half2_rn(x.x, x.y);
    *(__half2*)(dst + 2) = __floats2half2_rn(x.z, x.w);
}

// ---------------------------------------------------------------------------
// mma.sync fp16 GEMM (NT): C[m,n] = sum_k A[m,k]*B[n,k], fp32 accum.
// CTA 128x128, BK=64, 8 warps (4x2), warp tile 32x64.
// 3-stage cp.async ring, ONE barrier per chunk, 2-chunk prefetch depth.
// ---------------------------------------------------------------------------
#define BK 64
#define LDS_STR 72                    // 64 halves + 8 pad (144B stride, conflict-free)
#define TILE_H (128 * LDS_STR)
#define STAGE_H (2 * TILE_H)          // A | B
#define GEMM_SMEM (3 * STAGE_H * 2)   // 110592 B (3 stages)

__global__ __launch_bounds__(256, 2)
void gemm_mma(const __half* __restrict__ Ah, const __half* __restrict__ Bh,
              float* __restrict__ C, int K, int ldc) {
    extern __shared__ __half smem[];
    const uint32_t sbase = smem_u32(smem);

    const int tid  = threadIdx.x;
    const int warp = tid >> 5;
    const int lane = tid & 31;
    const int wm   = warp & 3;
    const int wn   = warp >> 2;
    const int bx = blockIdx.x, by = blockIdx.y;

    const __half* gA = Ah + (size_t)(by * 128) * K;
    const __half* gB = Bh + (size_t)(bx * 128) * K;

    float acc[2][8][4];
    #pragma unroll
    for (int i = 0; i < 2; i++)
        #pragma unroll
        for (int j = 0; j < 8; j++)
            #pragma unroll
            for (int t = 0; t < 4; t++) acc[i][j][t] = 0.0f;

    const int nchunk = K / BK;
    const int r0 = tid >> 2;
    const int ch0 = (tid & 3) * 8;

    auto load_stage = [&](int c, int s) {
        const size_t koff = (size_t)c * BK;
        uint32_t dst = sbase + (uint32_t)(s * STAGE_H) * 2;
        {
            const __half* a0 = gA + (size_t)r0 * K + koff;
            const __half* a1 = gA + (size_t)(r0 + 64) * K + koff;
            cpa16(dst + (r0 * LDS_STR + ch0) * 2,              a0 + ch0);
            cpa16(dst + (r0 * LDS_STR + ch0 + 32) * 2,         a0 + ch0 + 32);
            cpa16(dst + ((r0 + 64) * LDS_STR + ch0) * 2,       a1 + ch0);
            cpa16(dst + ((r0 + 64) * LDS_STR + ch0 + 32) * 2,  a1 + ch0 + 32);
        }
        {
            uint32_t d = dst + (uint32_t)TILE_H * 2;
            const __half* b0 = gB + (size_t)r0 * K + koff;
            const __half* b1 = gB + (size_t)(r0 + 64) * K + koff;
            cpa16(d + (r0 * LDS_STR + ch0) * 2,              b0 + ch0);
            cpa16(d + (r0 * LDS_STR + ch0 + 32) * 2,         b0 + ch0 + 32);
            cpa16(d + ((r0 + 64) * LDS_STR + ch0) * 2,       b1 + ch0);
            cpa16(d + ((r0 + 64) * LDS_STR + ch0 + 32) * 2,  b1 + ch0 + 32);
        }
    };

    const int a_row = (lane & 7) + ((lane >> 3) & 1) * 8;
    const int a_kof = (lane >> 4) * 8;
    const int b_mat = lane >> 3;
    const int b_row = lane & 7;
    const int b_kof = (b_mat & 1) * 8;
    const int b_jof = (b_mat >> 1);

    // prologue: 2-deep prefetch
    load_stage(0, 0);
    cpa_commit();
    load_stage(1, 1);
    cpa_commit();

    int stage = 0;
    for (int c = 0; c < nchunk; c++) {
        if (c == nchunk - 1) cpa_wait0(); else cpa_wait1();
        __syncthreads();               // all warps done with chunk c-1, chunk c resident
        if (c + 2 < nchunk) {          // prefetch chunk c+2 into ring slot (c+2)%3
            int s2 = stage + 2; if (s2 >= 3) s2 -= 3;
            load_stage(c + 2, s2);
            cpa_commit();
        }

        const uint32_t st = sbase + (uint32_t)(stage * STAGE_H) * 2;
        const uint32_t sA = st;
        const uint32_t sB = st + (uint32_t)TILE_H * 2;

        #pragma unroll
        for (int ks = 0; ks < 4; ks++) {
            uint32_t ah[2][4];
            #pragma unroll
            for (int i = 0; i < 2; i++) {
                int m_local = wm * 32 + i * 16 + a_row;
                int k = ks * 16 + a_kof;
                uint32_t off = (uint32_t)(m_local * LDS_STR + k) * 2;
                ldm_x4(ah[i], sA + off);
            }
            #pragma unroll
            for (int jp = 0; jp < 4; jp++) {
                int n_local = wn * 64 + (jp * 2 + b_jof) * 8 + b_row;
                int k = ks * 16 + b_kof;
                uint32_t off = (uint32_t)(n_local * LDS_STR + k) * 2;
                uint32_t rh[4];
                ldm_x4(rh, sB + off);
                const int j0 = jp * 2, j1 = jp * 2 + 1;
                mma_f16(acc[0][j0], ah[0], rh);   mma_f16(acc[0][j1], ah[0], rh + 2);
                mma_f16(acc[1][j0], ah[1], rh);   mma_f16(acc[1][j1], ah[1], rh + 2);
            }
        }
        if (++stage == 3) stage = 0;
    }

    const int gid = lane >> 2;
    const int tgc = (lane & 3) * 2;
    #pragma unroll
    for (int i = 0; i < 2; i++) {
        int row = by * 128 + wm * 32 + i * 16 + gid;
        #pragma unroll
        for (int j = 0; j < 8; j++) {
            int col = bx * 128 + wn * 64 + j * 8 + tgc;
            float2 v0 = {acc[i][j][0], acc[i][j][1]};
            float2 v1 = {acc[i][j][2], acc[i][j][3]};
            *(float2*)(C + (size_t)row * ldc + col)       = v0;
            *(float2*)(C + (size_t)(row + 8) * ldc + col) = v1;
        }
    }
}

// ---------------------------------------------------------------------------
// RMSNorm + RoPE, fp32 g_qkv -> fp16 buffers, [h][s][d] layout.
// Q heads: norm+rope, scale = (1/sqrt(128))*log2(e) folded, single fp16.
// K heads: norm+rope. V heads: plain convert.
// ---------------------------------------------------------------------------
__global__ __launch_bounds__(256)
void rms_rope_kernel(const float* __restrict__ cosb, const float* __restrict__ sinb,
                     const float* __restrict__ qw, const float* __restrict__ kw) {
    int gw = (blockIdx.x * blockDim.x + threadIdx.x) >> 5;
    int lane = threadIdx.x & 31;
    if (gw >= SEQ * 48) return;
    int s = gw / 48;
    int h = gw % 48;
    int d = lane * 4;

    float4 out;
    __half* dsingle;

    if (h < 40) {
        const float* base;
        const float* w;
        if (h < NQH) {
            base = g_qkv + (size_t)s * QKVD + h * HD;
            w = qw;
            dsingle = g_qh + ((size_t)h * SEQ + s) * HD;
        } else {
            int kh = h - NQH;
            base = g_qkv + (size_t)s * QKVD + QD + kh * HD;
            w = kw;
            dsingle = g_kh + ((size_t)kh * SEQ + s) * HD;
        }
        float4 x = *(const float4*)(base + d);
        float ss = x.x * x.x + x.y * x.y + x.z * x.z + x.w * x.w;
        #pragma unroll
        for (int o = 16; o > 0; o >>= 1) ss += __shfl_xor_sync(0xffffffffu, ss, o);
        float r = rsqrtf(ss * (1.0f / 128.0f) + 1e-6f);

        float4 wv = *(const float4*)(w + d);
        float4 xn;
        xn.x = x.x * r * wv.x; xn.y = x.y * r * wv.y;
        xn.z = x.z * r * wv.z; xn.w = x.w * r * wv.w;

        float4 ot;
        ot.x = __shfl_xor_sync(0xffffffffu, xn.x, 16);
        ot.y = __shfl_xor_sync(0xffffffffu, xn.y, 16);
        ot.z = __shfl_xor_sync(0xffffffffu, xn.z, 16);
        ot.w = __shfl_xor_sync(0xffffffffu, xn.w, 16);
        float sgn = (d < 64) ? -1.0f : 1.0f;

        float4 c = *(const float4*)(cosb + (size_t)s * HD + d);
        float4 si = *(const float4*)(sinb + (size_t)s * HD + d);
        out.x = xn.x * c.x + sgn * ot.x * si.x;
        out.y = xn.y * c.y + sgn * ot.y * si.y;
        out.z = xn.z * c.z + sgn * ot.z * si.z;
        out.w = xn.w * c.w + sgn * ot.w * si.w;
        if (h < NQH) {
            // fold softmax scale AND log2(e): S ends up in log2 domain
            const float sc = 0.12751743f;   // (1/sqrt(128)) * log2(e)
            out.x *= sc; out.y *= sc; out.z *= sc; out.w *= sc;
        }
    } else {
        int vh = h - 40;
        const float* base = g_qkv + (size_t)s * QKVD + QD + KVD + vh * HD;
        out = *(const float4*)(base + d);
        dsingle = g_vh + ((size_t)vh * SEQ + s) * HD;
    }

    *(__half2*)(dsingle + d)     = __floats2half2_rn(out.x, out.y);
    *(__half2*)(dsingle + d + 2) = __floats2half2_rn(out.z, out.w);
}

// ---------------------------------------------------------------------------
// Tensor-core flash attention, causal, GQA. log2-domain softmax (ex2.f16x2).
// CTA = (head, 128-row q tile), 8 warps. Single-term S (Q fp16) and P*V.
// KV tiles (64 rows) in a 3-stage cp.async pipeline (2-deep prefetch).
// Tile order reversed (longest first) to kill the causal-imbalance tail.
// ---------------------------------------------------------------------------
#define ASTR 136                   // halves per smem row
#define AKV  (64 * ASTR)           // halves per KV matrix
#define AQ   (128 * ASTR)          // halves per Q matrix
#define ATTN_SMEM ((AQ + 6 * AKV) * 2)   // 139264 B

__global__ __launch_bounds__(256, 1)
void flash_mma_kernel() {
    extern __shared__ __half asm_smem[];
    const uint32_t sb = smem_u32(asm_smem);
    const uint32_t sQ = sb;
    const uint32_t kvb = sQ + AQ * 2;
    const uint32_t sK[3] = { kvb, kvb + 2 * AKV * 2, kvb + 4 * AKV * 2 };
    const uint32_t sV[3] = { kvb + AKV * 2, kvb + 3 * AKV * 2, kvb + 5 * AKV * 2 };

    const int h  = blockIdx.x;
    const int qt = gridDim.y - 1 - blockIdx.y;   // longest tiles first
    const int q0 = qt * 128;
    const int kh = h >> 2;
    const int tid = threadIdx.x;
    const int warp = tid >> 5;
    const int lane = tid & 31;
    const int gid = lane >> 2;
    const int tig = lane & 3;

    const __half* bkh = g_kh + (size_t)kh * SEQ * HD;
    const __half* bvh = g_vh + (size_t)kh * SEQ * HD;

    auto load_kv = [&](int it, int buf) {
        const __half* pk = bkh + (size_t)(it * 64) * HD;
        const __half* pv = bvh + (size_t)(it * 64) * HD;
        #pragma unroll
        for (int i = 0; i < 4; i++) {
            int ch = tid + i * 256;            // 1024 chunks: 64 rows x 16
            int row = ch >> 4, c = ch & 15;
            uint32_t off = (uint32_t)(row * ASTR) * 2 + c * 16;
            size_t goff = (size_t)row * HD + c * 8;
            cpa16(sK[buf] + off, pk + goff);
            cpa16(sV[buf] + off, pv + goff);
        }
    };

    const int nit = 2 * qt + 1;              // KV tiles 0..nit

    // prologue: {Q + KV0} commit, {KV1} commit  (nit >= 1 always)
    {
        const __half* gq = g_qh + ((size_t)h * SEQ + q0) * HD;
        #pragma unroll
        for (int i = 0; i < 8; i++) {
            int ch = tid + i * 256;            // 2048 chunks: 128 rows x 16
            int row = ch >> 4, c = ch & 15;
            uint32_t off = (uint32_t)(row * ASTR) * 2 + c * 16;
            cpa16(sQ + off, gq + (size_t)row * HD + c * 8);
        }
        load_kv(0, 0);
        cpa_commit();
        load_kv(1, 1);
        cpa_commit();
    }

    float oacc[16][4];
    #pragma unroll
    for (int j = 0; j < 16; j++)
        #pragma unroll
        for (int t = 0; t < 4; t++) oacc[j][t] = 0.0f;
    float mrow[2] = {-1e30f, -1e30f};
    float lrow[2] = {0.0f, 0.0f};

    const uint32_t qoff_row = (uint32_t)((warp * 16 + (lane & 15)) * ASTR) * 2;
    const uint32_t qoff_col = (uint32_t)((lane >> 4) * 8) * 2;
    const uint32_t koff_rowbase = (uint32_t)((lane & 7) * ASTR) * 2;
    const uint32_t koff_col = (uint32_t)(((lane >> 3) & 3) * 8) * 2;
    const uint32_t voff_rowbase = (uint32_t)(((lane & 7) + 8 * ((lane >> 3) & 1)) * ASTR) * 2;
    const uint32_t voff_col = (uint32_t)((lane >> 4) * 8) * 2;

    for (int it = 0; it <= nit; it++) {
        const int cur = it % 3;
        if (it == nit) cpa_wait0(); else cpa_wait1();   // tile `it` resident
        __syncthreads();
        if (it + 1 < nit) {          // prefetch tile it+2 into buffer (it+2)%3
            load_kv(it + 2, (it + 2) % 3);
            cpa_commit();
        }
        // upper-half warps are fully masked in the last diagonal tile
        const bool active = !(it == nit && warp < 4);
        if (active) {
            const uint32_t sKc = sK[cur];
            const uint32_t sVc = sV[cur];

            // ---- S = Q K^T (log2 domain) ----
            float sacc[8][4];
            #pragma unroll
            for (int j = 0; j < 8; j++)
                #pragma unroll
                for (int t = 0; t < 4; t++) sacc[j][t] = 0.0f;

            #pragma unroll
            for (int ks2 = 0; ks2 < 4; ks2++) {
                uint32_t qf[2][4];
                #pragma unroll
                for (int e = 0; e < 2; e++) {
                    uint32_t off = qoff_row + ((uint32_t)((ks2 * 2 + e) * 16) * 2 + qoff_col);
                    ldm_x4(qf[e], sQ + off);
                }
                #pragma unroll
                for (int jn2 = 0; jn2 < 4; jn2++) {
                    const int jA = jn2 * 2, jB = jn2 * 2 + 1;
                    const uint32_t kcom = koff_rowbase + (uint32_t)(ks2 * 32) * 2 + koff_col;
                    uint32_t offA = (uint32_t)(jA * 8 * ASTR) * 2 + kcom;
                    uint32_t offB = (uint32_t)(jB * 8 * ASTR) * 2 + kcom;
                    uint32_t khA[4], khB[4];
                    ldm_x4(khA, sKc + offA); ldm_x4(khB, sKc + offB);
                    mma_f16(sacc[jA], qf[0], khA);     mma_f16(sacc[jB], qf[0], khB);
                    mma_f16(sacc[jA], qf[1], khA + 2); mma_f16(sacc[jB], qf[1], khB + 2);
                }
            }

            // ---- causal mask (last two KV tiles overlap the diagonal) ----
            if (it >= 2 * qt) {
                int qg0 = q0 + warp * 16 + gid;
                #pragma unroll
                for (int jn = 0; jn < 8; jn++) {
                    int kg = it * 64 + jn * 8 + tig * 2;
                    if (kg > qg0)     sacc[jn][0] = -1e30f;
                    if (kg + 1 > qg0) sacc[jn][1] = -1e30f;
                    if (kg > qg0 + 8)     sacc[jn][2] = -1e30f;
                    if (kg + 1 > qg0 + 8) sacc[jn][3] = -1e30f;
                }
            }

            // ---- online softmax (log2 domain, fp16x2 ex2) ----
            float mn0 = mrow[0], mn1 = mrow[1];
            #pragma unroll
            for (int jn = 0; jn < 8; jn++) {
                mn0 = fmaxf(mn0, fmaxf(sacc[jn][0], sacc[jn][1]));
                mn1 = fmaxf(mn1, fmaxf(sacc[jn][2], sacc[jn][3]));
            }
            mn0 = fmaxf(mn0, __shfl_xor_sync(0xffffffffu, mn0, 1));
            mn0 = fmaxf(mn0, __shfl_xor_sync(0xffffffffu, mn0, 2));
            mn1 = fmaxf(mn1, __shfl_xor_sync(0xffffffffu, mn1, 1));
            mn1 = fmaxf(mn1, __shfl_xor_sync(0xffffffffu, mn1, 2));
            float al0 = exp2f(mrow[0] - mn0);
            float al1 = exp2f(mrow[1] - mn1);
            mrow[0] = mn0; mrow[1] = mn1;
            lrow[0] *= al0; lrow[1] *= al1;

            uint32_t ph[8][2];
            float lacc0 = 0.0f, lacc1 = 0.0f;
            #pragma unroll
            for (int jn = 0; jn < 8; jn++) {
                uint32_t p0 = ex2_h2(sacc[jn][0] - mn0, sacc[jn][1] - mn0);
                uint32_t p1 = ex2_h2(sacc[jn][2] - mn1, sacc[jn][3] - mn1);
                ph[jn][0] = p0;
                ph[jn][1] = p1;
                float2 f0 = __half22float2(*(__half2*)&p0);
                float2 f1 = __half22float2(*(__half2*)&p1);
                lacc0 += f0.x + f0.y;
                lacc1 += f1.x + f1.y;
            }
            lrow[0] += lacc0;
            lrow[1] += lacc1;

            #pragma unroll
            for (int jd = 0; jd < 16; jd++) {
                oacc[jd][0] *= al0; oacc[jd][1] *= al0;
                oacc[jd][2] *= al1; oacc[jd][3] *= al1;
            }

            // ---- O += P V ----
            #pragma unroll
            for (int kks = 0; kks < 4; kks++) {
                uint32_t aPh[4] = {ph[2 * kks][0], ph[2 * kks][1],
                                   ph[2 * kks + 1][0], ph[2 * kks + 1][1]};
                #pragma unroll
                for (int jd2 = 0; jd2 < 8; jd2++) {
                    uint32_t off = (uint32_t)(kks * 16 * ASTR) * 2 + voff_rowbase +
                                   (uint32_t)(jd2 * 16) * 2 + voff_col;
                    uint32_t vh4[4];
                    ldm_x4_t(vh4, sVc + off);
                    mma_f16(oacc[jd2 * 2], aPh, vh4);
                    mma_f16(oacc[jd2 * 2 + 1], aPh, vh4 + 2);
                }
            }
        }
    }

    // final: reduce l across quad, normalize, write fp16
    lrow[0] += __shfl_xor_sync(0xffffffffu, lrow[0], 1);
    lrow[0] += __shfl_xor_sync(0xffffffffu, lrow[0], 2);
    lrow[1] += __shfl_xor_sync(0xffffffffu, lrow[1], 1);
    lrow[1] += __shfl_xor_sync(0xffffffffu, lrow[1], 2);
    float inv0 = 1.0f / lrow[0];
    float inv1 = 1.0f / lrow[1];

    int row0 = q0 + warp * 16 + gid;
    #pragma unroll
    for (int jd = 0; jd < 16; jd++) {
        int col = h * HD + jd * 8 + tig * 2;
        __half2 h0 = __floats2half2_rn(oacc[jd][0] * inv0, oacc[jd][1] * inv0);
        __half2 h1 = __floats2half2_rn(oacc[jd][2] * inv1, oacc[jd][3] * inv1);
        *(__half2*)(g_ao_h + (size_t)row0 * QD + col)       = h0;
        *(__half2*)(g_ao_h + (size_t)(row0 + 8) * QD + col) = h1;
    }
}

// ---------------------------------------------------------------------------
// launch
// ---------------------------------------------------------------------------
extern "C" void kernel_launch(void* const* d_in, const int* in_sizes, int n_in,
                              void* d_out, int out_size) {
    const float* hidden = (const float*)d_in[0];
    const float* cosb   = (const float*)d_in[1];
    const float* sinb   = (const float*)d_in[2];
    const float* Wq     = (const float*)d_in[3];
    const float* Wk     = (const float*)d_in[4];
    const float* Wv     = (const float*)d_in[5];
    const float* Wo     = (const float*)d_in[6];
    const float* qw     = (const float*)d_in[7];
    const float* kw     = (const float*)d_in[8];
    float* out = (float*)d_out;

    float* qkv_ptr = nullptr;
    __half *hid_h, *wqkv_h, *wo_h, *ao_h;
    cudaGetSymbolAddress((void**)&qkv_ptr, g_qkv);
    cudaGetSymbolAddress((void**)&hid_h, g_hid_h);
    cudaGetSymbolAddress((void**)&wqkv_h, g_wqkv_h);
    cudaGetSymbolAddress((void**)&wo_h, g_wo_h);
    cudaGetSymbolAddress((void**)&ao_h, g_ao_h);

    cudaFuncSetAttribute(gemm_mma, cudaFuncAttributeMaxDynamicSharedMemorySize, GEMM_SMEM);
    cudaFuncSetAttribute(flash_mma_kernel, cudaFuncAttributeMaxDynamicSharedMemorySize, ATTN_SMEM);

    // fused conversions to fp16 (one launch)
    {
        size_t total = (size_t)SEQ * HID + (size_t)QD * HID + 2 * (size_t)KVD * HID +
                       (size_t)HID * QD;
        int nthreads4 = (int)(total / 4);
        cvt_all<<<(nthreads4 + 255) / 256, 256>>>(hidden, Wq, Wk, Wv, Wo);
    }

    // fused QKV projection: g_qkv[2048, 6144] = hidden @ [Wq|Wk|Wv]^T
    gemm_mma<<<dim3(QKVD / 128, SEQ / 128), 256, GEMM_SMEM>>>(
        hid_h, wqkv_h, qkv_ptr, HID, QKVD);

    // RMSNorm + RoPE + fp16 conversion into [h][s][d] buffers
    {
        int nwarps = SEQ * 48;
        int nblocks = (nwarps * 32 + 255) / 256;
        rms_rope_kernel<<<nblocks, 256>>>(cosb, sinb, qw, kw);
    }

    // tensor-core causal GQA flash attention -> g_ao_h
    flash_mma_kernel<<<dim3(NQH, SEQ / 128), 256, ATTN_SMEM>>>();

    // output projection: out[2048, 2560] = O @ Wo^T
    gemm_mma<<<dim3(HID / 128, SEQ / 128), 256, GEMM_SMEM>>>(
        ao_h, wo_h, out, QD, HID);
}